// round 1
// baseline (speedup 1.0000x reference)
#include <cuda_runtime.h>
#include <cuda_bf16.h>
#include <math.h>

// Problem constants
#define BATCH 2
#define TT    4096
#define DIM   1024
#define MROWS (BATCH * TT)     // 8192
#define HEADS 16
#define HS    64               // DIM / HEADS

// ---------------- scratch (static device globals; no allocation) ------------
__device__ float g_xn[MROWS * DIM];        // LN1 output (residual source)
__device__ float g_q [MROWS * DIM];
__device__ float g_k [MROWS * DIM];
__device__ float g_v [MROWS * DIM];
__device__ float g_at[MROWS * 2 * DIM];    // [out_f | out_r]
__device__ float g_y [MROWS * DIM];        // attn @ Wfb + bfb
__device__ float g_z [MROWS * DIM];        // LN2 output

// ---------------- LayerNorm (optionally fused residual add) -----------------
// one block per row, 256 threads, each thread owns one float4 (1024 = 256*4)
__global__ void ln_kernel(const float* __restrict__ x,
                          const float* __restrict__ res,   // may be null
                          const float* __restrict__ g,
                          const float* __restrict__ b,
                          float* __restrict__ out)
{
    int row = blockIdx.x;
    int tid = threadIdx.x;
    const float4* xr = (const float4*)(x + (size_t)row * DIM);
    float4 v = xr[tid];
    if (res) {
        const float4* rr = (const float4*)(res + (size_t)row * DIM);
        float4 r = rr[tid];
        v.x += r.x; v.y += r.y; v.z += r.z; v.w += r.w;
    }
    float s  = v.x + v.y + v.z + v.w;
    float ss = v.x*v.x + v.y*v.y + v.z*v.z + v.w*v.w;

    #pragma unroll
    for (int o = 16; o; o >>= 1) {
        s  += __shfl_xor_sync(0xffffffffu, s,  o);
        ss += __shfl_xor_sync(0xffffffffu, ss, o);
    }
    __shared__ float rs[8], rss[8];
    int wid = tid >> 5, lid = tid & 31;
    if (lid == 0) { rs[wid] = s; rss[wid] = ss; }
    __syncthreads();
    float tots = 0.f, totss = 0.f;
    #pragma unroll
    for (int i = 0; i < 8; i++) { tots += rs[i]; totss += rss[i]; }

    float mean = tots * (1.0f / DIM);
    float var  = totss * (1.0f / DIM) - mean * mean;
    float inv  = rsqrtf(var + 1e-6f);

    const float4* gv = (const float4*)g;
    const float4* bv = (const float4*)b;
    float4 gg = gv[tid], bb = bv[tid];
    float4 o;
    o.x = (v.x - mean) * inv * gg.x + bb.x;
    o.y = (v.y - mean) * inv * gg.y + bb.y;
    o.z = (v.z - mean) * inv * gg.z + bb.z;
    o.w = (v.w - mean) * inv * gg.w + bb.w;
    ((float4*)(out + (size_t)row * DIM))[tid] = o;
}

// ---------------- fp32 tiled GEMM: C = A[MxK] * B[KxN] + bias, opt. gelu ----
__device__ __forceinline__ float gelu_exact(float x) {
    return 0.5f * x * (1.0f + erff(x * 0.7071067811865475f));
}

__global__ __launch_bounds__(256)
void sgemm128(const float* __restrict__ A, const float* __restrict__ Bm,
              const float* __restrict__ bias, float* __restrict__ C,
              int M, int N, int K, int epi)
{
    __shared__ float As[8][132];
    __shared__ float Bs[8][132];

    int bx = blockIdx.x;          // N tile
    int by = blockIdx.y;          // M tile
    int tid = threadIdx.x;
    int tx = tid & 15, ty = tid >> 4;

    const float* Ab = A + (size_t)(by * 128) * K;
    const float* Bb = Bm + bx * 128;

    int arow = tid >> 1, acol = (tid & 1) * 4;
    int brow = tid >> 5, bcol = (tid & 31) * 4;

    float acc[8][8];
    #pragma unroll
    for (int i = 0; i < 8; i++)
        #pragma unroll
        for (int j = 0; j < 8; j++) acc[i][j] = 0.f;

    for (int k0 = 0; k0 < K; k0 += 8) {
        float4 a4 = *(const float4*)(Ab + (size_t)arow * K + k0 + acol);
        As[acol + 0][arow] = a4.x;
        As[acol + 1][arow] = a4.y;
        As[acol + 2][arow] = a4.z;
        As[acol + 3][arow] = a4.w;
        float4 b4 = *(const float4*)(Bb + (size_t)(k0 + brow) * N + bcol);
        *(float4*)&Bs[brow][bcol] = b4;
        __syncthreads();

        #pragma unroll
        for (int kk = 0; kk < 8; kk++) {
            float ar[8], br[8];
            #pragma unroll
            for (int i = 0; i < 8; i++) ar[i] = As[kk][ty * 8 + i];
            #pragma unroll
            for (int j = 0; j < 8; j++) br[j] = Bs[kk][tx * 8 + j];
            #pragma unroll
            for (int i = 0; i < 8; i++)
                #pragma unroll
                for (int j = 0; j < 8; j++)
                    acc[i][j] = fmaf(ar[i], br[j], acc[i][j]);
        }
        __syncthreads();
    }

    int cn = bx * 128 + tx * 8;
    float bb[8];
    #pragma unroll
    for (int j = 0; j < 8; j++) bb[j] = bias[cn + j];

    #pragma unroll
    for (int i = 0; i < 8; i++) {
        int row = by * 128 + ty * 8 + i;
        float vals[8];
        #pragma unroll
        for (int j = 0; j < 8; j++) {
            float t = acc[i][j] + bb[j];
            vals[j] = (epi == 1) ? gelu_exact(t) : t;
        }
        float* cp = C + (size_t)row * N + cn;
        *(float4*)(cp + 0) = make_float4(vals[0], vals[1], vals[2], vals[3]);
        *(float4*)(cp + 4) = make_float4(vals[4], vals[5], vals[6], vals[7]);
    }
}

// ---------------- windowed local attention (S=3, qi=1 slice) ----------------
// one warp per (b, t, head); lane owns 2 consecutive floats of the head slice.
__global__ void attn_kernel(const float* __restrict__ q,
                            const float* __restrict__ k,
                            const float* __restrict__ v,
                            float* __restrict__ out)
{
    int gw   = (blockIdx.x * blockDim.x + threadIdx.x) >> 5;
    int lane = threadIdx.x & 31;
    if (gw >= MROWS * HEADS) return;
    int h   = gw & (HEADS - 1);
    int row = gw >> 4;                 // = b*T + t
    int t   = row & (TT - 1);

    int off = h * HS + lane * 2;

    auto ld2 = [&](const float* base, int rr) -> float2 {
        return *(const float2*)(base + (size_t)rr * DIM + off);
    };
    const float2 zero = make_float2(0.f, 0.f);

    // ---------- forward: query = q[t-1], keys/values = rows t-j ----------
    {
        float2 qf = (t >= 1) ? ld2(q, row - 1) : zero;
        float d0, d1, d2;
        {
            float2 k0 = ld2(k, row);
            float2 k1 = (t >= 1) ? ld2(k, row - 1) : zero;
            float2 k2 = (t >= 2) ? ld2(k, row - 2) : zero;
            d0 = qf.x * k0.x + qf.y * k0.y;
            d1 = qf.x * k1.x + qf.y * k1.y;
            d2 = qf.x * k2.x + qf.y * k2.y;
        }
        #pragma unroll
        for (int o = 16; o; o >>= 1) {
            d0 += __shfl_xor_sync(0xffffffffu, d0, o);
            d1 += __shfl_xor_sync(0xffffffffu, d1, o);
            d2 += __shfl_xor_sync(0xffffffffu, d2, o);
        }
        d0 *= 0.125f; d1 *= 0.125f; d2 *= 0.125f;
        float m = fmaxf(d0, fmaxf(d1, d2));
        float e0 = expf(d0 - m), e1 = expf(d1 - m), e2 = expf(d2 - m);
        float inv = 1.0f / (e0 + e1 + e2);
        e0 *= inv; e1 *= inv; e2 *= inv;

        float2 v0 = ld2(v, row);
        float2 v1 = (t >= 1) ? ld2(v, row - 1) : zero;
        float2 v2 = (t >= 2) ? ld2(v, row - 2) : zero;
        float2 o;
        o.x = e0 * v0.x + e1 * v1.x + e2 * v2.x;
        o.y = e0 * v0.y + e1 * v1.y + e2 * v2.y;
        *(float2*)(out + (size_t)row * (2 * DIM) + off) = o;
    }

    // ---------- reverse: query = q[t+1], keys/values = rows t+j ----------
    {
        float2 qr = (t + 1 < TT) ? ld2(q, row + 1) : zero;
        float d0, d1, d2;
        {
            float2 k0 = ld2(k, row);
            float2 k1 = (t + 1 < TT) ? ld2(k, row + 1) : zero;
            float2 k2 = (t + 2 < TT) ? ld2(k, row + 2) : zero;
            d0 = qr.x * k0.x + qr.y * k0.y;
            d1 = qr.x * k1.x + qr.y * k1.y;
            d2 = qr.x * k2.x + qr.y * k2.y;
        }
        #pragma unroll
        for (int o = 16; o; o >>= 1) {
            d0 += __shfl_xor_sync(0xffffffffu, d0, o);
            d1 += __shfl_xor_sync(0xffffffffu, d1, o);
            d2 += __shfl_xor_sync(0xffffffffu, d2, o);
        }
        d0 *= 0.125f; d1 *= 0.125f; d2 *= 0.125f;
        float m = fmaxf(d0, fmaxf(d1, d2));
        float e0 = expf(d0 - m), e1 = expf(d1 - m), e2 = expf(d2 - m);
        float inv = 1.0f / (e0 + e1 + e2);
        e0 *= inv; e1 *= inv; e2 *= inv;

        float2 v0 = ld2(v, row);
        float2 v1 = (t + 1 < TT) ? ld2(v, row + 1) : zero;
        float2 v2 = (t + 2 < TT) ? ld2(v, row + 2) : zero;
        float2 o;
        o.x = e0 * v0.x + e1 * v1.x + e2 * v2.x;
        o.y = e0 * v0.y + e1 * v1.y + e2 * v2.y;
        *(float2*)(out + (size_t)row * (2 * DIM) + DIM + off) = o;
    }
}

// ---------------- launch --------------------------------------------------
extern "C" void kernel_launch(void* const* d_in, const int* in_sizes, int n_in,
                              void* d_out, int out_size)
{
    const float* x   = (const float*)d_in[0];
    const float* Wq  = (const float*)d_in[1];
    const float* bq  = (const float*)d_in[2];
    const float* Wk  = (const float*)d_in[3];
    const float* bk  = (const float*)d_in[4];
    const float* Wv  = (const float*)d_in[5];
    const float* bv  = (const float*)d_in[6];
    const float* Wfb = (const float*)d_in[7];
    const float* bfb = (const float*)d_in[8];
    const float* Wo  = (const float*)d_in[9];
    const float* bo  = (const float*)d_in[10];
    const float* g1  = (const float*)d_in[11];
    const float* b1  = (const float*)d_in[12];
    const float* g2  = (const float*)d_in[13];
    const float* b2  = (const float*)d_in[14];
    float* out = (float*)d_out;

    void *p_xn, *p_q, *p_k, *p_v, *p_at, *p_y, *p_z;
    cudaGetSymbolAddress(&p_xn, g_xn);
    cudaGetSymbolAddress(&p_q,  g_q);
    cudaGetSymbolAddress(&p_k,  g_k);
    cudaGetSymbolAddress(&p_v,  g_v);
    cudaGetSymbolAddress(&p_at, g_at);
    cudaGetSymbolAddress(&p_y,  g_y);
    cudaGetSymbolAddress(&p_z,  g_z);
    float* xn = (float*)p_xn;
    float* q  = (float*)p_q;
    float* k  = (float*)p_k;
    float* v  = (float*)p_v;
    float* at = (float*)p_at;
    float* y  = (float*)p_y;
    float* z  = (float*)p_z;

    // 1) LN1
    ln_kernel<<<MROWS, 256>>>(x, nullptr, g1, b1, xn);

    // 2) q, k, v GEMMs
    dim3 g1k(DIM / 128, MROWS / 128);
    sgemm128<<<g1k, 256>>>(xn, Wq, bq, q, MROWS, DIM, DIM, 0);
    sgemm128<<<g1k, 256>>>(xn, Wk, bk, k, MROWS, DIM, DIM, 0);
    sgemm128<<<g1k, 256>>>(xn, Wv, bv, v, MROWS, DIM, DIM, 0);

    // 3) windowed local attention (fwd + rev) -> at [MROWS, 2*DIM]
    int warps = MROWS * HEADS;
    int blocks = (warps * 32) / 256;
    attn_kernel<<<blocks, 256>>>(q, k, v, at);

    // 4) y = at @ Wfb + bfb   (K = 2048)
    sgemm128<<<g1k, 256>>>(at, Wfb, bfb, y, MROWS, DIM, 2 * DIM, 0);

    // 5) z = LN2(y + xn)
    ln_kernel<<<MROWS, 256>>>(y, xn, g2, b2, z);

    // 6) out = gelu(z @ Wo + bo)
    sgemm128<<<g1k, 256>>>(z, Wo, bo, out, MROWS, DIM, DIM, 1);
}

// round 3
// speedup vs baseline: 2.0219x; 2.0219x over previous
#include <cuda_runtime.h>
#include <cuda_bf16.h>
#include <math.h>
#include <stdint.h>

// Problem constants
#define BATCH 2
#define TT    4096
#define DIM   1024
#define MROWS (BATCH * TT)     // 8192
#define HEADS 16
#define HS    64

// ---------------- scratch (static device globals; no allocation) ------------
__device__ float g_xn [MROWS * DIM];
__device__ float g_qkv[(size_t)MROWS * 3 * DIM];   // [q | k | v] per row
__device__ float g_at [MROWS * 2 * DIM];
__device__ float g_y  [MROWS * DIM];
__device__ float g_z  [MROWS * DIM];

// bf16 split buffers: A' = [hi | lo | hi] along K, B' = [hi | hi | lo]
__device__ __nv_bfloat16 g_a3k [(size_t)MROWS * 3 * DIM];      // 8192 x 3072
__device__ __nv_bfloat16 g_a6k [(size_t)MROWS * 6 * DIM];      // 8192 x 6144
__device__ __nv_bfloat16 g_wqkvT[(size_t)(3 * DIM) * 3 * DIM]; // 3072 x 3072 (N-major)
__device__ __nv_bfloat16 g_woT [(size_t)DIM * 3 * DIM];        // 1024 x 3072
__device__ __nv_bfloat16 g_wfbT[(size_t)DIM * 6 * DIM];        // 1024 x 6144
__device__ float g_bqkv[3 * DIM];

// ---------------- PTX helpers ----------------------------------------------
__device__ __forceinline__ uint32_t s2u(const void* p) {
    uint32_t a;
    asm("{ .reg .u64 t; cvta.to.shared.u64 t, %1; cvt.u32.u64 %0, t; }"
        : "=r"(a) : "l"(p));
    return a;
}
__device__ __forceinline__ void cpa16(uint32_t s, const void* g) {
    asm volatile("cp.async.cg.shared.global [%0], [%1], 16;" :: "r"(s), "l"(g));
}
#define CP_COMMIT() asm volatile("cp.async.commit_group;" ::: "memory")
#define CP_WAIT1()  asm volatile("cp.async.wait_group 1;" ::: "memory")

#define LDSM4(r0, r1, r2, r3, addr) \
    asm volatile("ldmatrix.sync.aligned.m8n8.x4.shared.b16 {%0,%1,%2,%3}, [%4];" \
        : "=r"(r0), "=r"(r1), "=r"(r2), "=r"(r3) : "r"(addr))

#define MMA16816(d, a, b) \
    asm volatile("mma.sync.aligned.m16n8k16.row.col.f32.bf16.bf16.f32 " \
        "{%0,%1,%2,%3},{%4,%5,%6,%7},{%8,%9},{%0,%1,%2,%3};" \
        : "+f"((d)[0]), "+f"((d)[1]), "+f"((d)[2]), "+f"((d)[3]) \
        : "r"((a)[0]), "r"((a)[1]), "r"((a)[2]), "r"((a)[3]), \
          "r"((b)[0]), "r"((b)[1]))

// ---------------- LayerNorm (optionally fused residual add) -----------------
__global__ void ln_kernel(const float* __restrict__ x,
                          const float* __restrict__ res,
                          const float* __restrict__ g,
                          const float* __restrict__ b,
                          float* __restrict__ out)
{
    int row = blockIdx.x;
    int tid = threadIdx.x;
    float4 v = ((const float4*)(x + (size_t)row * DIM))[tid];
    if (res) {
        float4 r = ((const float4*)(res + (size_t)row * DIM))[tid];
        v.x += r.x; v.y += r.y; v.z += r.z; v.w += r.w;
    }
    float s  = v.x + v.y + v.z + v.w;
    float ss = v.x*v.x + v.y*v.y + v.z*v.z + v.w*v.w;
    #pragma unroll
    for (int o = 16; o; o >>= 1) {
        s  += __shfl_xor_sync(0xffffffffu, s,  o);
        ss += __shfl_xor_sync(0xffffffffu, ss, o);
    }
    __shared__ float rs[8], rss[8];
    int wid = tid >> 5, lid = tid & 31;
    if (lid == 0) { rs[wid] = s; rss[wid] = ss; }
    __syncthreads();
    float tots = 0.f, totss = 0.f;
    #pragma unroll
    for (int i = 0; i < 8; i++) { tots += rs[i]; totss += rss[i]; }
    float mean = tots * (1.0f / DIM);
    float var  = totss * (1.0f / DIM) - mean * mean;
    float inv  = rsqrtf(var + 1e-6f);
    float4 gg = ((const float4*)g)[tid], bb = ((const float4*)b)[tid];
    float4 o;
    o.x = (v.x - mean) * inv * gg.x + bb.x;
    o.y = (v.y - mean) * inv * gg.y + bb.y;
    o.z = (v.z - mean) * inv * gg.z + bb.z;
    o.w = (v.w - mean) * inv * gg.w + bb.w;
    ((float4*)(out + (size_t)row * DIM))[tid] = o;
}

// ---------------- bf16 hi/lo split kernels ----------------------------------
__global__ void split_act(const float* __restrict__ X, __nv_bfloat16* __restrict__ O, int K)
{
    size_t idx = (size_t)blockIdx.x * blockDim.x + threadIdx.x;
    if (idx >= (size_t)MROWS * K) return;
    int k = (int)(idx % K);
    size_t m = idx / K;
    float x = X[idx];
    __nv_bfloat16 h = __float2bfloat16(x);
    __nv_bfloat16 l = __float2bfloat16(x - __bfloat162float(h));
    size_t b = m * (size_t)(3 * K);
    O[b + k]         = h;
    O[b + K + k]     = l;
    O[b + 2 * K + k] = h;
}

// W[K,N] fp32 -> O[(nofs+n), 3K] bf16 (N-major) as [hi | hi | lo]
__global__ void split_weight(const float* __restrict__ W, __nv_bfloat16* __restrict__ O,
                             int K, int N, int nofs)
{
    size_t idx = (size_t)blockIdx.x * blockDim.x + threadIdx.x;
    if (idx >= (size_t)K * N) return;
    int k = (int)(idx % K);
    int n = (int)(idx / K);
    float x = W[(size_t)k * N + n];
    __nv_bfloat16 h = __float2bfloat16(x);
    __nv_bfloat16 l = __float2bfloat16(x - __bfloat162float(h));
    size_t b = (size_t)(nofs + n) * (3 * K);
    O[b + k]         = h;
    O[b + K + k]     = h;
    O[b + 2 * K + k] = l;
}

__global__ void makebias(const float* bq, const float* bk, const float* bv, float* o)
{
    int i = blockIdx.x * blockDim.x + threadIdx.x;
    if (i < DIM) o[i] = bq[i];
    else if (i < 2 * DIM) o[i] = bk[i - DIM];
    else if (i < 3 * DIM) o[i] = bv[i - 2 * DIM];
}

// ---------------- HMMA bf16 GEMM --------------------------------------------
// C[M, Nout] = A'[M, K3] * B'[Nout, K3]^T + bias   (bf16 in, fp32 accum)
// CTA tile 128x128, BK=32, 3-stage cp.async, 8 warps of 32x64.
#define BKB   64                // bytes of data per SMEM row (32 bf16)
#define ROWB  80                // padded row stride (bank-conflict-free ldmatrix)
#define STGB  (128 * ROWB)      // 10240 per operand per stage
#define GSMEM (3 * 2 * STGB)    // 61440

__device__ __forceinline__ float gelu_exact(float x) {
    return 0.5f * x * (1.0f + erff(x * 0.7071067811865475f));
}

__global__ __launch_bounds__(256)
void gemm_hmma(const __nv_bfloat16* __restrict__ A, const __nv_bfloat16* __restrict__ B,
               const float* __restrict__ bias, float* __restrict__ C,
               int K3, int ldc, int epi)
{
    extern __shared__ char smem[];
    const uint32_t sb = s2u(smem);
    const int tid  = threadIdx.x;
    const int wid  = tid >> 5, lane = tid & 31;
    const int bx   = blockIdx.x, by = blockIdx.y;
    const int wm   = wid & 3;          // 4 warps along M
    const int wn   = wid >> 2;         // 2 warps along N
    const int NT   = K3 / 32;

    uint32_t sA[3], sB[3];
    #pragma unroll
    for (int s = 0; s < 3; s++) {
        sA[s] = sb + s * 2 * STGB;
        sB[s] = sA[s] + STGB;
    }

    const __nv_bfloat16* Ag = A + (size_t)(by * 128 + (tid >> 2)) * K3 + (tid & 3) * 8;
    const __nv_bfloat16* Bg = B + (size_t)(bx * 128 + (tid >> 2)) * K3 + (tid & 3) * 8;
    const uint32_t soff0 = (tid >> 2) * ROWB + (tid & 3) * 16;
    const uint32_t soff1 = ((tid + 256) >> 2) * ROWB + (tid & 3) * 16;

    auto load_stage = [&](int s, int kt) {
        size_t kof = (size_t)kt * 32;
        cpa16(sA[s] + soff0, Ag + kof);
        cpa16(sA[s] + soff1, Ag + kof + (size_t)64 * K3);
        cpa16(sB[s] + soff0, Bg + kof);
        cpa16(sB[s] + soff1, Bg + kof + (size_t)64 * K3);
    };

    float acc[2][8][4];
    #pragma unroll
    for (int i = 0; i < 2; i++)
        #pragma unroll
        for (int j = 0; j < 8; j++)
            #pragma unroll
            for (int r = 0; r < 4; r++) acc[i][j][r] = 0.f;

    load_stage(0, 0); CP_COMMIT();
    load_stage(1, 1); CP_COMMIT();

    // ldmatrix shared addresses (per k-half add 32B)
    const uint32_t aAddrBase = (wm * 32 + (lane & 15)) * ROWB + (lane >> 4) * 16;
    const uint32_t bAddrBase = (wn * 64 + (lane & 7) + ((lane >> 4) & 1) * 8) * ROWB
                             + ((lane >> 3) & 1) * 16;

    for (int kt = 0; kt < NT; kt++) {
        CP_WAIT1();
        __syncthreads();
        int s = kt % 3;
        if (kt + 2 < NT) load_stage((kt + 2) % 3, kt + 2);
        CP_COMMIT();

        #pragma unroll
        for (int kh = 0; kh < 2; kh++) {         // two k16 steps inside BK=32
            uint32_t a[2][4], b[8][2];
            #pragma unroll
            for (int mt = 0; mt < 2; mt++)
                LDSM4(a[mt][0], a[mt][1], a[mt][2], a[mt][3],
                      sA[s] + aAddrBase + mt * 16 * ROWB + kh * 32);
            #pragma unroll
            for (int np = 0; np < 4; np++) {
                uint32_t r0, r1, r2, r3;
                LDSM4(r0, r1, r2, r3, sB[s] + bAddrBase + np * 16 * ROWB + kh * 32);
                b[np*2][0] = r0; b[np*2][1] = r1;
                b[np*2+1][0] = r2; b[np*2+1][1] = r3;
            }
            #pragma unroll
            for (int mt = 0; mt < 2; mt++)
                #pragma unroll
                for (int nt = 0; nt < 8; nt++)
                    MMA16816(acc[mt][nt], a[mt], b[nt]);
        }
    }

    // epilogue: bias (+gelu) and direct store
    #pragma unroll
    for (int mt = 0; mt < 2; mt++) {
        int r0 = by * 128 + wm * 32 + mt * 16 + (lane >> 2);
        #pragma unroll
        for (int nt = 0; nt < 8; nt++) {
            int col = bx * 128 + wn * 64 + nt * 8 + (lane & 3) * 2;
            float b0 = __ldg(bias + col), b1 = __ldg(bias + col + 1);
            float v0 = acc[mt][nt][0] + b0, v1 = acc[mt][nt][1] + b1;
            float v2 = acc[mt][nt][2] + b0, v3 = acc[mt][nt][3] + b1;
            if (epi) { v0 = gelu_exact(v0); v1 = gelu_exact(v1);
                       v2 = gelu_exact(v2); v3 = gelu_exact(v3); }
            *(float2*)(C + (size_t)r0 * ldc + col)       = make_float2(v0, v1);
            *(float2*)(C + (size_t)(r0 + 8) * ldc + col) = make_float2(v2, v3);
        }
    }
}

// ---------------- windowed local attention (S=3, qi=1 slice) ----------------
// qkv layout: row-major [MROWS, 3*DIM] = [q | k | v]
__global__ void attn_kernel(const float* __restrict__ qkv,
                            float* __restrict__ out)
{
    int gw   = (blockIdx.x * blockDim.x + threadIdx.x) >> 5;
    int lane = threadIdx.x & 31;
    if (gw >= MROWS * HEADS) return;
    int h   = gw & (HEADS - 1);
    int row = gw >> 4;
    int t   = row & (TT - 1);
    int off = h * HS + lane * 2;

    auto ld2 = [&](int part, int rr) -> float2 {
        return *(const float2*)(qkv + (size_t)rr * (3 * DIM) + part * DIM + off);
    };
    const float2 zero = make_float2(0.f, 0.f);

    {   // forward
        float2 qf = (t >= 1) ? ld2(0, row - 1) : zero;
        float2 k0 = ld2(1, row);
        float2 k1 = (t >= 1) ? ld2(1, row - 1) : zero;
        float2 k2 = (t >= 2) ? ld2(1, row - 2) : zero;
        float d0 = qf.x*k0.x + qf.y*k0.y;
        float d1 = qf.x*k1.x + qf.y*k1.y;
        float d2 = qf.x*k2.x + qf.y*k2.y;
        #pragma unroll
        for (int o = 16; o; o >>= 1) {
            d0 += __shfl_xor_sync(0xffffffffu, d0, o);
            d1 += __shfl_xor_sync(0xffffffffu, d1, o);
            d2 += __shfl_xor_sync(0xffffffffu, d2, o);
        }
        d0 *= 0.125f; d1 *= 0.125f; d2 *= 0.125f;
        float m = fmaxf(d0, fmaxf(d1, d2));
        float e0 = expf(d0-m), e1 = expf(d1-m), e2 = expf(d2-m);
        float inv = 1.0f / (e0 + e1 + e2);
        e0 *= inv; e1 *= inv; e2 *= inv;
        float2 v0 = ld2(2, row);
        float2 v1 = (t >= 1) ? ld2(2, row - 1) : zero;
        float2 v2 = (t >= 2) ? ld2(2, row - 2) : zero;
        float2 o;
        o.x = e0*v0.x + e1*v1.x + e2*v2.x;
        o.y = e0*v0.y + e1*v1.y + e2*v2.y;
        *(float2*)(out + (size_t)row * (2*DIM) + off) = o;
    }
    {   // reverse
        float2 qr = (t + 1 < TT) ? ld2(0, row + 1) : zero;
        float2 k0 = ld2(1, row);
        float2 k1 = (t + 1 < TT) ? ld2(1, row + 1) : zero;
        float2 k2 = (t + 2 < TT) ? ld2(1, row + 2) : zero;
        float d0 = qr.x*k0.x + qr.y*k0.y;
        float d1 = qr.x*k1.x + qr.y*k1.y;
        float d2 = qr.x*k2.x + qr.y*k2.y;
        #pragma unroll
        for (int o = 16; o; o >>= 1) {
            d0 += __shfl_xor_sync(0xffffffffu, d0, o);
            d1 += __shfl_xor_sync(0xffffffffu, d1, o);
            d2 += __shfl_xor_sync(0xffffffffu, d2, o);
        }
        d0 *= 0.125f; d1 *= 0.125f; d2 *= 0.125f;
        float m = fmaxf(d0, fmaxf(d1, d2));
        float e0 = expf(d0-m), e1 = expf(d1-m), e2 = expf(d2-m);
        float inv = 1.0f / (e0 + e1 + e2);
        e0 *= inv; e1 *= inv; e2 *= inv;
        float2 v0 = ld2(2, row);
        float2 v1 = (t + 1 < TT) ? ld2(2, row + 1) : zero;
        float2 v2 = (t + 2 < TT) ? ld2(2, row + 2) : zero;
        float2 o;
        o.x = e0*v0.x + e1*v1.x + e2*v2.x;
        o.y = e0*v0.y + e1*v1.y + e2*v2.y;
        *(float2*)(out + (size_t)row * (2*DIM) + DIM + off) = o;
    }
}

// ---------------- launch ----------------------------------------------------
extern "C" void kernel_launch(void* const* d_in, const int* in_sizes, int n_in,
                              void* d_out, int out_size)
{
    const float* x   = (const float*)d_in[0];
    const float* Wq  = (const float*)d_in[1];
    const float* bq  = (const float*)d_in[2];
    const float* Wk  = (const float*)d_in[3];
    const float* bk  = (const float*)d_in[4];
    const float* Wv  = (const float*)d_in[5];
    const float* bv  = (const float*)d_in[6];
    const float* Wfb = (const float*)d_in[7];
    const float* bfb = (const float*)d_in[8];
    const float* Wo  = (const float*)d_in[9];
    const float* bo  = (const float*)d_in[10];
    const float* g1  = (const float*)d_in[11];
    const float* b1  = (const float*)d_in[12];
    const float* g2  = (const float*)d_in[13];
    const float* b2  = (const float*)d_in[14];
    float* out = (float*)d_out;

    void *p;
    float *xn, *qkv, *at, *y, *z, *bqkv;
    __nv_bfloat16 *a3k, *a6k, *wqkvT, *woT, *wfbT;
    cudaGetSymbolAddress(&p, g_xn);    xn    = (float*)p;
    cudaGetSymbolAddress(&p, g_qkv);   qkv   = (float*)p;
    cudaGetSymbolAddress(&p, g_at);    at    = (float*)p;
    cudaGetSymbolAddress(&p, g_y);     y     = (float*)p;
    cudaGetSymbolAddress(&p, g_z);     z     = (float*)p;
    cudaGetSymbolAddress(&p, g_bqkv);  bqkv  = (float*)p;
    cudaGetSymbolAddress(&p, g_a3k);   a3k   = (__nv_bfloat16*)p;
    cudaGetSymbolAddress(&p, g_a6k);   a6k   = (__nv_bfloat16*)p;
    cudaGetSymbolAddress(&p, g_wqkvT); wqkvT = (__nv_bfloat16*)p;
    cudaGetSymbolAddress(&p, g_woT);   woT   = (__nv_bfloat16*)p;
    cudaGetSymbolAddress(&p, g_wfbT);  wfbT  = (__nv_bfloat16*)p;

    cudaFuncSetAttribute(gemm_hmma, cudaFuncAttributeMaxDynamicSharedMemorySize, GSMEM);

    int wth = 256;
    // weight splits (N-major, [hi|hi|lo])
    split_weight<<<(DIM*DIM + wth-1)/wth, wth>>>(Wq, wqkvT, DIM, DIM, 0);
    split_weight<<<(DIM*DIM + wth-1)/wth, wth>>>(Wk, wqkvT, DIM, DIM, DIM);
    split_weight<<<(DIM*DIM + wth-1)/wth, wth>>>(Wv, wqkvT, DIM, DIM, 2*DIM);
    split_weight<<<(DIM*DIM + wth-1)/wth, wth>>>(Wo, woT, DIM, DIM, 0);
    split_weight<<<(2*DIM*DIM + wth-1)/wth, wth>>>(Wfb, wfbT, 2*DIM, DIM, 0);
    makebias<<<(3*DIM)/wth, wth>>>(bq, bk, bv, bqkv);

    // 1) LN1
    ln_kernel<<<MROWS, 256>>>(x, nullptr, g1, b1, xn);
    // 2) split + fused qkv GEMM: [8192, 3072] = a3k @ wqkvT^T
    split_act<<<(MROWS*DIM)/256, 256>>>(xn, a3k, DIM);
    gemm_hmma<<<dim3(24, 64), 256, GSMEM>>>(a3k, wqkvT, bqkv, qkv, 3*DIM, 3*DIM, 0);
    // 3) local attention
    attn_kernel<<<(MROWS*HEADS*32)/256, 256>>>(qkv, at);
    // 4) y = at @ Wfb + bfb
    split_act<<<(MROWS*2*DIM)/256, 256>>>(at, a6k, 2*DIM);
    gemm_hmma<<<dim3(8, 64), 256, GSMEM>>>(a6k, wfbT, bfb, y, 6*DIM, DIM, 0);
    // 5) z = LN2(y + xn)
    ln_kernel<<<MROWS, 256>>>(y, xn, g2, b2, z);
    // 6) out = gelu(z @ Wo + bo)
    split_act<<<(MROWS*DIM)/256, 256>>>(z, a3k, DIM);
    gemm_hmma<<<dim3(8, 64), 256, GSMEM>>>(a3k, woT, bo, out, 3*DIM, DIM, 1);
}

// round 4
// speedup vs baseline: 2.6552x; 1.3132x over previous
#include <cuda_runtime.h>
#include <cuda_bf16.h>
#include <math.h>
#include <stdint.h>

// Problem constants
#define BATCH 2
#define TT    4096
#define DIM   1024
#define MROWS (BATCH * TT)     // 8192
#define HEADS 16
#define HS    64

// ---------------- scratch (static device globals; no allocation) ------------
__device__ float g_xn [MROWS * DIM];
__device__ float g_qkv[(size_t)MROWS * 3 * DIM];   // [q | k | v] per row
__device__ float g_y  [MROWS * DIM];

// bf16 split buffers: A' = [hi | lo | hi] along K, B' = [hi | hi | lo]
__device__ __nv_bfloat16 g_a3k [(size_t)MROWS * 3 * DIM];      // 8192 x 3072
__device__ __nv_bfloat16 g_a6k [(size_t)MROWS * 6 * DIM];      // 8192 x 6144
__device__ __nv_bfloat16 g_wqkvT[(size_t)(3 * DIM) * 3 * DIM]; // 3072 x 3072 (N-major)
__device__ __nv_bfloat16 g_woT [(size_t)DIM * 3 * DIM];        // 1024 x 3072
__device__ __nv_bfloat16 g_wfbT[(size_t)DIM * 6 * DIM];        // 1024 x 6144
__device__ float g_bqkv[3 * DIM];

// ---------------- PTX helpers ----------------------------------------------
__device__ __forceinline__ uint32_t s2u(const void* p) {
    uint32_t a;
    asm("{ .reg .u64 t; cvta.to.shared.u64 t, %1; cvt.u32.u64 %0, t; }"
        : "=r"(a) : "l"(p));
    return a;
}
__device__ __forceinline__ void cpa16(uint32_t s, const void* g) {
    asm volatile("cp.async.cg.shared.global [%0], [%1], 16;" :: "r"(s), "l"(g));
}
#define CP_COMMIT() asm volatile("cp.async.commit_group;" ::: "memory")
#define CP_WAIT2()  asm volatile("cp.async.wait_group 2;" ::: "memory")

#define LDSM4(r0, r1, r2, r3, addr) \
    asm volatile("ldmatrix.sync.aligned.m8n8.x4.shared.b16 {%0,%1,%2,%3}, [%4];" \
        : "=r"(r0), "=r"(r1), "=r"(r2), "=r"(r3) : "r"(addr))

#define MMA16816(d, a, b) \
    asm volatile("mma.sync.aligned.m16n8k16.row.col.f32.bf16.bf16.f32 " \
        "{%0,%1,%2,%3},{%4,%5,%6,%7},{%8,%9},{%0,%1,%2,%3};" \
        : "+f"((d)[0]), "+f"((d)[1]), "+f"((d)[2]), "+f"((d)[3]) \
        : "r"((a)[0]), "r"((a)[1]), "r"((a)[2]), "r"((a)[3]), \
          "r"((b)[0]), "r"((b)[1]))

__device__ __forceinline__ __nv_bfloat162 split_hi2(float a, float b,
                                                    __nv_bfloat162& lo) {
    __nv_bfloat16 ha = __float2bfloat16(a);
    __nv_bfloat16 hb = __float2bfloat16(b);
    lo = __nv_bfloat162(__float2bfloat16(a - __bfloat162float(ha)),
                        __float2bfloat16(b - __bfloat162float(hb)));
    return __nv_bfloat162(ha, hb);
}

// ---------------- LayerNorm fused with bf16 hi/lo split ---------------------
// out split row layout: [hi(1024) | lo(1024) | hi(1024)]
__global__ void ln_split_kernel(const float* __restrict__ x,
                                const float* __restrict__ res,
                                const float* __restrict__ g,
                                const float* __restrict__ b,
                                float* __restrict__ xn_out,          // may be null
                                __nv_bfloat16* __restrict__ split_out)
{
    int row = blockIdx.x;
    int tid = threadIdx.x;
    float4 v = ((const float4*)(x + (size_t)row * DIM))[tid];
    if (res) {
        float4 r = ((const float4*)(res + (size_t)row * DIM))[tid];
        v.x += r.x; v.y += r.y; v.z += r.z; v.w += r.w;
    }
    float s  = v.x + v.y + v.z + v.w;
    float ss = v.x*v.x + v.y*v.y + v.z*v.z + v.w*v.w;
    #pragma unroll
    for (int o = 16; o; o >>= 1) {
        s  += __shfl_xor_sync(0xffffffffu, s,  o);
        ss += __shfl_xor_sync(0xffffffffu, ss, o);
    }
    __shared__ float rs[8], rss[8];
    int wid = tid >> 5, lid = tid & 31;
    if (lid == 0) { rs[wid] = s; rss[wid] = ss; }
    __syncthreads();
    float tots = 0.f, totss = 0.f;
    #pragma unroll
    for (int i = 0; i < 8; i++) { tots += rs[i]; totss += rss[i]; }
    float mean = tots * (1.0f / DIM);
    float var  = totss * (1.0f / DIM) - mean * mean;
    float inv  = rsqrtf(var + 1e-6f);
    float4 gg = ((const float4*)g)[tid], bb = ((const float4*)b)[tid];
    float4 o;
    o.x = (v.x - mean) * inv * gg.x + bb.x;
    o.y = (v.y - mean) * inv * gg.y + bb.y;
    o.z = (v.z - mean) * inv * gg.z + bb.z;
    o.w = (v.w - mean) * inv * gg.w + bb.w;
    if (xn_out) ((float4*)(xn_out + (size_t)row * DIM))[tid] = o;

    __nv_bfloat162 l0, l1;
    __nv_bfloat162 h0 = split_hi2(o.x, o.y, l0);
    __nv_bfloat162 h1 = split_hi2(o.z, o.w, l1);
    __nv_bfloat16* base = split_out + (size_t)row * (3 * DIM) + tid * 4;
    *(__nv_bfloat162*)(base)            = h0;
    *(__nv_bfloat162*)(base + 2)        = h1;
    *(__nv_bfloat162*)(base + DIM)      = l0;
    *(__nv_bfloat162*)(base + DIM + 2)  = l1;
    *(__nv_bfloat162*)(base + 2*DIM)    = h0;
    *(__nv_bfloat162*)(base + 2*DIM + 2)= h1;
}

// ---------------- all weight splits in one kernel ----------------------------
// Wq,Wk,Wv,Wo: [1024,1024]; Wfb: [2048,1024]. Each fp32 W[K,N] -> bf16 N-major
// [hi|hi|lo] along 3K.
__global__ void split_weight_all(const float* __restrict__ Wq,
                                 const float* __restrict__ Wk,
                                 const float* __restrict__ Wv,
                                 const float* __restrict__ Wo,
                                 const float* __restrict__ Wfb,
                                 __nv_bfloat16* __restrict__ wqkvT,
                                 __nv_bfloat16* __restrict__ woT,
                                 __nv_bfloat16* __restrict__ wfbT)
{
    size_t idx = (size_t)blockIdx.x * blockDim.x + threadIdx.x;   // < 6M
    const size_t SQ = (size_t)DIM * DIM;                          // 1M
    const float* W; __nv_bfloat16* O; int K, nofs;
    if (idx < 4 * SQ) {
        int which = (int)(idx >> 20);
        idx &= (SQ - 1);
        K = DIM;
        if      (which == 0) { W = Wq; O = g_wqkvT; nofs = 0; }
        else if (which == 1) { W = Wk; O = g_wqkvT; nofs = DIM; }
        else if (which == 2) { W = Wv; O = g_wqkvT; nofs = 2 * DIM; }
        else                 { W = Wo; O = g_woT;   nofs = 0; }
        (void)wqkvT; (void)woT;
    } else {
        idx -= 4 * SQ;
        K = 2 * DIM; W = Wfb; O = g_wfbT; nofs = 0;
        (void)wfbT;
    }
    int k = (int)(idx % K);
    int n = (int)(idx / K);
    float x = W[(size_t)k * DIM + n];
    __nv_bfloat16 h = __float2bfloat16(x);
    __nv_bfloat16 l = __float2bfloat16(x - __bfloat162float(h));
    size_t b = (size_t)(nofs + n) * (3 * K);
    O[b + k]         = h;
    O[b + K + k]     = h;
    O[b + 2 * K + k] = l;
}

__global__ void makebias(const float* bq, const float* bk, const float* bv, float* o)
{
    int i = blockIdx.x * blockDim.x + threadIdx.x;
    if (i < DIM) o[i] = bq[i];
    else if (i < 2 * DIM) o[i] = bk[i - DIM];
    else if (i < 3 * DIM) o[i] = bv[i - 2 * DIM];
}

// ---------------- HMMA bf16 GEMM --------------------------------------------
// C[M, Nout] = A'[M, K3] * B'[Nout, K3]^T + bias   (bf16 in, fp32 accum)
// CTA tile 128x128, BK=32, 4-stage cp.async, 8 warps of 32x64.
#define ROWB  80                // padded row stride (bank-conflict-free ldmatrix)
#define STGB  (128 * ROWB)      // 10240 per operand per stage
#define GSMEM (4 * 2 * STGB)    // 81920

__device__ __forceinline__ float gelu_exact(float x) {
    return 0.5f * x * (1.0f + erff(x * 0.7071067811865475f));
}

__global__ __launch_bounds__(256, 2)
void gemm_hmma(const __nv_bfloat16* __restrict__ A, const __nv_bfloat16* __restrict__ B,
               const float* __restrict__ bias, float* __restrict__ C,
               int K3, int ldc, int epi)
{
    extern __shared__ char smem[];
    const uint32_t sb = s2u(smem);
    const int tid  = threadIdx.x;
    const int wid  = tid >> 5, lane = tid & 31;
    const int bx   = blockIdx.x, by = blockIdx.y;
    const int wm   = wid & 3;          // 4 warps along M
    const int wn   = wid >> 2;         // 2 warps along N
    const int NT   = K3 / 32;

    uint32_t sA[4], sB[4];
    #pragma unroll
    for (int s = 0; s < 4; s++) {
        sA[s] = sb + s * 2 * STGB;
        sB[s] = sA[s] + STGB;
    }

    const __nv_bfloat16* Ag = A + (size_t)(by * 128 + (tid >> 2)) * K3 + (tid & 3) * 8;
    const __nv_bfloat16* Bg = B + (size_t)(bx * 128 + (tid >> 2)) * K3 + (tid & 3) * 8;
    const uint32_t soff0 = (tid >> 2) * ROWB + (tid & 3) * 16;
    const uint32_t soff1 = ((tid + 256) >> 2) * ROWB + (tid & 3) * 16;

    auto load_stage = [&](int s, int kt) {
        size_t kof = (size_t)kt * 32;
        cpa16(sA[s] + soff0, Ag + kof);
        cpa16(sA[s] + soff1, Ag + kof + (size_t)64 * K3);
        cpa16(sB[s] + soff0, Bg + kof);
        cpa16(sB[s] + soff1, Bg + kof + (size_t)64 * K3);
    };

    float acc[2][8][4];
    #pragma unroll
    for (int i = 0; i < 2; i++)
        #pragma unroll
        for (int j = 0; j < 8; j++)
            #pragma unroll
            for (int r = 0; r < 4; r++) acc[i][j][r] = 0.f;

    load_stage(0, 0); CP_COMMIT();
    load_stage(1, 1); CP_COMMIT();
    load_stage(2, 2); CP_COMMIT();

    const uint32_t aAddrBase = (wm * 32 + (lane & 15)) * ROWB + (lane >> 4) * 16;
    const uint32_t bAddrBase = (wn * 64 + (lane & 7) + ((lane >> 4) & 1) * 8) * ROWB
                             + ((lane >> 3) & 1) * 16;

    for (int kt = 0; kt < NT; kt++) {
        CP_WAIT2();
        __syncthreads();
        int s = kt & 3;
        if (kt + 3 < NT) load_stage((kt + 3) & 3, kt + 3);
        CP_COMMIT();

        #pragma unroll
        for (int kh = 0; kh < 2; kh++) {
            uint32_t a[2][4], b[8][2];
            #pragma unroll
            for (int mt = 0; mt < 2; mt++)
                LDSM4(a[mt][0], a[mt][1], a[mt][2], a[mt][3],
                      sA[s] + aAddrBase + mt * 16 * ROWB + kh * 32);
            #pragma unroll
            for (int np = 0; np < 4; np++) {
                uint32_t r0, r1, r2, r3;
                LDSM4(r0, r1, r2, r3, sB[s] + bAddrBase + np * 16 * ROWB + kh * 32);
                b[np*2][0] = r0; b[np*2][1] = r1;
                b[np*2+1][0] = r2; b[np*2+1][1] = r3;
            }
            #pragma unroll
            for (int mt = 0; mt < 2; mt++)
                #pragma unroll
                for (int nt = 0; nt < 8; nt++)
                    MMA16816(acc[mt][nt], a[mt], b[nt]);
        }
    }

    #pragma unroll
    for (int mt = 0; mt < 2; mt++) {
        int r0 = by * 128 + wm * 32 + mt * 16 + (lane >> 2);
        #pragma unroll
        for (int nt = 0; nt < 8; nt++) {
            int col = bx * 128 + wn * 64 + nt * 8 + (lane & 3) * 2;
            float b0 = __ldg(bias + col), b1 = __ldg(bias + col + 1);
            float v0 = acc[mt][nt][0] + b0, v1 = acc[mt][nt][1] + b1;
            float v2 = acc[mt][nt][2] + b0, v3 = acc[mt][nt][3] + b1;
            if (epi) { v0 = gelu_exact(v0); v1 = gelu_exact(v1);
                       v2 = gelu_exact(v2); v3 = gelu_exact(v3); }
            *(float2*)(C + (size_t)r0 * ldc + col)       = make_float2(v0, v1);
            *(float2*)(C + (size_t)(r0 + 8) * ldc + col) = make_float2(v2, v3);
        }
    }
}

// ---------------- windowed local attention + bf16 split output --------------
// qkv layout: row-major [MROWS, 3*DIM] = [q | k | v]
// out: bf16 split rows [hi(2048) | lo(2048) | hi(2048)], fwd cols 0..1023, rev 1024..2047
__global__ void attn_kernel(const float* __restrict__ qkv,
                            __nv_bfloat16* __restrict__ out)
{
    int gw   = (blockIdx.x * blockDim.x + threadIdx.x) >> 5;
    int lane = threadIdx.x & 31;
    if (gw >= MROWS * HEADS) return;
    int h   = gw & (HEADS - 1);
    int row = gw >> 4;
    int t   = row & (TT - 1);
    int off = h * HS + lane * 2;

    auto ld2 = [&](int part, int rr) -> float2 {
        return *(const float2*)(qkv + (size_t)rr * (3 * DIM) + part * DIM + off);
    };
    auto store_split = [&](int col, float a, float b) {
        __nv_bfloat162 lo;
        __nv_bfloat162 hi = split_hi2(a, b, lo);
        __nv_bfloat16* base = out + (size_t)row * (6 * DIM) + col;
        *(__nv_bfloat162*)(base)           = hi;
        *(__nv_bfloat162*)(base + 2*DIM)   = lo;
        *(__nv_bfloat162*)(base + 4*DIM)   = hi;
    };
    const float2 zero = make_float2(0.f, 0.f);

    {   // forward
        float2 qf = (t >= 1) ? ld2(0, row - 1) : zero;
        float2 k0 = ld2(1, row);
        float2 k1 = (t >= 1) ? ld2(1, row - 1) : zero;
        float2 k2 = (t >= 2) ? ld2(1, row - 2) : zero;
        float d0 = qf.x*k0.x + qf.y*k0.y;
        float d1 = qf.x*k1.x + qf.y*k1.y;
        float d2 = qf.x*k2.x + qf.y*k2.y;
        #pragma unroll
        for (int o = 16; o; o >>= 1) {
            d0 += __shfl_xor_sync(0xffffffffu, d0, o);
            d1 += __shfl_xor_sync(0xffffffffu, d1, o);
            d2 += __shfl_xor_sync(0xffffffffu, d2, o);
        }
        d0 *= 0.125f; d1 *= 0.125f; d2 *= 0.125f;
        float m = fmaxf(d0, fmaxf(d1, d2));
        float e0 = expf(d0-m), e1 = expf(d1-m), e2 = expf(d2-m);
        float inv = 1.0f / (e0 + e1 + e2);
        e0 *= inv; e1 *= inv; e2 *= inv;
        float2 v0 = ld2(2, row);
        float2 v1 = (t >= 1) ? ld2(2, row - 1) : zero;
        float2 v2 = (t >= 2) ? ld2(2, row - 2) : zero;
        store_split(off, e0*v0.x + e1*v1.x + e2*v2.x,
                         e0*v0.y + e1*v1.y + e2*v2.y);
    }
    {   // reverse
        float2 qr = (t + 1 < TT) ? ld2(0, row + 1) : zero;
        float2 k0 = ld2(1, row);
        float2 k1 = (t + 1 < TT) ? ld2(1, row + 1) : zero;
        float2 k2 = (t + 2 < TT) ? ld2(1, row + 2) : zero;
        float d0 = qr.x*k0.x + qr.y*k0.y;
        float d1 = qr.x*k1.x + qr.y*k1.y;
        float d2 = qr.x*k2.x + qr.y*k2.y;
        #pragma unroll
        for (int o = 16; o; o >>= 1) {
            d0 += __shfl_xor_sync(0xffffffffu, d0, o);
            d1 += __shfl_xor_sync(0xffffffffu, d1, o);
            d2 += __shfl_xor_sync(0xffffffffu, d2, o);
        }
        d0 *= 0.125f; d1 *= 0.125f; d2 *= 0.125f;
        float m = fmaxf(d0, fmaxf(d1, d2));
        float e0 = expf(d0-m), e1 = expf(d1-m), e2 = expf(d2-m);
        float inv = 1.0f / (e0 + e1 + e2);
        e0 *= inv; e1 *= inv; e2 *= inv;
        float2 v0 = ld2(2, row);
        float2 v1 = (t + 1 < TT) ? ld2(2, row + 1) : zero;
        float2 v2 = (t + 2 < TT) ? ld2(2, row + 2) : zero;
        store_split(DIM + off, e0*v0.x + e1*v1.x + e2*v2.x,
                               e0*v0.y + e1*v1.y + e2*v2.y);
    }
}

// ---------------- launch ----------------------------------------------------
extern "C" void kernel_launch(void* const* d_in, const int* in_sizes, int n_in,
                              void* d_out, int out_size)
{
    const float* x   = (const float*)d_in[0];
    const float* Wq  = (const float*)d_in[1];
    const float* bq  = (const float*)d_in[2];
    const float* Wk  = (const float*)d_in[3];
    const float* bk  = (const float*)d_in[4];
    const float* Wv  = (const float*)d_in[5];
    const float* bv  = (const float*)d_in[6];
    const float* Wfb = (const float*)d_in[7];
    const float* bfb = (const float*)d_in[8];
    const float* Wo  = (const float*)d_in[9];
    const float* bo  = (const float*)d_in[10];
    const float* g1  = (const float*)d_in[11];
    const float* b1  = (const float*)d_in[12];
    const float* g2  = (const float*)d_in[13];
    const float* b2  = (const float*)d_in[14];
    float* out = (float*)d_out;

    void *p;
    float *xn, *qkv, *y, *bqkv;
    __nv_bfloat16 *a3k, *a6k, *wqkvT, *woT, *wfbT;
    cudaGetSymbolAddress(&p, g_xn);    xn    = (float*)p;
    cudaGetSymbolAddress(&p, g_qkv);   qkv   = (float*)p;
    cudaGetSymbolAddress(&p, g_y);     y     = (float*)p;
    cudaGetSymbolAddress(&p, g_bqkv);  bqkv  = (float*)p;
    cudaGetSymbolAddress(&p, g_a3k);   a3k   = (__nv_bfloat16*)p;
    cudaGetSymbolAddress(&p, g_a6k);   a6k   = (__nv_bfloat16*)p;
    cudaGetSymbolAddress(&p, g_wqkvT); wqkvT = (__nv_bfloat16*)p;
    cudaGetSymbolAddress(&p, g_woT);   woT   = (__nv_bfloat16*)p;
    cudaGetSymbolAddress(&p, g_wfbT);  wfbT  = (__nv_bfloat16*)p;

    cudaFuncSetAttribute(gemm_hmma, cudaFuncAttributeMaxDynamicSharedMemorySize, GSMEM);

    // 0) weight prep (one launch) + bias concat
    size_t welems = 4 * (size_t)DIM * DIM + 2 * (size_t)DIM * DIM;  // 6M
    split_weight_all<<<(int)(welems / 256), 256>>>(Wq, Wk, Wv, Wo, Wfb,
                                                   wqkvT, woT, wfbT);
    makebias<<<(3 * DIM) / 256, 256>>>(bq, bk, bv, bqkv);

    // 1) LN1 + split
    ln_split_kernel<<<MROWS, 256>>>(x, nullptr, g1, b1, xn, a3k);
    // 2) fused qkv GEMM: [8192, 3072]
    gemm_hmma<<<dim3(24, 64), 256, GSMEM>>>(a3k, wqkvT, bqkv, qkv, 3*DIM, 3*DIM, 0);
    // 3) local attention -> split a6k
    attn_kernel<<<(MROWS*HEADS*32)/256, 256>>>(qkv, a6k);
    // 4) y = at @ Wfb + bfb
    gemm_hmma<<<dim3(8, 64), 256, GSMEM>>>(a6k, wfbT, bfb, y, 6*DIM, DIM, 0);
    // 5) LN2(y + xn) + split
    ln_split_kernel<<<MROWS, 256>>>(y, xn, g2, b2, nullptr, a3k);
    // 6) out = gelu(z @ Wo + bo)
    gemm_hmma<<<dim3(8, 64), 256, GSMEM>>>(a3k, woT, bo, out, 3*DIM, DIM, 1);
}

// round 5
// speedup vs baseline: 2.9898x; 1.1260x over previous
#include <cuda_runtime.h>
#include <cuda_bf16.h>
#include <math.h>
#include <stdint.h>

// Problem constants
#define BATCH 2
#define TT    4096
#define DIM   1024
#define MROWS (BATCH * TT)     // 8192
#define HEADS 16
#define HS    64

// ---------------- scratch (static device globals; no allocation) ------------
__device__ float g_xn [MROWS * DIM];
__device__ float g_qkv[(size_t)MROWS * 3 * DIM];   // [q | k | v] per row
__device__ float g_y  [MROWS * DIM];

// bf16 split buffers: A' = [hi | lo | hi] along K, B' = [hi | hi | lo]
__device__ __nv_bfloat16 g_a3k [(size_t)MROWS * 3 * DIM];      // 8192 x 3072
__device__ __nv_bfloat16 g_a6k [(size_t)MROWS * 6 * DIM];      // 8192 x 6144
__device__ __nv_bfloat16 g_wqkvT[(size_t)(3 * DIM) * 3 * DIM]; // 3072 x 3072 (N-major)
__device__ __nv_bfloat16 g_woT [(size_t)DIM * 3 * DIM];        // 1024 x 3072
__device__ __nv_bfloat16 g_wfbT[(size_t)DIM * 6 * DIM];        // 1024 x 6144
__device__ float g_bqkv[3 * DIM];

// ---------------- PTX helpers ----------------------------------------------
__device__ __forceinline__ uint32_t s2u(const void* p) {
    uint32_t a;
    asm("{ .reg .u64 t; cvta.to.shared.u64 t, %1; cvt.u32.u64 %0, t; }"
        : "=r"(a) : "l"(p));
    return a;
}
__device__ __forceinline__ void cpa16(uint32_t s, const void* g) {
    asm volatile("cp.async.cg.shared.global [%0], [%1], 16;" :: "r"(s), "l"(g));
}
#define CP_COMMIT() asm volatile("cp.async.commit_group;" ::: "memory")
#define CP_WAIT1()  asm volatile("cp.async.wait_group 1;" ::: "memory")

#define LDSM4(r0, r1, r2, r3, addr) \
    asm volatile("ldmatrix.sync.aligned.m8n8.x4.shared.b16 {%0,%1,%2,%3}, [%4];" \
        : "=r"(r0), "=r"(r1), "=r"(r2), "=r"(r3) : "r"(addr))

#define MMA16816(d, a, b) \
    asm volatile("mma.sync.aligned.m16n8k16.row.col.f32.bf16.bf16.f32 " \
        "{%0,%1,%2,%3},{%4,%5,%6,%7},{%8,%9},{%0,%1,%2,%3};" \
        : "+f"((d)[0]), "+f"((d)[1]), "+f"((d)[2]), "+f"((d)[3]) \
        : "r"((a)[0]), "r"((a)[1]), "r"((a)[2]), "r"((a)[3]), \
          "r"((b)[0]), "r"((b)[1]))

__device__ __forceinline__ __nv_bfloat162 split_hi2(float a, float b,
                                                    __nv_bfloat162& lo) {
    __nv_bfloat16 ha = __float2bfloat16(a);
    __nv_bfloat16 hb = __float2bfloat16(b);
    lo = __nv_bfloat162(__float2bfloat16(a - __bfloat162float(ha)),
                        __float2bfloat16(b - __bfloat162float(hb)));
    return __nv_bfloat162(ha, hb);
}

// ---------------- LayerNorm fused with bf16 hi/lo split ---------------------
__global__ void ln_split_kernel(const float* __restrict__ x,
                                const float* __restrict__ res,
                                const float* __restrict__ g,
                                const float* __restrict__ b,
                                float* __restrict__ xn_out,          // may be null
                                __nv_bfloat16* __restrict__ split_out)
{
    int row = blockIdx.x;
    int tid = threadIdx.x;
    float4 v = ((const float4*)(x + (size_t)row * DIM))[tid];
    if (res) {
        float4 r = ((const float4*)(res + (size_t)row * DIM))[tid];
        v.x += r.x; v.y += r.y; v.z += r.z; v.w += r.w;
    }
    float s  = v.x + v.y + v.z + v.w;
    float ss = v.x*v.x + v.y*v.y + v.z*v.z + v.w*v.w;
    #pragma unroll
    for (int o = 16; o; o >>= 1) {
        s  += __shfl_xor_sync(0xffffffffu, s,  o);
        ss += __shfl_xor_sync(0xffffffffu, ss, o);
    }
    __shared__ float rs[8], rss[8];
    int wid = tid >> 5, lid = tid & 31;
    if (lid == 0) { rs[wid] = s; rss[wid] = ss; }
    __syncthreads();
    float tots = 0.f, totss = 0.f;
    #pragma unroll
    for (int i = 0; i < 8; i++) { tots += rs[i]; totss += rss[i]; }
    float mean = tots * (1.0f / DIM);
    float var  = totss * (1.0f / DIM) - mean * mean;
    float inv  = rsqrtf(var + 1e-6f);
    float4 gg = ((const float4*)g)[tid], bb = ((const float4*)b)[tid];
    float4 o;
    o.x = (v.x - mean) * inv * gg.x + bb.x;
    o.y = (v.y - mean) * inv * gg.y + bb.y;
    o.z = (v.z - mean) * inv * gg.z + bb.z;
    o.w = (v.w - mean) * inv * gg.w + bb.w;
    if (xn_out) ((float4*)(xn_out + (size_t)row * DIM))[tid] = o;

    __nv_bfloat162 l0, l1;
    __nv_bfloat162 h0 = split_hi2(o.x, o.y, l0);
    __nv_bfloat162 h1 = split_hi2(o.z, o.w, l1);
    __nv_bfloat16* base = split_out + (size_t)row * (3 * DIM) + tid * 4;
    *(__nv_bfloat162*)(base)            = h0;
    *(__nv_bfloat162*)(base + 2)        = h1;
    *(__nv_bfloat162*)(base + DIM)      = l0;
    *(__nv_bfloat162*)(base + DIM + 2)  = l1;
    *(__nv_bfloat162*)(base + 2*DIM)    = h0;
    *(__nv_bfloat162*)(base + 2*DIM + 2)= h1;
}

// ---------------- all weight splits in one kernel ----------------------------
__global__ void split_weight_all(const float* __restrict__ Wq,
                                 const float* __restrict__ Wk,
                                 const float* __restrict__ Wv,
                                 const float* __restrict__ Wo,
                                 const float* __restrict__ Wfb)
{
    size_t idx = (size_t)blockIdx.x * blockDim.x + threadIdx.x;   // < 6M
    const size_t SQ = (size_t)DIM * DIM;                          // 1M
    const float* W; __nv_bfloat16* O; int K, nofs;
    if (idx < 4 * SQ) {
        int which = (int)(idx >> 20);
        idx &= (SQ - 1);
        K = DIM;
        if      (which == 0) { W = Wq; O = g_wqkvT; nofs = 0; }
        else if (which == 1) { W = Wk; O = g_wqkvT; nofs = DIM; }
        else if (which == 2) { W = Wv; O = g_wqkvT; nofs = 2 * DIM; }
        else                 { W = Wo; O = g_woT;   nofs = 0; }
    } else {
        idx -= 4 * SQ;
        K = 2 * DIM; W = Wfb; O = g_wfbT; nofs = 0;
    }
    int k = (int)(idx % K);
    int n = (int)(idx / K);
    float x = W[(size_t)k * DIM + n];
    __nv_bfloat16 h = __float2bfloat16(x);
    __nv_bfloat16 l = __float2bfloat16(x - __bfloat162float(h));
    size_t b = (size_t)(nofs + n) * (3 * K);
    O[b + k]         = h;
    O[b + K + k]     = h;
    O[b + 2 * K + k] = l;
}

__global__ void makebias(const float* bq, const float* bk, const float* bv, float* o)
{
    int i = blockIdx.x * blockDim.x + threadIdx.x;
    if (i < DIM) o[i] = bq[i];
    else if (i < 2 * DIM) o[i] = bk[i - DIM];
    else if (i < 3 * DIM) o[i] = bv[i - 2 * DIM];
}

// ---------------- HMMA bf16 GEMM --------------------------------------------
// C[M, Nout] = A'[M, K3] * B'[Nout, K3]^T + bias   (bf16 in, fp32 accum)
// CTA tile 128x128, BK=64 (128B swizzled rows), 3-stage cp.async, 8 warps 32x64.
#define STG_OP 16384                 // 128 rows x 128 bytes per operand
#define GSMEM  (3 * 2 * STG_OP)      // 98304

__device__ __forceinline__ float gelu_exact(float x) {
    return 0.5f * x * (1.0f + erff(x * 0.7071067811865475f));
}

__global__ __launch_bounds__(256, 2)
void gemm_hmma(const __nv_bfloat16* __restrict__ A, const __nv_bfloat16* __restrict__ B,
               const float* __restrict__ bias, float* __restrict__ C,
               int K3, int ldc, int epi)
{
    extern __shared__ char smem[];
    const uint32_t sb = s2u(smem);
    const int tid  = threadIdx.x;
    const int wid  = tid >> 5, lane = tid & 31;
    const int bx   = blockIdx.x, by = blockIdx.y;
    const int wm   = wid & 3;          // 4 warps along M
    const int wn   = wid >> 2;         // 2 warps along N
    const int NT   = K3 >> 6;          // K-chunks of 64

    uint32_t sA[3], sB[3];
    #pragma unroll
    for (int s = 0; s < 3; s++) {
        sA[s] = sb + s * 2 * STG_OP;
        sB[s] = sA[s] + STG_OP;
    }

    // ---- cp.async store addressing: row = tid>>3 (+i*32), 16B chunk = tid&7
    const int lrow = tid >> 3;                       // 0..31
    const uint32_t ssw = ((tid & 7) * 16) ^ ((lrow & 7) << 4);
    const __nv_bfloat16* Ag = A + (size_t)(by * 128 + lrow) * K3 + (tid & 7) * 8;
    const __nv_bfloat16* Bg = B + (size_t)(bx * 128 + lrow) * K3 + (tid & 7) * 8;

    auto load_stage = [&](int s, int kt) {
        size_t kof = (size_t)kt * 64;
        #pragma unroll
        for (int i = 0; i < 4; i++)
            cpa16(sA[s] + (lrow + i * 32) * 128 + ssw, Ag + kof + (size_t)i * 32 * K3);
        #pragma unroll
        for (int i = 0; i < 4; i++)
            cpa16(sB[s] + (lrow + i * 32) * 128 + ssw, Bg + kof + (size_t)i * 32 * K3);
    };

    float acc[2][8][4];
    #pragma unroll
    for (int i = 0; i < 2; i++)
        #pragma unroll
        for (int j = 0; j < 8; j++)
            #pragma unroll
            for (int r = 0; r < 4; r++) acc[i][j][r] = 0.f;

    load_stage(0, 0); CP_COMMIT();
    load_stage(1, 1); CP_COMMIT();

    // ---- ldmatrix addressing (lane-constant xor masks)
    const uint32_t maskx = (lane & 7) << 4;
    // A: rows wm*32 + (lane&15) (+mt*16); col-byte = kh*32 + (lane>>4)*16
    const uint32_t aRow = (wm * 32 + (lane & 15)) * 128;
    const uint32_t aHf  = (lane >> 4) * 16;
    // B: rows wn*64 + (lane&7) + ((lane>>4)&1)*8 (+np*16); col-byte = kh*32 + ((lane>>3)&1)*16
    const uint32_t bRow = (wn * 64 + (lane & 7) + ((lane >> 4) & 1) * 8) * 128;
    const uint32_t bHf  = ((lane >> 3) & 1) * 16;

    for (int kt = 0; kt < NT; kt++) {
        CP_WAIT1();
        __syncthreads();
        int s = kt % 3;
        if (kt + 2 < NT) load_stage((kt + 2) % 3, kt + 2);
        CP_COMMIT();

        #pragma unroll
        for (int kh = 0; kh < 4; kh++) {
            const uint32_t axo = (kh * 32 + aHf) ^ maskx;
            const uint32_t bxo = (kh * 32 + bHf) ^ maskx;
            uint32_t a[2][4], b[8][2];
            #pragma unroll
            for (int mt = 0; mt < 2; mt++)
                LDSM4(a[mt][0], a[mt][1], a[mt][2], a[mt][3],
                      sA[s] + aRow + mt * 16 * 128 + axo);
            #pragma unroll
            for (int np = 0; np < 4; np++) {
                uint32_t r0, r1, r2, r3;
                LDSM4(r0, r1, r2, r3, sB[s] + bRow + np * 16 * 128 + bxo);
                b[np*2][0] = r0; b[np*2][1] = r1;
                b[np*2+1][0] = r2; b[np*2+1][1] = r3;
            }
            #pragma unroll
            for (int mt = 0; mt < 2; mt++)
                #pragma unroll
                for (int nt = 0; nt < 8; nt++)
                    MMA16816(acc[mt][nt], a[mt], b[nt]);
        }
    }

    #pragma unroll
    for (int mt = 0; mt < 2; mt++) {
        int r0 = by * 128 + wm * 32 + mt * 16 + (lane >> 2);
        #pragma unroll
        for (int nt = 0; nt < 8; nt++) {
            int col = bx * 128 + wn * 64 + nt * 8 + (lane & 3) * 2;
            float b0 = __ldg(bias + col), b1 = __ldg(bias + col + 1);
            float v0 = acc[mt][nt][0] + b0, v1 = acc[mt][nt][1] + b1;
            float v2 = acc[mt][nt][2] + b0, v3 = acc[mt][nt][3] + b1;
            if (epi) { v0 = gelu_exact(v0); v1 = gelu_exact(v1);
                       v2 = gelu_exact(v2); v3 = gelu_exact(v3); }
            *(float2*)(C + (size_t)r0 * ldc + col)       = make_float2(v0, v1);
            *(float2*)(C + (size_t)(r0 + 8) * ldc + col) = make_float2(v2, v3);
        }
    }
}

// ---------------- windowed local attention + bf16 split output --------------
__global__ void attn_kernel(const float* __restrict__ qkv,
                            __nv_bfloat16* __restrict__ out)
{
    int gw   = (blockIdx.x * blockDim.x + threadIdx.x) >> 5;
    int lane = threadIdx.x & 31;
    if (gw >= MROWS * HEADS) return;
    int h   = gw & (HEADS - 1);
    int row = gw >> 4;
    int t   = row & (TT - 1);
    int off = h * HS + lane * 2;

    auto ld2 = [&](int part, int rr) -> float2 {
        return *(const float2*)(qkv + (size_t)rr * (3 * DIM) + part * DIM + off);
    };
    auto store_split = [&](int col, float a, float b) {
        __nv_bfloat162 lo;
        __nv_bfloat162 hi = split_hi2(a, b, lo);
        __nv_bfloat16* base = out + (size_t)row * (6 * DIM) + col;
        *(__nv_bfloat162*)(base)           = hi;
        *(__nv_bfloat162*)(base + 2*DIM)   = lo;
        *(__nv_bfloat162*)(base + 4*DIM)   = hi;
    };
    const float2 zero = make_float2(0.f, 0.f);

    {   // forward
        float2 qf = (t >= 1) ? ld2(0, row - 1) : zero;
        float2 k0 = ld2(1, row);
        float2 k1 = (t >= 1) ? ld2(1, row - 1) : zero;
        float2 k2 = (t >= 2) ? ld2(1, row - 2) : zero;
        float d0 = qf.x*k0.x + qf.y*k0.y;
        float d1 = qf.x*k1.x + qf.y*k1.y;
        float d2 = qf.x*k2.x + qf.y*k2.y;
        #pragma unroll
        for (int o = 16; o; o >>= 1) {
            d0 += __shfl_xor_sync(0xffffffffu, d0, o);
            d1 += __shfl_xor_sync(0xffffffffu, d1, o);
            d2 += __shfl_xor_sync(0xffffffffu, d2, o);
        }
        d0 *= 0.125f; d1 *= 0.125f; d2 *= 0.125f;
        float m = fmaxf(d0, fmaxf(d1, d2));
        float e0 = expf(d0-m), e1 = expf(d1-m), e2 = expf(d2-m);
        float inv = 1.0f / (e0 + e1 + e2);
        e0 *= inv; e1 *= inv; e2 *= inv;
        float2 v0 = ld2(2, row);
        float2 v1 = (t >= 1) ? ld2(2, row - 1) : zero;
        float2 v2 = (t >= 2) ? ld2(2, row - 2) : zero;
        store_split(off, e0*v0.x + e1*v1.x + e2*v2.x,
                         e0*v0.y + e1*v1.y + e2*v2.y);
    }
    {   // reverse
        float2 qr = (t + 1 < TT) ? ld2(0, row + 1) : zero;
        float2 k0 = ld2(1, row);
        float2 k1 = (t + 1 < TT) ? ld2(1, row + 1) : zero;
        float2 k2 = (t + 2 < TT) ? ld2(1, row + 2) : zero;
        float d0 = qr.x*k0.x + qr.y*k0.y;
        float d1 = qr.x*k1.x + qr.y*k1.y;
        float d2 = qr.x*k2.x + qr.y*k2.y;
        #pragma unroll
        for (int o = 16; o; o >>= 1) {
            d0 += __shfl_xor_sync(0xffffffffu, d0, o);
            d1 += __shfl_xor_sync(0xffffffffu, d1, o);
            d2 += __shfl_xor_sync(0xffffffffu, d2, o);
        }
        d0 *= 0.125f; d1 *= 0.125f; d2 *= 0.125f;
        float m = fmaxf(d0, fmaxf(d1, d2));
        float e0 = expf(d0-m), e1 = expf(d1-m), e2 = expf(d2-m);
        float inv = 1.0f / (e0 + e1 + e2);
        e0 *= inv; e1 *= inv; e2 *= inv;
        float2 v0 = ld2(2, row);
        float2 v1 = (t + 1 < TT) ? ld2(2, row + 1) : zero;
        float2 v2 = (t + 2 < TT) ? ld2(2, row + 2) : zero;
        store_split(DIM + off, e0*v0.x + e1*v1.x + e2*v2.x,
                               e0*v0.y + e1*v1.y + e2*v2.y);
    }
}

// ---------------- launch ----------------------------------------------------
extern "C" void kernel_launch(void* const* d_in, const int* in_sizes, int n_in,
                              void* d_out, int out_size)
{
    const float* x   = (const float*)d_in[0];
    const float* Wq  = (const float*)d_in[1];
    const float* bq  = (const float*)d_in[2];
    const float* Wk  = (const float*)d_in[3];
    const float* bk  = (const float*)d_in[4];
    const float* Wv  = (const float*)d_in[5];
    const float* bv  = (const float*)d_in[6];
    const float* Wfb = (const float*)d_in[7];
    const float* bfb = (const float*)d_in[8];
    const float* Wo  = (const float*)d_in[9];
    const float* bo  = (const float*)d_in[10];
    const float* g1  = (const float*)d_in[11];
    const float* b1  = (const float*)d_in[12];
    const float* g2  = (const float*)d_in[13];
    const float* b2  = (const float*)d_in[14];
    float* out = (float*)d_out;

    void *p;
    float *xn, *qkv, *y, *bqkv;
    __nv_bfloat16 *a3k, *a6k, *wqkvT, *woT, *wfbT;
    cudaGetSymbolAddress(&p, g_xn);    xn    = (float*)p;
    cudaGetSymbolAddress(&p, g_qkv);   qkv   = (float*)p;
    cudaGetSymbolAddress(&p, g_y);     y     = (float*)p;
    cudaGetSymbolAddress(&p, g_bqkv);  bqkv  = (float*)p;
    cudaGetSymbolAddress(&p, g_a3k);   a3k   = (__nv_bfloat16*)p;
    cudaGetSymbolAddress(&p, g_a6k);   a6k   = (__nv_bfloat16*)p;
    cudaGetSymbolAddress(&p, g_wqkvT); wqkvT = (__nv_bfloat16*)p;
    cudaGetSymbolAddress(&p, g_woT);   woT   = (__nv_bfloat16*)p;
    cudaGetSymbolAddress(&p, g_wfbT);  wfbT  = (__nv_bfloat16*)p;

    cudaFuncSetAttribute(gemm_hmma, cudaFuncAttributeMaxDynamicSharedMemorySize, GSMEM);

    // 0) weight prep (one launch) + bias concat
    size_t welems = 6 * (size_t)DIM * DIM;  // 6M
    split_weight_all<<<(int)(welems / 256), 256>>>(Wq, Wk, Wv, Wo, Wfb);
    makebias<<<(3 * DIM) / 256, 256>>>(bq, bk, bv, bqkv);

    // 1) LN1 + split
    ln_split_kernel<<<MROWS, 256>>>(x, nullptr, g1, b1, xn, a3k);
    // 2) fused qkv GEMM: [8192, 3072]
    gemm_hmma<<<dim3(24, 64), 256, GSMEM>>>(a3k, wqkvT, bqkv, qkv, 3*DIM, 3*DIM, 0);
    // 3) local attention -> split a6k
    attn_kernel<<<(MROWS*HEADS*32)/256, 256>>>(qkv, a6k);
    // 4) y = at @ Wfb + bfb
    gemm_hmma<<<dim3(8, 64), 256, GSMEM>>>(a6k, wfbT, bfb, y, 6*DIM, DIM, 0);
    // 5) LN2(y + xn) + split
    ln_split_kernel<<<MROWS, 256>>>(y, xn, g2, b2, nullptr, a3k);
    // 6) out = gelu(z @ Wo + bo)
    gemm_hmma<<<dim3(8, 64), 256, GSMEM>>>(a3k, woT, bo, out, 3*DIM, DIM, 1);
}

// round 6
// speedup vs baseline: 3.1714x; 1.0607x over previous
#include <cuda_runtime.h>
#include <cuda_bf16.h>
#include <math.h>
#include <stdint.h>

// Problem constants
#define BATCH 2
#define TT    4096
#define DIM   1024
#define MROWS (BATCH * TT)     // 8192
#define HEADS 16
#define HS    64

// ---------------- scratch (static device globals; no allocation) ------------
__device__ float g_xn [MROWS * DIM];
__device__ float g_qkv[(size_t)MROWS * 3 * DIM];   // [q | k | v] per row
__device__ float g_y  [MROWS * DIM];

// bf16 split buffers: A' = [hi | lo | hi] along K, B' = [hi | hi | lo]
__device__ __nv_bfloat16 g_a3k [(size_t)MROWS * 3 * DIM];      // 8192 x 3072
__device__ __nv_bfloat16 g_a6k [(size_t)MROWS * 6 * DIM];      // 8192 x 6144
__device__ __nv_bfloat16 g_wqkvT[(size_t)(3 * DIM) * 3 * DIM]; // 3072 x 3072 (N-major)
__device__ __nv_bfloat16 g_woT [(size_t)DIM * 3 * DIM];        // 1024 x 3072
__device__ __nv_bfloat16 g_wfbT[(size_t)DIM * 6 * DIM];        // 1024 x 6144
__device__ float g_bqkv[3 * DIM];

// ---------------- PTX helpers ----------------------------------------------
__device__ __forceinline__ uint32_t s2u(const void* p) {
    uint32_t a;
    asm("{ .reg .u64 t; cvta.to.shared.u64 t, %1; cvt.u32.u64 %0, t; }"
        : "=r"(a) : "l"(p));
    return a;
}
__device__ __forceinline__ void cpa16(uint32_t s, const void* g) {
    asm volatile("cp.async.cg.shared.global [%0], [%1], 16;" :: "r"(s), "l"(g));
}
#define CP_COMMIT() asm volatile("cp.async.commit_group;" ::: "memory")
#define CP_WAIT1()  asm volatile("cp.async.wait_group 1;" ::: "memory")

#define LDSM4(r0, r1, r2, r3, addr) \
    asm volatile("ldmatrix.sync.aligned.m8n8.x4.shared.b16 {%0,%1,%2,%3}, [%4];" \
        : "=r"(r0), "=r"(r1), "=r"(r2), "=r"(r3) : "r"(addr))

#define MMA16816(d, a, b) \
    asm volatile("mma.sync.aligned.m16n8k16.row.col.f32.bf16.bf16.f32 " \
        "{%0,%1,%2,%3},{%4,%5,%6,%7},{%8,%9},{%0,%1,%2,%3};" \
        : "+f"((d)[0]), "+f"((d)[1]), "+f"((d)[2]), "+f"((d)[3]) \
        : "r"((a)[0]), "r"((a)[1]), "r"((a)[2]), "r"((a)[3]), \
          "r"((b)[0]), "r"((b)[1]))

__device__ __forceinline__ __nv_bfloat162 split_hi2(float a, float b,
                                                    __nv_bfloat162& lo) {
    __nv_bfloat16 ha = __float2bfloat16(a);
    __nv_bfloat16 hb = __float2bfloat16(b);
    lo = __nv_bfloat162(__float2bfloat16(a - __bfloat162float(ha)),
                        __float2bfloat16(b - __bfloat162float(hb)));
    return __nv_bfloat162(ha, hb);
}

// ---------------- LayerNorm fused with bf16 hi/lo split ---------------------
__global__ void ln_split_kernel(const float* __restrict__ x,
                                const float* __restrict__ res,
                                const float* __restrict__ g,
                                const float* __restrict__ b,
                                float* __restrict__ xn_out,          // may be null
                                __nv_bfloat16* __restrict__ split_out)
{
    int row = blockIdx.x;
    int tid = threadIdx.x;
    float4 v = ((const float4*)(x + (size_t)row * DIM))[tid];
    if (res) {
        float4 r = ((const float4*)(res + (size_t)row * DIM))[tid];
        v.x += r.x; v.y += r.y; v.z += r.z; v.w += r.w;
    }
    float s  = v.x + v.y + v.z + v.w;
    float ss = v.x*v.x + v.y*v.y + v.z*v.z + v.w*v.w;
    #pragma unroll
    for (int o = 16; o; o >>= 1) {
        s  += __shfl_xor_sync(0xffffffffu, s,  o);
        ss += __shfl_xor_sync(0xffffffffu, ss, o);
    }
    __shared__ float rs[8], rss[8];
    int wid = tid >> 5, lid = tid & 31;
    if (lid == 0) { rs[wid] = s; rss[wid] = ss; }
    __syncthreads();
    float tots = 0.f, totss = 0.f;
    #pragma unroll
    for (int i = 0; i < 8; i++) { tots += rs[i]; totss += rss[i]; }
    float mean = tots * (1.0f / DIM);
    float var  = totss * (1.0f / DIM) - mean * mean;
    float inv  = rsqrtf(var + 1e-6f);
    float4 gg = ((const float4*)g)[tid], bb = ((const float4*)b)[tid];
    float4 o;
    o.x = (v.x - mean) * inv * gg.x + bb.x;
    o.y = (v.y - mean) * inv * gg.y + bb.y;
    o.z = (v.z - mean) * inv * gg.z + bb.z;
    o.w = (v.w - mean) * inv * gg.w + bb.w;
    if (xn_out) ((float4*)(xn_out + (size_t)row * DIM))[tid] = o;

    __nv_bfloat162 l0, l1;
    __nv_bfloat162 h0 = split_hi2(o.x, o.y, l0);
    __nv_bfloat162 h1 = split_hi2(o.z, o.w, l1);
    __nv_bfloat16* base = split_out + (size_t)row * (3 * DIM) + tid * 4;
    *(__nv_bfloat162*)(base)            = h0;
    *(__nv_bfloat162*)(base + 2)        = h1;
    *(__nv_bfloat162*)(base + DIM)      = l0;
    *(__nv_bfloat162*)(base + DIM + 2)  = l1;
    *(__nv_bfloat162*)(base + 2*DIM)    = h0;
    *(__nv_bfloat162*)(base + 2*DIM + 2)= h1;
}

// ---------------- all weight splits in one kernel ----------------------------
__global__ void split_weight_all(const float* __restrict__ Wq,
                                 const float* __restrict__ Wk,
                                 const float* __restrict__ Wv,
                                 const float* __restrict__ Wo,
                                 const float* __restrict__ Wfb)
{
    size_t idx = (size_t)blockIdx.x * blockDim.x + threadIdx.x;   // < 6M
    const size_t SQ = (size_t)DIM * DIM;                          // 1M
    const float* W; __nv_bfloat16* O; int K, nofs;
    if (idx < 4 * SQ) {
        int which = (int)(idx >> 20);
        idx &= (SQ - 1);
        K = DIM;
        if      (which == 0) { W = Wq; O = g_wqkvT; nofs = 0; }
        else if (which == 1) { W = Wk; O = g_wqkvT; nofs = DIM; }
        else if (which == 2) { W = Wv; O = g_wqkvT; nofs = 2 * DIM; }
        else                 { W = Wo; O = g_woT;   nofs = 0; }
    } else {
        idx -= 4 * SQ;
        K = 2 * DIM; W = Wfb; O = g_wfbT; nofs = 0;
    }
    int k = (int)(idx % K);
    int n = (int)(idx / K);
    float x = W[(size_t)k * DIM + n];
    __nv_bfloat16 h = __float2bfloat16(x);
    __nv_bfloat16 l = __float2bfloat16(x - __bfloat162float(h));
    size_t b = (size_t)(nofs + n) * (3 * K);
    O[b + k]         = h;
    O[b + K + k]     = h;
    O[b + 2 * K + k] = l;
}

__global__ void makebias(const float* bq, const float* bk, const float* bv, float* o)
{
    int i = blockIdx.x * blockDim.x + threadIdx.x;
    if (i < DIM) o[i] = bq[i];
    else if (i < 2 * DIM) o[i] = bk[i - DIM];
    else if (i < 3 * DIM) o[i] = bv[i - 2 * DIM];
}

// ---------------- HMMA bf16 GEMM --------------------------------------------
// C[M, Nout] = A'[M, K3] * B'[Nout, K3]^T + bias   (bf16 in, fp32 accum)
// CTA tile 128x128, BK=64 (128B swizzled rows), 3-stage cp.async.
// 4 warps, warp tile 64x64 (CUTLASS shape): 8 LDSM.x4 per 32 MMAs.
#define STG_OP 16384                 // 128 rows x 128 bytes per operand
#define GSMEM  (3 * 2 * STG_OP)      // 98304

__device__ __forceinline__ float gelu_exact(float x) {
    return 0.5f * x * (1.0f + erff(x * 0.7071067811865475f));
}

__global__ __launch_bounds__(128, 2)
void gemm_hmma(const __nv_bfloat16* __restrict__ A, const __nv_bfloat16* __restrict__ B,
               const float* __restrict__ bias, float* __restrict__ C,
               int K3, int ldc, int epi)
{
    extern __shared__ char smem[];
    const uint32_t sb = s2u(smem);
    const int tid  = threadIdx.x;
    const int wid  = tid >> 5, lane = tid & 31;
    const int bx   = blockIdx.x, by = blockIdx.y;
    const int wm   = wid & 1;          // 2 warps along M (64 each)
    const int wn   = wid >> 1;         // 2 warps along N (64 each)
    const int NT   = K3 >> 6;          // K-chunks of 64

    uint32_t sA[3], sB[3];
    #pragma unroll
    for (int s = 0; s < 3; s++) {
        sA[s] = sb + s * 2 * STG_OP;
        sB[s] = sA[s] + STG_OP;
    }

    // ---- cp.async store addressing: 128 threads, 16 rows/pass, 8 passes
    const int lrow = tid >> 3;                       // 0..15
    const uint32_t ssw = ((tid & 7) * 16) ^ ((lrow & 7) << 4);
    const __nv_bfloat16* Ag = A + (size_t)(by * 128 + lrow) * K3 + (tid & 7) * 8;
    const __nv_bfloat16* Bg = B + (size_t)(bx * 128 + lrow) * K3 + (tid & 7) * 8;

    auto load_stage = [&](int s, int kt) {
        size_t kof = (size_t)kt * 64;
        #pragma unroll
        for (int i = 0; i < 8; i++)
            cpa16(sA[s] + (lrow + i * 16) * 128 + ssw, Ag + kof + (size_t)i * 16 * K3);
        #pragma unroll
        for (int i = 0; i < 8; i++)
            cpa16(sB[s] + (lrow + i * 16) * 128 + ssw, Bg + kof + (size_t)i * 16 * K3);
    };

    float acc[4][8][4];
    #pragma unroll
    for (int i = 0; i < 4; i++)
        #pragma unroll
        for (int j = 0; j < 8; j++)
            #pragma unroll
            for (int r = 0; r < 4; r++) acc[i][j][r] = 0.f;

    load_stage(0, 0); CP_COMMIT();
    load_stage(1, 1); CP_COMMIT();

    // ---- ldmatrix addressing (lane-constant xor masks)
    const uint32_t maskx = (lane & 7) << 4;
    const uint32_t aRow = (wm * 64 + (lane & 15)) * 128;
    const uint32_t aHf  = (lane >> 4) * 16;
    const uint32_t bRow = (wn * 64 + (lane & 7) + ((lane >> 4) & 1) * 8) * 128;
    const uint32_t bHf  = ((lane >> 3) & 1) * 16;

    for (int kt = 0; kt < NT; kt++) {
        CP_WAIT1();
        __syncthreads();
        int s = kt % 3;
        if (kt + 2 < NT) load_stage((kt + 2) % 3, kt + 2);
        CP_COMMIT();

        #pragma unroll
        for (int kh = 0; kh < 4; kh++) {
            const uint32_t axo = (kh * 32 + aHf) ^ maskx;
            const uint32_t bxo = (kh * 32 + bHf) ^ maskx;
            uint32_t a[4][4], b[8][2];
            #pragma unroll
            for (int mt = 0; mt < 4; mt++)
                LDSM4(a[mt][0], a[mt][1], a[mt][2], a[mt][3],
                      sA[s] + aRow + mt * 16 * 128 + axo);
            #pragma unroll
            for (int np = 0; np < 4; np++) {
                uint32_t r0, r1, r2, r3;
                LDSM4(r0, r1, r2, r3, sB[s] + bRow + np * 16 * 128 + bxo);
                b[np*2][0] = r0; b[np*2][1] = r1;
                b[np*2+1][0] = r2; b[np*2+1][1] = r3;
            }
            #pragma unroll
            for (int mt = 0; mt < 4; mt++)
                #pragma unroll
                for (int nt = 0; nt < 8; nt++)
                    MMA16816(acc[mt][nt], a[mt], b[nt]);
        }
    }

    // epilogue: bias hoisted (independent of mt), optional gelu, direct store
    float bv0[8], bv1[8];
    #pragma unroll
    for (int nt = 0; nt < 8; nt++) {
        int col = bx * 128 + wn * 64 + nt * 8 + (lane & 3) * 2;
        bv0[nt] = __ldg(bias + col);
        bv1[nt] = __ldg(bias + col + 1);
    }
    #pragma unroll
    for (int mt = 0; mt < 4; mt++) {
        int r0 = by * 128 + wm * 64 + mt * 16 + (lane >> 2);
        #pragma unroll
        for (int nt = 0; nt < 8; nt++) {
            int col = bx * 128 + wn * 64 + nt * 8 + (lane & 3) * 2;
            float v0 = acc[mt][nt][0] + bv0[nt], v1 = acc[mt][nt][1] + bv1[nt];
            float v2 = acc[mt][nt][2] + bv0[nt], v3 = acc[mt][nt][3] + bv1[nt];
            if (epi) { v0 = gelu_exact(v0); v1 = gelu_exact(v1);
                       v2 = gelu_exact(v2); v3 = gelu_exact(v3); }
            *(float2*)(C + (size_t)r0 * ldc + col)       = make_float2(v0, v1);
            *(float2*)(C + (size_t)(r0 + 8) * ldc + col) = make_float2(v2, v3);
        }
    }
}

// ---------------- windowed local attention + bf16 split output --------------
__global__ void attn_kernel(const float* __restrict__ qkv,
                            __nv_bfloat16* __restrict__ out)
{
    int gw   = (blockIdx.x * blockDim.x + threadIdx.x) >> 5;
    int lane = threadIdx.x & 31;
    if (gw >= MROWS * HEADS) return;
    int h   = gw & (HEADS - 1);
    int row = gw >> 4;
    int t   = row & (TT - 1);
    int off = h * HS + lane * 2;

    auto ld2 = [&](int part, int rr) -> float2 {
        return *(const float2*)(qkv + (size_t)rr * (3 * DIM) + part * DIM + off);
    };
    auto store_split = [&](int col, float a, float b) {
        __nv_bfloat162 lo;
        __nv_bfloat162 hi = split_hi2(a, b, lo);
        __nv_bfloat16* base = out + (size_t)row * (6 * DIM) + col;
        *(__nv_bfloat162*)(base)           = hi;
        *(__nv_bfloat162*)(base + 2*DIM)   = lo;
        *(__nv_bfloat162*)(base + 4*DIM)   = hi;
    };
    const float2 zero = make_float2(0.f, 0.f);

    {   // forward
        float2 qf = (t >= 1) ? ld2(0, row - 1) : zero;
        float2 k0 = ld2(1, row);
        float2 k1 = (t >= 1) ? ld2(1, row - 1) : zero;
        float2 k2 = (t >= 2) ? ld2(1, row - 2) : zero;
        float d0 = qf.x*k0.x + qf.y*k0.y;
        float d1 = qf.x*k1.x + qf.y*k1.y;
        float d2 = qf.x*k2.x + qf.y*k2.y;
        #pragma unroll
        for (int o = 16; o; o >>= 1) {
            d0 += __shfl_xor_sync(0xffffffffu, d0, o);
            d1 += __shfl_xor_sync(0xffffffffu, d1, o);
            d2 += __shfl_xor_sync(0xffffffffu, d2, o);
        }
        d0 *= 0.125f; d1 *= 0.125f; d2 *= 0.125f;
        float m = fmaxf(d0, fmaxf(d1, d2));
        float e0 = expf(d0-m), e1 = expf(d1-m), e2 = expf(d2-m);
        float inv = 1.0f / (e0 + e1 + e2);
        e0 *= inv; e1 *= inv; e2 *= inv;
        float2 v0 = ld2(2, row);
        float2 v1 = (t >= 1) ? ld2(2, row - 1) : zero;
        float2 v2 = (t >= 2) ? ld2(2, row - 2) : zero;
        store_split(off, e0*v0.x + e1*v1.x + e2*v2.x,
                         e0*v0.y + e1*v1.y + e2*v2.y);
    }
    {   // reverse
        float2 qr = (t + 1 < TT) ? ld2(0, row + 1) : zero;
        float2 k0 = ld2(1, row);
        float2 k1 = (t + 1 < TT) ? ld2(1, row + 1) : zero;
        float2 k2 = (t + 2 < TT) ? ld2(1, row + 2) : zero;
        float d0 = qr.x*k0.x + qr.y*k0.y;
        float d1 = qr.x*k1.x + qr.y*k1.y;
        float d2 = qr.x*k2.x + qr.y*k2.y;
        #pragma unroll
        for (int o = 16; o; o >>= 1) {
            d0 += __shfl_xor_sync(0xffffffffu, d0, o);
            d1 += __shfl_xor_sync(0xffffffffu, d1, o);
            d2 += __shfl_xor_sync(0xffffffffu, d2, o);
        }
        d0 *= 0.125f; d1 *= 0.125f; d2 *= 0.125f;
        float m = fmaxf(d0, fmaxf(d1, d2));
        float e0 = expf(d0-m), e1 = expf(d1-m), e2 = expf(d2-m);
        float inv = 1.0f / (e0 + e1 + e2);
        e0 *= inv; e1 *= inv; e2 *= inv;
        float2 v0 = ld2(2, row);
        float2 v1 = (t + 1 < TT) ? ld2(2, row + 1) : zero;
        float2 v2 = (t + 2 < TT) ? ld2(2, row + 2) : zero;
        store_split(DIM + off, e0*v0.x + e1*v1.x + e2*v2.x,
                               e0*v0.y + e1*v1.y + e2*v2.y);
    }
}

// ---------------- launch ----------------------------------------------------
extern "C" void kernel_launch(void* const* d_in, const int* in_sizes, int n_in,
                              void* d_out, int out_size)
{
    const float* x   = (const float*)d_in[0];
    const float* Wq  = (const float*)d_in[1];
    const float* bq  = (const float*)d_in[2];
    const float* Wk  = (const float*)d_in[3];
    const float* bk  = (const float*)d_in[4];
    const float* Wv  = (const float*)d_in[5];
    const float* bv  = (const float*)d_in[6];
    const float* Wfb = (const float*)d_in[7];
    const float* bfb = (const float*)d_in[8];
    const float* Wo  = (const float*)d_in[9];
    const float* bo  = (const float*)d_in[10];
    const float* g1  = (const float*)d_in[11];
    const float* b1  = (const float*)d_in[12];
    const float* g2  = (const float*)d_in[13];
    const float* b2  = (const float*)d_in[14];
    float* out = (float*)d_out;

    void *p;
    float *xn, *qkv, *y, *bqkv;
    __nv_bfloat16 *a3k, *a6k, *wqkvT, *woT, *wfbT;
    cudaGetSymbolAddress(&p, g_xn);    xn    = (float*)p;
    cudaGetSymbolAddress(&p, g_qkv);   qkv   = (float*)p;
    cudaGetSymbolAddress(&p, g_y);     y     = (float*)p;
    cudaGetSymbolAddress(&p, g_bqkv);  bqkv  = (float*)p;
    cudaGetSymbolAddress(&p, g_a3k);   a3k   = (__nv_bfloat16*)p;
    cudaGetSymbolAddress(&p, g_a6k);   a6k   = (__nv_bfloat16*)p;
    cudaGetSymbolAddress(&p, g_wqkvT); wqkvT = (__nv_bfloat16*)p;
    cudaGetSymbolAddress(&p, g_woT);   woT   = (__nv_bfloat16*)p;
    cudaGetSymbolAddress(&p, g_wfbT);  wfbT  = (__nv_bfloat16*)p;

    cudaFuncSetAttribute(gemm_hmma, cudaFuncAttributeMaxDynamicSharedMemorySize, GSMEM);

    // 0) weight prep (one launch) + bias concat
    size_t welems = 6 * (size_t)DIM * DIM;  // 6M
    split_weight_all<<<(int)(welems / 256), 256>>>(Wq, Wk, Wv, Wo, Wfb);
    makebias<<<(3 * DIM) / 256, 256>>>(bq, bk, bv, bqkv);

    // 1) LN1 + split
    ln_split_kernel<<<MROWS, 256>>>(x, nullptr, g1, b1, xn, a3k);
    // 2) fused qkv GEMM: [8192, 3072]
    gemm_hmma<<<dim3(24, 64), 128, GSMEM>>>(a3k, wqkvT, bqkv, qkv, 3*DIM, 3*DIM, 0);
    // 3) local attention -> split a6k
    attn_kernel<<<(MROWS*HEADS*32)/256, 256>>>(qkv, a6k);
    // 4) y = at @ Wfb + bfb
    gemm_hmma<<<dim3(8, 64), 128, GSMEM>>>(a6k, wfbT, bfb, y, 6*DIM, DIM, 0);
    // 5) LN2(y + xn) + split
    ln_split_kernel<<<MROWS, 256>>>(y, xn, g2, b2, nullptr, a3k);
    // 6) out = gelu(z @ Wo + bo)
    gemm_hmma<<<dim3(8, 64), 128, GSMEM>>>(a3k, woT, bo, out, 3*DIM, DIM, 1);
}

// round 7
// speedup vs baseline: 3.2140x; 1.0134x over previous
#include <cuda_runtime.h>
#include <cuda_bf16.h>
#include <math.h>
#include <stdint.h>

// Problem constants
#define BATCH 2
#define TT    4096
#define DIM   1024
#define MROWS (BATCH * TT)     // 8192
#define HEADS 16
#define HS    64

// ---------------- scratch (static device globals; no allocation) ------------
__device__ float g_xn [MROWS * DIM];
__device__ float g_qkv[(size_t)MROWS * 3 * DIM];   // [q | k | v] per row
__device__ float g_y  [MROWS * DIM];

// bf16 split buffers: A' = [hi | lo | hi] along K, B' = [hi | hi | lo]
__device__ __nv_bfloat16 g_a3k [(size_t)MROWS * 3 * DIM];      // 8192 x 3072
__device__ __nv_bfloat16 g_a6k [(size_t)MROWS * 6 * DIM];      // 8192 x 6144
__device__ __nv_bfloat16 g_wqkvT[(size_t)(3 * DIM) * 3 * DIM]; // 3072 x 3072 (N-major)
__device__ __nv_bfloat16 g_woT [(size_t)DIM * 3 * DIM];        // 1024 x 3072
__device__ __nv_bfloat16 g_wfbT[(size_t)DIM * 6 * DIM];        // 1024 x 6144
__device__ float g_bqkv[3 * DIM];

// ---------------- PTX helpers ----------------------------------------------
__device__ __forceinline__ uint32_t s2u(const void* p) {
    uint32_t a;
    asm("{ .reg .u64 t; cvta.to.shared.u64 t, %1; cvt.u32.u64 %0, t; }"
        : "=r"(a) : "l"(p));
    return a;
}
__device__ __forceinline__ void cpa16(uint32_t s, const void* g) {
    asm volatile("cp.async.cg.shared.global [%0], [%1], 16;" :: "r"(s), "l"(g));
}
#define CP_COMMIT() asm volatile("cp.async.commit_group;" ::: "memory")
#define CP_WAIT1()  asm volatile("cp.async.wait_group 1;" ::: "memory")

#define LDSM4(r0, r1, r2, r3, addr) \
    asm volatile("ldmatrix.sync.aligned.m8n8.x4.shared.b16 {%0,%1,%2,%3}, [%4];" \
        : "=r"(r0), "=r"(r1), "=r"(r2), "=r"(r3) : "r"(addr))

#define MMA16816(d, a, b) \
    asm volatile("mma.sync.aligned.m16n8k16.row.col.f32.bf16.bf16.f32 " \
        "{%0,%1,%2,%3},{%4,%5,%6,%7},{%8,%9},{%0,%1,%2,%3};" \
        : "+f"((d)[0]), "+f"((d)[1]), "+f"((d)[2]), "+f"((d)[3]) \
        : "r"((a)[0]), "r"((a)[1]), "r"((a)[2]), "r"((a)[3]), \
          "r"((b)[0]), "r"((b)[1]))

__device__ __forceinline__ __nv_bfloat162 split_hi2(float a, float b,
                                                    __nv_bfloat162& lo) {
    __nv_bfloat16 ha = __float2bfloat16(a);
    __nv_bfloat16 hb = __float2bfloat16(b);
    lo = __nv_bfloat162(__float2bfloat16(a - __bfloat162float(ha)),
                        __float2bfloat16(b - __bfloat162float(hb)));
    return __nv_bfloat162(ha, hb);
}

// ---------------- LayerNorm fused with bf16 hi/lo split ---------------------
__global__ void ln_split_kernel(const float* __restrict__ x,
                                const float* __restrict__ res,
                                const float* __restrict__ g,
                                const float* __restrict__ b,
                                float* __restrict__ xn_out,          // may be null
                                __nv_bfloat16* __restrict__ split_out)
{
    int row = blockIdx.x;
    int tid = threadIdx.x;
    float4 v = ((const float4*)(x + (size_t)row * DIM))[tid];
    if (res) {
        float4 r = ((const float4*)(res + (size_t)row * DIM))[tid];
        v.x += r.x; v.y += r.y; v.z += r.z; v.w += r.w;
    }
    float s  = v.x + v.y + v.z + v.w;
    float ss = v.x*v.x + v.y*v.y + v.z*v.z + v.w*v.w;
    #pragma unroll
    for (int o = 16; o; o >>= 1) {
        s  += __shfl_xor_sync(0xffffffffu, s,  o);
        ss += __shfl_xor_sync(0xffffffffu, ss, o);
    }
    __shared__ float rs[8], rss[8];
    int wid = tid >> 5, lid = tid & 31;
    if (lid == 0) { rs[wid] = s; rss[wid] = ss; }
    __syncthreads();
    float tots = 0.f, totss = 0.f;
    #pragma unroll
    for (int i = 0; i < 8; i++) { tots += rs[i]; totss += rss[i]; }
    float mean = tots * (1.0f / DIM);
    float var  = totss * (1.0f / DIM) - mean * mean;
    float inv  = rsqrtf(var + 1e-6f);
    float4 gg = ((const float4*)g)[tid], bb = ((const float4*)b)[tid];
    float4 o;
    o.x = (v.x - mean) * inv * gg.x + bb.x;
    o.y = (v.y - mean) * inv * gg.y + bb.y;
    o.z = (v.z - mean) * inv * gg.z + bb.z;
    o.w = (v.w - mean) * inv * gg.w + bb.w;
    if (xn_out) ((float4*)(xn_out + (size_t)row * DIM))[tid] = o;

    __nv_bfloat162 l0, l1;
    __nv_bfloat162 h0 = split_hi2(o.x, o.y, l0);
    __nv_bfloat162 h1 = split_hi2(o.z, o.w, l1);
    __nv_bfloat16* base = split_out + (size_t)row * (3 * DIM) + tid * 4;
    *(__nv_bfloat162*)(base)            = h0;
    *(__nv_bfloat162*)(base + 2)        = h1;
    *(__nv_bfloat162*)(base + DIM)      = l0;
    *(__nv_bfloat162*)(base + DIM + 2)  = l1;
    *(__nv_bfloat162*)(base + 2*DIM)    = h0;
    *(__nv_bfloat162*)(base + 2*DIM + 2)= h1;
}

// ---------------- all weight splits in one kernel ----------------------------
__global__ void split_weight_all(const float* __restrict__ Wq,
                                 const float* __restrict__ Wk,
                                 const float* __restrict__ Wv,
                                 const float* __restrict__ Wo,
                                 const float* __restrict__ Wfb)
{
    size_t idx = (size_t)blockIdx.x * blockDim.x + threadIdx.x;   // < 6M
    const size_t SQ = (size_t)DIM * DIM;                          // 1M
    const float* W; __nv_bfloat16* O; int K, nofs;
    if (idx < 4 * SQ) {
        int which = (int)(idx >> 20);
        idx &= (SQ - 1);
        K = DIM;
        if      (which == 0) { W = Wq; O = g_wqkvT; nofs = 0; }
        else if (which == 1) { W = Wk; O = g_wqkvT; nofs = DIM; }
        else if (which == 2) { W = Wv; O = g_wqkvT; nofs = 2 * DIM; }
        else                 { W = Wo; O = g_woT;   nofs = 0; }
    } else {
        idx -= 4 * SQ;
        K = 2 * DIM; W = Wfb; O = g_wfbT; nofs = 0;
    }
    int k = (int)(idx % K);
    int n = (int)(idx / K);
    float x = W[(size_t)k * DIM + n];
    __nv_bfloat16 h = __float2bfloat16(x);
    __nv_bfloat16 l = __float2bfloat16(x - __bfloat162float(h));
    size_t b = (size_t)(nofs + n) * (3 * K);
    O[b + k]         = h;
    O[b + K + k]     = h;
    O[b + 2 * K + k] = l;
}

__global__ void makebias(const float* bq, const float* bk, const float* bv, float* o)
{
    int i = blockIdx.x * blockDim.x + threadIdx.x;
    if (i < DIM) o[i] = bq[i];
    else if (i < 2 * DIM) o[i] = bk[i - DIM];
    else if (i < 3 * DIM) o[i] = bv[i - 2 * DIM];
}

// ---------------- HMMA bf16 GEMM --------------------------------------------
// C[M, Nout] = A'[M, K3] * B'[Nout, K3]^T + bias   (bf16 in, fp32 accum)
// CTA tile 128x128, BK=64 (128B swizzled rows), 3-stage cp.async.
// 4 warps, warp tile 64x64; fragments double-buffered across kh steps.
#define STG_OP 16384                 // 128 rows x 128 bytes per operand
#define GSMEM  (3 * 2 * STG_OP)      // 98304

__device__ __forceinline__ float gelu_exact(float x) {
    return 0.5f * x * (1.0f + erff(x * 0.7071067811865475f));
}

__global__ __launch_bounds__(128, 2)
void gemm_hmma(const __nv_bfloat16* __restrict__ A, const __nv_bfloat16* __restrict__ B,
               const float* __restrict__ bias, float* __restrict__ C,
               int K3, int ldc, int epi)
{
    extern __shared__ char smem[];
    const uint32_t sb = s2u(smem);
    const int tid  = threadIdx.x;
    const int wid  = tid >> 5, lane = tid & 31;
    const int bx   = blockIdx.x, by = blockIdx.y;
    const int wm   = wid & 1;          // 2 warps along M (64 each)
    const int wn   = wid >> 1;         // 2 warps along N (64 each)
    const int NT   = K3 >> 6;          // K-chunks of 64

    uint32_t sA[3], sB[3];
    #pragma unroll
    for (int s = 0; s < 3; s++) {
        sA[s] = sb + s * 2 * STG_OP;
        sB[s] = sA[s] + STG_OP;
    }

    // ---- cp.async store addressing: 128 threads, 16 rows/pass, 8 passes
    const int lrow = tid >> 3;                       // 0..15
    const uint32_t ssw = ((tid & 7) * 16) ^ ((lrow & 7) << 4);
    const __nv_bfloat16* Ag = A + (size_t)(by * 128 + lrow) * K3 + (tid & 7) * 8;
    const __nv_bfloat16* Bg = B + (size_t)(bx * 128 + lrow) * K3 + (tid & 7) * 8;

    auto load_stage = [&](int s, int kt) {
        size_t kof = (size_t)kt * 64;
        #pragma unroll
        for (int i = 0; i < 8; i++)
            cpa16(sA[s] + (lrow + i * 16) * 128 + ssw, Ag + kof + (size_t)i * 16 * K3);
        #pragma unroll
        for (int i = 0; i < 8; i++)
            cpa16(sB[s] + (lrow + i * 16) * 128 + ssw, Bg + kof + (size_t)i * 16 * K3);
    };

    float acc[4][8][4];
    #pragma unroll
    for (int i = 0; i < 4; i++)
        #pragma unroll
        for (int j = 0; j < 8; j++)
            #pragma unroll
            for (int r = 0; r < 4; r++) acc[i][j][r] = 0.f;

    load_stage(0, 0); CP_COMMIT();
    load_stage(1, 1); CP_COMMIT();

    // ---- ldmatrix addressing: precomputed per-kh swizzled column offsets
    const uint32_t maskx = (lane & 7) << 4;
    const uint32_t aRow = (wm * 64 + (lane & 15)) * 128;
    const uint32_t bRow = (wn * 64 + (lane & 7) + ((lane >> 4) & 1) * 8) * 128;
    uint32_t axo[4], bxo[4];
    {
        const uint32_t aHf = (lane >> 4) * 16;
        const uint32_t bHf = ((lane >> 3) & 1) * 16;
        #pragma unroll
        for (int kh = 0; kh < 4; kh++) {
            axo[kh] = (kh * 32 + aHf) ^ maskx;
            bxo[kh] = (kh * 32 + bHf) ^ maskx;
        }
    }

    // fragment double buffers
    uint32_t af[2][4][4], bf[2][8][2];

    #define LD_FRAGS(buf, sAd, sBd, kh) do {                                   \
        _Pragma("unroll")                                                      \
        for (int mt = 0; mt < 4; mt++)                                         \
            LDSM4(af[buf][mt][0], af[buf][mt][1], af[buf][mt][2],              \
                  af[buf][mt][3], (sAd) + aRow + mt * 16 * 128 + axo[kh]);     \
        _Pragma("unroll")                                                      \
        for (int np = 0; np < 4; np++)                                         \
            LDSM4(bf[buf][np*2][0], bf[buf][np*2][1], bf[buf][np*2+1][0],      \
                  bf[buf][np*2+1][1], (sBd) + bRow + np * 16 * 128 + bxo[kh]); \
    } while (0)

    for (int kt = 0; kt < NT; kt++) {
        CP_WAIT1();
        __syncthreads();
        int s = kt % 3;
        if (kt + 2 < NT) load_stage((kt + 2) % 3, kt + 2);
        CP_COMMIT();

        const uint32_t sAd = sA[s], sBd = sB[s];
        LD_FRAGS(0, sAd, sBd, 0);
        #pragma unroll
        for (int kh = 0; kh < 4; kh++) {
            int cur = kh & 1;
            if (kh < 3) {
                if ((kh & 1) == 0) LD_FRAGS(1, sAd, sBd, kh + 1);
                else               LD_FRAGS(0, sAd, sBd, kh + 1);
            }
            #pragma unroll
            for (int mt = 0; mt < 4; mt++)
                #pragma unroll
                for (int nt = 0; nt < 8; nt++)
                    MMA16816(acc[mt][nt], af[cur][mt], bf[cur][nt]);
        }
    }

    // epilogue: bias hoisted, optional gelu, direct store
    float bv0[8], bv1[8];
    #pragma unroll
    for (int nt = 0; nt < 8; nt++) {
        int col = bx * 128 + wn * 64 + nt * 8 + (lane & 3) * 2;
        bv0[nt] = __ldg(bias + col);
        bv1[nt] = __ldg(bias + col + 1);
    }
    #pragma unroll
    for (int mt = 0; mt < 4; mt++) {
        int r0 = by * 128 + wm * 64 + mt * 16 + (lane >> 2);
        #pragma unroll
        for (int nt = 0; nt < 8; nt++) {
            int col = bx * 128 + wn * 64 + nt * 8 + (lane & 3) * 2;
            float v0 = acc[mt][nt][0] + bv0[nt], v1 = acc[mt][nt][1] + bv1[nt];
            float v2 = acc[mt][nt][2] + bv0[nt], v3 = acc[mt][nt][3] + bv1[nt];
            if (epi) { v0 = gelu_exact(v0); v1 = gelu_exact(v1);
                       v2 = gelu_exact(v2); v3 = gelu_exact(v3); }
            *(float2*)(C + (size_t)r0 * ldc + col)       = make_float2(v0, v1);
            *(float2*)(C + (size_t)(r0 + 8) * ldc + col) = make_float2(v2, v3);
        }
    }
    #undef LD_FRAGS
}

// ---------------- windowed local attention + bf16 split output --------------
__global__ void attn_kernel(const float* __restrict__ qkv,
                            __nv_bfloat16* __restrict__ out)
{
    int gw   = (blockIdx.x * blockDim.x + threadIdx.x) >> 5;
    int lane = threadIdx.x & 31;
    if (gw >= MROWS * HEADS) return;
    int h   = gw & (HEADS - 1);
    int row = gw >> 4;
    int t   = row & (TT - 1);
    int off = h * HS + lane * 2;

    auto ld2 = [&](int part, int rr) -> float2 {
        return *(const float2*)(qkv + (size_t)rr * (3 * DIM) + part * DIM + off);
    };
    auto store_split = [&](int col, float a, float b) {
        __nv_bfloat162 lo;
        __nv_bfloat162 hi = split_hi2(a, b, lo);
        __nv_bfloat16* base = out + (size_t)row * (6 * DIM) + col;
        *(__nv_bfloat162*)(base)           = hi;
        *(__nv_bfloat162*)(base + 2*DIM)   = lo;
        *(__nv_bfloat162*)(base + 4*DIM)   = hi;
    };
    const float2 zero = make_float2(0.f, 0.f);

    {   // forward
        float2 qf = (t >= 1) ? ld2(0, row - 1) : zero;
        float2 k0 = ld2(1, row);
        float2 k1 = (t >= 1) ? ld2(1, row - 1) : zero;
        float2 k2 = (t >= 2) ? ld2(1, row - 2) : zero;
        float d0 = qf.x*k0.x + qf.y*k0.y;
        float d1 = qf.x*k1.x + qf.y*k1.y;
        float d2 = qf.x*k2.x + qf.y*k2.y;
        #pragma unroll
        for (int o = 16; o; o >>= 1) {
            d0 += __shfl_xor_sync(0xffffffffu, d0, o);
            d1 += __shfl_xor_sync(0xffffffffu, d1, o);
            d2 += __shfl_xor_sync(0xffffffffu, d2, o);
        }
        d0 *= 0.125f; d1 *= 0.125f; d2 *= 0.125f;
        float m = fmaxf(d0, fmaxf(d1, d2));
        float e0 = expf(d0-m), e1 = expf(d1-m), e2 = expf(d2-m);
        float inv = 1.0f / (e0 + e1 + e2);
        e0 *= inv; e1 *= inv; e2 *= inv;
        float2 v0 = ld2(2, row);
        float2 v1 = (t >= 1) ? ld2(2, row - 1) : zero;
        float2 v2 = (t >= 2) ? ld2(2, row - 2) : zero;
        store_split(off, e0*v0.x + e1*v1.x + e2*v2.x,
                         e0*v0.y + e1*v1.y + e2*v2.y);
    }
    {   // reverse
        float2 qr = (t + 1 < TT) ? ld2(0, row + 1) : zero;
        float2 k0 = ld2(1, row);
        float2 k1 = (t + 1 < TT) ? ld2(1, row + 1) : zero;
        float2 k2 = (t + 2 < TT) ? ld2(1, row + 2) : zero;
        float d0 = qr.x*k0.x + qr.y*k0.y;
        float d1 = qr.x*k1.x + qr.y*k1.y;
        float d2 = qr.x*k2.x + qr.y*k2.y;
        #pragma unroll
        for (int o = 16; o; o >>= 1) {
            d0 += __shfl_xor_sync(0xffffffffu, d0, o);
            d1 += __shfl_xor_sync(0xffffffffu, d1, o);
            d2 += __shfl_xor_sync(0xffffffffu, d2, o);
        }
        d0 *= 0.125f; d1 *= 0.125f; d2 *= 0.125f;
        float m = fmaxf(d0, fmaxf(d1, d2));
        float e0 = expf(d0-m), e1 = expf(d1-m), e2 = expf(d2-m);
        float inv = 1.0f / (e0 + e1 + e2);
        e0 *= inv; e1 *= inv; e2 *= inv;
        float2 v0 = ld2(2, row);
        float2 v1 = (t + 1 < TT) ? ld2(2, row + 1) : zero;
        float2 v2 = (t + 2 < TT) ? ld2(2, row + 2) : zero;
        store_split(DIM + off, e0*v0.x + e1*v1.x + e2*v2.x,
                               e0*v0.y + e1*v1.y + e2*v2.y);
    }
}

// ---------------- launch ----------------------------------------------------
extern "C" void kernel_launch(void* const* d_in, const int* in_sizes, int n_in,
                              void* d_out, int out_size)
{
    const float* x   = (const float*)d_in[0];
    const float* Wq  = (const float*)d_in[1];
    const float* bq  = (const float*)d_in[2];
    const float* Wk  = (const float*)d_in[3];
    const float* bk  = (const float*)d_in[4];
    const float* Wv  = (const float*)d_in[5];
    const float* bv  = (const float*)d_in[6];
    const float* Wfb = (const float*)d_in[7];
    const float* bfb = (const float*)d_in[8];
    const float* Wo  = (const float*)d_in[9];
    const float* bo  = (const float*)d_in[10];
    const float* g1  = (const float*)d_in[11];
    const float* b1  = (const float*)d_in[12];
    const float* g2  = (const float*)d_in[13];
    const float* b2  = (const float*)d_in[14];
    float* out = (float*)d_out;

    void *p;
    float *xn, *qkv, *y, *bqkv;
    __nv_bfloat16 *a3k, *a6k, *wqkvT, *woT, *wfbT;
    cudaGetSymbolAddress(&p, g_xn);    xn    = (float*)p;
    cudaGetSymbolAddress(&p, g_qkv);   qkv   = (float*)p;
    cudaGetSymbolAddress(&p, g_y);     y     = (float*)p;
    cudaGetSymbolAddress(&p, g_bqkv);  bqkv  = (float*)p;
    cudaGetSymbolAddress(&p, g_a3k);   a3k   = (__nv_bfloat16*)p;
    cudaGetSymbolAddress(&p, g_a6k);   a6k   = (__nv_bfloat16*)p;
    cudaGetSymbolAddress(&p, g_wqkvT); wqkvT = (__nv_bfloat16*)p;
    cudaGetSymbolAddress(&p, g_woT);   woT   = (__nv_bfloat16*)p;
    cudaGetSymbolAddress(&p, g_wfbT);  wfbT  = (__nv_bfloat16*)p;

    cudaFuncSetAttribute(gemm_hmma, cudaFuncAttributeMaxDynamicSharedMemorySize, GSMEM);

    // 0) weight prep (one launch) + bias concat
    size_t welems = 6 * (size_t)DIM * DIM;  // 6M
    split_weight_all<<<(int)(welems / 256), 256>>>(Wq, Wk, Wv, Wo, Wfb);
    makebias<<<(3 * DIM) / 256, 256>>>(bq, bk, bv, bqkv);

    // 1) LN1 + split
    ln_split_kernel<<<MROWS, 256>>>(x, nullptr, g1, b1, xn, a3k);
    // 2) fused qkv GEMM: [8192, 3072]
    gemm_hmma<<<dim3(24, 64), 128, GSMEM>>>(a3k, wqkvT, bqkv, qkv, 3*DIM, 3*DIM, 0);
    // 3) local attention -> split a6k
    attn_kernel<<<(MROWS*HEADS*32)/256, 256>>>(qkv, a6k);
    // 4) y = at @ Wfb + bfb
    gemm_hmma<<<dim3(8, 64), 128, GSMEM>>>(a6k, wfbT, bfb, y, 6*DIM, DIM, 0);
    // 5) LN2(y + xn) + split
    ln_split_kernel<<<MROWS, 256>>>(y, xn, g2, b2, nullptr, a3k);
    // 6) out = gelu(z @ Wo + bo)
    gemm_hmma<<<dim3(8, 64), 128, GSMEM>>>(a3k, woT, bo, out, 3*DIM, DIM, 1);
}

// round 8
// speedup vs baseline: 4.4794x; 1.3937x over previous
#include <cuda_runtime.h>
#include <cuda_fp16.h>
#include <math.h>
#include <stdint.h>

// Problem constants
#define BATCH 2
#define TT    4096
#define DIM   1024
#define MROWS (BATCH * TT)     // 8192
#define HEADS 16
#define HS    64

// ---------------- scratch (static device globals; no allocation) ------------
__device__ float g_xn [MROWS * DIM];
__device__ float g_qkv[(size_t)MROWS * 3 * DIM];   // [q | k | v] per row
__device__ float g_y  [MROWS * DIM];

// fp16 split buffers: A' = [hi | lo] along K, B' = [hi | hi]
__device__ __half g_a2k [(size_t)MROWS * 2 * DIM];      // 8192 x 2048
__device__ __half g_a4k [(size_t)MROWS * 4 * DIM];      // 8192 x 4096
__device__ __half g_wqkvT[(size_t)(3 * DIM) * 2 * DIM]; // 3072 x 2048 (N-major)
__device__ __half g_woT [(size_t)DIM * 2 * DIM];        // 1024 x 2048
__device__ __half g_wfbT[(size_t)DIM * 4 * DIM];        // 1024 x 4096
__device__ float g_bqkv[3 * DIM];

// ---------------- PTX helpers ----------------------------------------------
__device__ __forceinline__ uint32_t s2u(const void* p) {
    uint32_t a;
    asm("{ .reg .u64 t; cvta.to.shared.u64 t, %1; cvt.u32.u64 %0, t; }"
        : "=r"(a) : "l"(p));
    return a;
}
__device__ __forceinline__ void cpa16(uint32_t s, const void* g) {
    asm volatile("cp.async.cg.shared.global [%0], [%1], 16;" :: "r"(s), "l"(g));
}
#define CP_COMMIT() asm volatile("cp.async.commit_group;" ::: "memory")
#define CP_WAIT1()  asm volatile("cp.async.wait_group 1;" ::: "memory")

#define LDSM4(r0, r1, r2, r3, addr) \
    asm volatile("ldmatrix.sync.aligned.m8n8.x4.shared.b16 {%0,%1,%2,%3}, [%4];" \
        : "=r"(r0), "=r"(r1), "=r"(r2), "=r"(r3) : "r"(addr))

#define MMA16816(d, a, b) \
    asm volatile("mma.sync.aligned.m16n8k16.row.col.f32.f16.f16.f32 " \
        "{%0,%1,%2,%3},{%4,%5,%6,%7},{%8,%9},{%0,%1,%2,%3};" \
        : "+f"((d)[0]), "+f"((d)[1]), "+f"((d)[2]), "+f"((d)[3]) \
        : "r"((a)[0]), "r"((a)[1]), "r"((a)[2]), "r"((a)[3]), \
          "r"((b)[0]), "r"((b)[1]))

// fp16 hi/lo split of a float pair
__device__ __forceinline__ __half2 split_hi2(float a, float b, __half2& lo) {
    __half ha = __float2half(a);
    __half hb = __float2half(b);
    lo = __halves2half2(__float2half(a - __half2float(ha)),
                        __float2half(b - __half2float(hb)));
    return __halves2half2(ha, hb);
}

// ---------------- LayerNorm fused with fp16 hi/lo split ---------------------
// out split row layout: [hi(1024) | lo(1024)]
__global__ void ln_split_kernel(const float* __restrict__ x,
                                const float* __restrict__ res,
                                const float* __restrict__ g,
                                const float* __restrict__ b,
                                float* __restrict__ xn_out,          // may be null
                                __half* __restrict__ split_out)
{
    int row = blockIdx.x;
    int tid = threadIdx.x;
    float4 v = ((const float4*)(x + (size_t)row * DIM))[tid];
    if (res) {
        float4 r = ((const float4*)(res + (size_t)row * DIM))[tid];
        v.x += r.x; v.y += r.y; v.z += r.z; v.w += r.w;
    }
    float s  = v.x + v.y + v.z + v.w;
    float ss = v.x*v.x + v.y*v.y + v.z*v.z + v.w*v.w;
    #pragma unroll
    for (int o = 16; o; o >>= 1) {
        s  += __shfl_xor_sync(0xffffffffu, s,  o);
        ss += __shfl_xor_sync(0xffffffffu, ss, o);
    }
    __shared__ float rs[8], rss[8];
    int wid = tid >> 5, lid = tid & 31;
    if (lid == 0) { rs[wid] = s; rss[wid] = ss; }
    __syncthreads();
    float tots = 0.f, totss = 0.f;
    #pragma unroll
    for (int i = 0; i < 8; i++) { tots += rs[i]; totss += rss[i]; }
    float mean = tots * (1.0f / DIM);
    float var  = totss * (1.0f / DIM) - mean * mean;
    float inv  = rsqrtf(var + 1e-6f);
    float4 gg = ((const float4*)g)[tid], bb = ((const float4*)b)[tid];
    float4 o;
    o.x = (v.x - mean) * inv * gg.x + bb.x;
    o.y = (v.y - mean) * inv * gg.y + bb.y;
    o.z = (v.z - mean) * inv * gg.z + bb.z;
    o.w = (v.w - mean) * inv * gg.w + bb.w;
    if (xn_out) ((float4*)(xn_out + (size_t)row * DIM))[tid] = o;

    __half2 l0, l1;
    __half2 h0 = split_hi2(o.x, o.y, l0);
    __half2 h1 = split_hi2(o.z, o.w, l1);
    __half* base = split_out + (size_t)row * (2 * DIM) + tid * 4;
    *(__half2*)(base)           = h0;
    *(__half2*)(base + 2)       = h1;
    *(__half2*)(base + DIM)     = l0;
    *(__half2*)(base + DIM + 2) = l1;
}

// ---------------- all weight splits in one kernel ----------------------------
// W[K,N] fp32 -> O[N, 2K] fp16 N-major as [hi | hi] (duplicated)
__global__ void split_weight_all(const float* __restrict__ Wq,
                                 const float* __restrict__ Wk,
                                 const float* __restrict__ Wv,
                                 const float* __restrict__ Wo,
                                 const float* __restrict__ Wfb)
{
    size_t idx = (size_t)blockIdx.x * blockDim.x + threadIdx.x;   // < 6M
    const size_t SQ = (size_t)DIM * DIM;                          // 1M
    const float* W; __half* O; int K, nofs;
    if (idx < 4 * SQ) {
        int which = (int)(idx >> 20);
        idx &= (SQ - 1);
        K = DIM;
        if      (which == 0) { W = Wq; O = g_wqkvT; nofs = 0; }
        else if (which == 1) { W = Wk; O = g_wqkvT; nofs = DIM; }
        else if (which == 2) { W = Wv; O = g_wqkvT; nofs = 2 * DIM; }
        else                 { W = Wo; O = g_woT;   nofs = 0; }
    } else {
        idx -= 4 * SQ;
        K = 2 * DIM; W = Wfb; O = g_wfbT; nofs = 0;
    }
    int k = (int)(idx % K);
    int n = (int)(idx / K);
    float x = W[(size_t)k * DIM + n];
    __half h = __float2half(x);
    size_t b = (size_t)(nofs + n) * (2 * K);
    O[b + k]     = h;
    O[b + K + k] = h;
}

__global__ void makebias(const float* bq, const float* bk, const float* bv, float* o)
{
    int i = blockIdx.x * blockDim.x + threadIdx.x;
    if (i < DIM) o[i] = bq[i];
    else if (i < 2 * DIM) o[i] = bk[i - DIM];
    else if (i < 3 * DIM) o[i] = bv[i - 2 * DIM];
}

// ---------------- HMMA fp16 GEMM --------------------------------------------
// C[M, Nout] = A'[M, K2] * B'[Nout, K2]^T + bias   (fp16 in, fp32 accum)
// CTA tile 128x128, BK=64 (128B swizzled rows), 3-stage cp.async.
// 4 warps, warp tile 64x64; fragments double-buffered across kh steps.
#define STG_OP 16384                 // 128 rows x 128 bytes per operand
#define GSMEM  (3 * 2 * STG_OP)      // 98304

__device__ __forceinline__ float gelu_exact(float x) {
    return 0.5f * x * (1.0f + erff(x * 0.7071067811865475f));
}

__global__ __launch_bounds__(128, 2)
void gemm_hmma(const __half* __restrict__ A, const __half* __restrict__ B,
               const float* __restrict__ bias, float* __restrict__ C,
               int K2, int ldc, int epi)
{
    extern __shared__ char smem[];
    const uint32_t sb = s2u(smem);
    const int tid  = threadIdx.x;
    const int wid  = tid >> 5, lane = tid & 31;
    const int bx   = blockIdx.x, by = blockIdx.y;
    const int wm   = wid & 1;          // 2 warps along M (64 each)
    const int wn   = wid >> 1;         // 2 warps along N (64 each)
    const int NT   = K2 >> 6;          // K-chunks of 64

    uint32_t sA[3], sB[3];
    #pragma unroll
    for (int s = 0; s < 3; s++) {
        sA[s] = sb + s * 2 * STG_OP;
        sB[s] = sA[s] + STG_OP;
    }

    // ---- cp.async store addressing: 128 threads, 16 rows/pass, 8 passes
    const int lrow = tid >> 3;                       // 0..15
    const uint32_t ssw = ((tid & 7) * 16) ^ ((lrow & 7) << 4);
    const __half* Ag = A + (size_t)(by * 128 + lrow) * K2 + (tid & 7) * 8;
    const __half* Bg = B + (size_t)(bx * 128 + lrow) * K2 + (tid & 7) * 8;

    auto load_stage = [&](int s, int kt) {
        size_t kof = (size_t)kt * 64;
        #pragma unroll
        for (int i = 0; i < 8; i++)
            cpa16(sA[s] + (lrow + i * 16) * 128 + ssw, Ag + kof + (size_t)i * 16 * K2);
        #pragma unroll
        for (int i = 0; i < 8; i++)
            cpa16(sB[s] + (lrow + i * 16) * 128 + ssw, Bg + kof + (size_t)i * 16 * K2);
    };

    float acc[4][8][4];
    #pragma unroll
    for (int i = 0; i < 4; i++)
        #pragma unroll
        for (int j = 0; j < 8; j++)
            #pragma unroll
            for (int r = 0; r < 4; r++) acc[i][j][r] = 0.f;

    load_stage(0, 0); CP_COMMIT();
    load_stage(1, 1); CP_COMMIT();

    // ---- ldmatrix addressing: precomputed per-kh swizzled column offsets
    const uint32_t maskx = (lane & 7) << 4;
    const uint32_t aRow = (wm * 64 + (lane & 15)) * 128;
    const uint32_t bRow = (wn * 64 + (lane & 7) + ((lane >> 4) & 1) * 8) * 128;
    uint32_t axo[4], bxo[4];
    {
        const uint32_t aHf = (lane >> 4) * 16;
        const uint32_t bHf = ((lane >> 3) & 1) * 16;
        #pragma unroll
        for (int kh = 0; kh < 4; kh++) {
            axo[kh] = (kh * 32 + aHf) ^ maskx;
            bxo[kh] = (kh * 32 + bHf) ^ maskx;
        }
    }

    // fragment double buffers
    uint32_t af[2][4][4], bf[2][8][2];

    #define LD_FRAGS(buf, sAd, sBd, kh) do {                                   \
        _Pragma("unroll")                                                      \
        for (int mt = 0; mt < 4; mt++)                                         \
            LDSM4(af[buf][mt][0], af[buf][mt][1], af[buf][mt][2],              \
                  af[buf][mt][3], (sAd) + aRow + mt * 16 * 128 + axo[kh]);     \
        _Pragma("unroll")                                                      \
        for (int np = 0; np < 4; np++)                                         \
            LDSM4(bf[buf][np*2][0], bf[buf][np*2][1], bf[buf][np*2+1][0],      \
                  bf[buf][np*2+1][1], (sBd) + bRow + np * 16 * 128 + bxo[kh]); \
    } while (0)

    for (int kt = 0; kt < NT; kt++) {
        CP_WAIT1();
        __syncthreads();
        int s = kt % 3;
        if (kt + 2 < NT) load_stage((kt + 2) % 3, kt + 2);
        CP_COMMIT();

        const uint32_t sAd = sA[s], sBd = sB[s];
        LD_FRAGS(0, sAd, sBd, 0);
        #pragma unroll
        for (int kh = 0; kh < 4; kh++) {
            int cur = kh & 1;
            if (kh < 3) {
                if ((kh & 1) == 0) LD_FRAGS(1, sAd, sBd, kh + 1);
                else               LD_FRAGS(0, sAd, sBd, kh + 1);
            }
            #pragma unroll
            for (int mt = 0; mt < 4; mt++)
                #pragma unroll
                for (int nt = 0; nt < 8; nt++)
                    MMA16816(acc[mt][nt], af[cur][mt], bf[cur][nt]);
        }
    }

    // epilogue: bias hoisted, optional gelu, direct store
    float bv0[8], bv1[8];
    #pragma unroll
    for (int nt = 0; nt < 8; nt++) {
        int col = bx * 128 + wn * 64 + nt * 8 + (lane & 3) * 2;
        bv0[nt] = __ldg(bias + col);
        bv1[nt] = __ldg(bias + col + 1);
    }
    #pragma unroll
    for (int mt = 0; mt < 4; mt++) {
        int r0 = by * 128 + wm * 64 + mt * 16 + (lane >> 2);
        #pragma unroll
        for (int nt = 0; nt < 8; nt++) {
            int col = bx * 128 + wn * 64 + nt * 8 + (lane & 3) * 2;
            float v0 = acc[mt][nt][0] + bv0[nt], v1 = acc[mt][nt][1] + bv1[nt];
            float v2 = acc[mt][nt][2] + bv0[nt], v3 = acc[mt][nt][3] + bv1[nt];
            if (epi) { v0 = gelu_exact(v0); v1 = gelu_exact(v1);
                       v2 = gelu_exact(v2); v3 = gelu_exact(v3); }
            *(float2*)(C + (size_t)r0 * ldc + col)       = make_float2(v0, v1);
            *(float2*)(C + (size_t)(r0 + 8) * ldc + col) = make_float2(v2, v3);
        }
    }
    #undef LD_FRAGS
}

// ---------------- windowed local attention + fp16 split output --------------
// qkv layout: row-major [MROWS, 3*DIM] = [q | k | v]
// out rows: [hi_f(1024) hi_r(1024) | lo_f(1024) lo_r(1024)]  (K2 = 4096)
__global__ void attn_kernel(const float* __restrict__ qkv,
                            __half* __restrict__ out)
{
    int gw   = (blockIdx.x * blockDim.x + threadIdx.x) >> 5;
    int lane = threadIdx.x & 31;
    if (gw >= MROWS * HEADS) return;
    int h   = gw & (HEADS - 1);
    int row = gw >> 4;
    int t   = row & (TT - 1);
    int off = h * HS + lane * 2;

    auto ld2 = [&](int part, int rr) -> float2 {
        return *(const float2*)(qkv + (size_t)rr * (3 * DIM) + part * DIM + off);
    };
    auto store_split = [&](int col, float a, float b) {
        __half2 lo;
        __half2 hi = split_hi2(a, b, lo);
        __half* base = out + (size_t)row * (4 * DIM) + col;
        *(__half2*)(base)           = hi;
        *(__half2*)(base + 2 * DIM) = lo;
    };
    const float2 zero = make_float2(0.f, 0.f);

    {   // forward
        float2 qf = (t >= 1) ? ld2(0, row - 1) : zero;
        float2 k0 = ld2(1, row);
        float2 k1 = (t >= 1) ? ld2(1, row - 1) : zero;
        float2 k2 = (t >= 2) ? ld2(1, row - 2) : zero;
        float d0 = qf.x*k0.x + qf.y*k0.y;
        float d1 = qf.x*k1.x + qf.y*k1.y;
        float d2 = qf.x*k2.x + qf.y*k2.y;
        #pragma unroll
        for (int o = 16; o; o >>= 1) {
            d0 += __shfl_xor_sync(0xffffffffu, d0, o);
            d1 += __shfl_xor_sync(0xffffffffu, d1, o);
            d2 += __shfl_xor_sync(0xffffffffu, d2, o);
        }
        d0 *= 0.125f; d1 *= 0.125f; d2 *= 0.125f;
        float m = fmaxf(d0, fmaxf(d1, d2));
        float e0 = expf(d0-m), e1 = expf(d1-m), e2 = expf(d2-m);
        float inv = 1.0f / (e0 + e1 + e2);
        e0 *= inv; e1 *= inv; e2 *= inv;
        float2 v0 = ld2(2, row);
        float2 v1 = (t >= 1) ? ld2(2, row - 1) : zero;
        float2 v2 = (t >= 2) ? ld2(2, row - 2) : zero;
        store_split(off, e0*v0.x + e1*v1.x + e2*v2.x,
                         e0*v0.y + e1*v1.y + e2*v2.y);
    }
    {   // reverse
        float2 qr = (t + 1 < TT) ? ld2(0, row + 1) : zero;
        float2 k0 = ld2(1, row);
        float2 k1 = (t + 1 < TT) ? ld2(1, row + 1) : zero;
        float2 k2 = (t + 2 < TT) ? ld2(1, row + 2) : zero;
        float d0 = qr.x*k0.x + qr.y*k0.y;
        float d1 = qr.x*k1.x + qr.y*k1.y;
        float d2 = qr.x*k2.x + qr.y*k2.y;
        #pragma unroll
        for (int o = 16; o; o >>= 1) {
            d0 += __shfl_xor_sync(0xffffffffu, d0, o);
            d1 += __shfl_xor_sync(0xffffffffu, d1, o);
            d2 += __shfl_xor_sync(0xffffffffu, d2, o);
        }
        d0 *= 0.125f; d1 *= 0.125f; d2 *= 0.125f;
        float m = fmaxf(d0, fmaxf(d1, d2));
        float e0 = expf(d0-m), e1 = expf(d1-m), e2 = expf(d2-m);
        float inv = 1.0f / (e0 + e1 + e2);
        e0 *= inv; e1 *= inv; e2 *= inv;
        float2 v0 = ld2(2, row);
        float2 v1 = (t + 1 < TT) ? ld2(2, row + 1) : zero;
        float2 v2 = (t + 2 < TT) ? ld2(2, row + 2) : zero;
        store_split(DIM + off, e0*v0.x + e1*v1.x + e2*v2.x,
                               e0*v0.y + e1*v1.y + e2*v2.y);
    }
}

// ---------------- launch ----------------------------------------------------
extern "C" void kernel_launch(void* const* d_in, const int* in_sizes, int n_in,
                              void* d_out, int out_size)
{
    const float* x   = (const float*)d_in[0];
    const float* Wq  = (const float*)d_in[1];
    const float* bq  = (const float*)d_in[2];
    const float* Wk  = (const float*)d_in[3];
    const float* bk  = (const float*)d_in[4];
    const float* Wv  = (const float*)d_in[5];
    const float* bv  = (const float*)d_in[6];
    const float* Wfb = (const float*)d_in[7];
    const float* bfb = (const float*)d_in[8];
    const float* Wo  = (const float*)d_in[9];
    const float* bo  = (const float*)d_in[10];
    const float* g1  = (const float*)d_in[11];
    const float* b1  = (const float*)d_in[12];
    const float* g2  = (const float*)d_in[13];
    const float* b2  = (const float*)d_in[14];
    float* out = (float*)d_out;

    void *p;
    float *xn, *qkv, *y, *bqkv;
    __half *a2k, *a4k, *wqkvT, *woT, *wfbT;
    cudaGetSymbolAddress(&p, g_xn);    xn    = (float*)p;
    cudaGetSymbolAddress(&p, g_qkv);   qkv   = (float*)p;
    cudaGetSymbolAddress(&p, g_y);     y     = (float*)p;
    cudaGetSymbolAddress(&p, g_bqkv);  bqkv  = (float*)p;
    cudaGetSymbolAddress(&p, g_a2k);   a2k   = (__half*)p;
    cudaGetSymbolAddress(&p, g_a4k);   a4k   = (__half*)p;
    cudaGetSymbolAddress(&p, g_wqkvT); wqkvT = (__half*)p;
    cudaGetSymbolAddress(&p, g_woT);   woT   = (__half*)p;
    cudaGetSymbolAddress(&p, g_wfbT);  wfbT  = (__half*)p;

    cudaFuncSetAttribute(gemm_hmma, cudaFuncAttributeMaxDynamicSharedMemorySize, GSMEM);

    // 0) weight prep (one launch) + bias concat
    size_t welems = 6 * (size_t)DIM * DIM;  // 6M
    split_weight_all<<<(int)(welems / 256), 256>>>(Wq, Wk, Wv, Wo, Wfb);
    makebias<<<(3 * DIM) / 256, 256>>>(bq, bk, bv, bqkv);

    // 1) LN1 + split
    ln_split_kernel<<<MROWS, 256>>>(x, nullptr, g1, b1, xn, a2k);
    // 2) fused qkv GEMM: [8192, 3072], K2 = 2048
    gemm_hmma<<<dim3(24, 64), 128, GSMEM>>>(a2k, wqkvT, bqkv, qkv, 2*DIM, 3*DIM, 0);
    // 3) local attention -> split a4k
    attn_kernel<<<(MROWS*HEADS*32)/256, 256>>>(qkv, a4k);
    // 4) y = at @ Wfb + bfb, K2 = 4096
    gemm_hmma<<<dim3(8, 64), 128, GSMEM>>>(a4k, wfbT, bfb, y, 4*DIM, DIM, 0);
    // 5) LN2(y + xn) + split
    ln_split_kernel<<<MROWS, 256>>>(y, xn, g2, b2, nullptr, a2k);
    // 6) out = gelu(z @ Wo + bo), K2 = 2048
    gemm_hmma<<<dim3(8, 64), 128, GSMEM>>>(a2k, woT, bo, out, 2*DIM, DIM, 1);
}

// round 9
// speedup vs baseline: 7.2835x; 1.6260x over previous
#include <cuda_runtime.h>
#include <cuda_fp16.h>
#include <math.h>
#include <stdint.h>

// Problem constants
#define BATCH 2
#define TT    4096
#define DIM   1024
#define MROWS (BATCH * TT)     // 8192
#define HEADS 16
#define HS    64

// ---------------- scratch (static device globals; no allocation) ------------
__device__ float g_xn [MROWS * DIM];
__device__ float g_qkv[(size_t)MROWS * 3 * DIM];   // [q | k | v] per row
__device__ float g_y  [MROWS * DIM];

// fp16 buffers (no splitting)
__device__ __half g_ah  [(size_t)MROWS * DIM];          // 8192 x 1024 (LN out)
__device__ __half g_at  [(size_t)MROWS * 2 * DIM];      // 8192 x 2048 (attn out)
__device__ __half g_wqkvT[(size_t)(3 * DIM) * DIM];     // 3072 x 1024 (N-major)
__device__ __half g_woT [(size_t)DIM * DIM];            // 1024 x 1024
__device__ __half g_wfbT[(size_t)DIM * 2 * DIM];        // 1024 x 2048
__device__ float g_bqkv[3 * DIM];

// ---------------- PTX helpers ----------------------------------------------
__device__ __forceinline__ uint32_t s2u(const void* p) {
    uint32_t a;
    asm("{ .reg .u64 t; cvta.to.shared.u64 t, %1; cvt.u32.u64 %0, t; }"
        : "=r"(a) : "l"(p));
    return a;
}
__device__ __forceinline__ void cpa16(uint32_t s, const void* g) {
    asm volatile("cp.async.cg.shared.global [%0], [%1], 16;" :: "r"(s), "l"(g));
}
#define CP_COMMIT() asm volatile("cp.async.commit_group;" ::: "memory")
#define CP_WAIT1()  asm volatile("cp.async.wait_group 1;" ::: "memory")

#define LDSM4(r0, r1, r2, r3, addr) \
    asm volatile("ldmatrix.sync.aligned.m8n8.x4.shared.b16 {%0,%1,%2,%3}, [%4];" \
        : "=r"(r0), "=r"(r1), "=r"(r2), "=r"(r3) : "r"(addr))

#define MMA16816(d, a, b) \
    asm volatile("mma.sync.aligned.m16n8k16.row.col.f32.f16.f16.f32 " \
        "{%0,%1,%2,%3},{%4,%5,%6,%7},{%8,%9},{%0,%1,%2,%3};" \
        : "+f"((d)[0]), "+f"((d)[1]), "+f"((d)[2]), "+f"((d)[3]) \
        : "r"((a)[0]), "r"((a)[1]), "r"((a)[2]), "r"((a)[3]), \
          "r"((b)[0]), "r"((b)[1]))

// ---------------- LayerNorm fused with fp16 conversion ----------------------
__global__ void ln_h_kernel(const float* __restrict__ x,
                            const float* __restrict__ res,
                            const float* __restrict__ g,
                            const float* __restrict__ b,
                            float* __restrict__ xn_out,          // may be null
                            __half* __restrict__ h_out)
{
    int row = blockIdx.x;
    int tid = threadIdx.x;
    float4 v = ((const float4*)(x + (size_t)row * DIM))[tid];
    if (res) {
        float4 r = ((const float4*)(res + (size_t)row * DIM))[tid];
        v.x += r.x; v.y += r.y; v.z += r.z; v.w += r.w;
    }
    float s  = v.x + v.y + v.z + v.w;
    float ss = v.x*v.x + v.y*v.y + v.z*v.z + v.w*v.w;
    #pragma unroll
    for (int o = 16; o; o >>= 1) {
        s  += __shfl_xor_sync(0xffffffffu, s,  o);
        ss += __shfl_xor_sync(0xffffffffu, ss, o);
    }
    __shared__ float rs[8], rss[8];
    int wid = tid >> 5, lid = tid & 31;
    if (lid == 0) { rs[wid] = s; rss[wid] = ss; }
    __syncthreads();
    float tots = 0.f, totss = 0.f;
    #pragma unroll
    for (int i = 0; i < 8; i++) { tots += rs[i]; totss += rss[i]; }
    float mean = tots * (1.0f / DIM);
    float var  = totss * (1.0f / DIM) - mean * mean;
    float inv  = rsqrtf(var + 1e-6f);
    float4 gg = ((const float4*)g)[tid], bb = ((const float4*)b)[tid];
    float4 o;
    o.x = (v.x - mean) * inv * gg.x + bb.x;
    o.y = (v.y - mean) * inv * gg.y + bb.y;
    o.z = (v.z - mean) * inv * gg.z + bb.z;
    o.w = (v.w - mean) * inv * gg.w + bb.w;
    if (xn_out) ((float4*)(xn_out + (size_t)row * DIM))[tid] = o;

    __half* base = h_out + (size_t)row * DIM + tid * 4;
    *(__half2*)(base)     = __halves2half2(__float2half(o.x), __float2half(o.y));
    *(__half2*)(base + 2) = __halves2half2(__float2half(o.z), __float2half(o.w));
}

// ---------------- all weight conversions in one kernel ----------------------
// W[K,N] fp32 -> O[N, K] fp16 (N-major)
__global__ void split_weight_all(const float* __restrict__ Wq,
                                 const float* __restrict__ Wk,
                                 const float* __restrict__ Wv,
                                 const float* __restrict__ Wo,
                                 const float* __restrict__ Wfb)
{
    size_t idx = (size_t)blockIdx.x * blockDim.x + threadIdx.x;   // < 6M
    const size_t SQ = (size_t)DIM * DIM;                          // 1M
    const float* W; __half* O; int K, nofs;
    if (idx < 4 * SQ) {
        int which = (int)(idx >> 20);
        idx &= (SQ - 1);
        K = DIM;
        if      (which == 0) { W = Wq; O = g_wqkvT; nofs = 0; }
        else if (which == 1) { W = Wk; O = g_wqkvT; nofs = DIM; }
        else if (which == 2) { W = Wv; O = g_wqkvT; nofs = 2 * DIM; }
        else                 { W = Wo; O = g_woT;   nofs = 0; }
    } else {
        idx -= 4 * SQ;
        K = 2 * DIM; W = Wfb; O = g_wfbT; nofs = 0;
    }
    int k = (int)(idx % K);
    int n = (int)(idx / K);
    float x = W[(size_t)k * DIM + n];
    O[(size_t)(nofs + n) * K + k] = __float2half(x);
}

__global__ void makebias(const float* bq, const float* bk, const float* bv, float* o)
{
    int i = blockIdx.x * blockDim.x + threadIdx.x;
    if (i < DIM) o[i] = bq[i];
    else if (i < 2 * DIM) o[i] = bk[i - DIM];
    else if (i < 3 * DIM) o[i] = bv[i - 2 * DIM];
}

// ---------------- HMMA fp16 GEMM --------------------------------------------
// C[M, Nout] = A[M, K] * B[Nout, K]^T + bias   (fp16 in, fp32 accum)
// CTA tile 128x128, BK=64 (128B swizzled rows), 3-stage cp.async.
// 4 warps, warp tile 64x64; fragments double-buffered across kh steps.
#define STG_OP 16384                 // 128 rows x 128 bytes per operand
#define GSMEM  (3 * 2 * STG_OP)      // 98304

__device__ __forceinline__ float gelu_exact(float x) {
    return 0.5f * x * (1.0f + erff(x * 0.7071067811865475f));
}

__global__ __launch_bounds__(128, 2)
void gemm_hmma(const __half* __restrict__ A, const __half* __restrict__ B,
               const float* __restrict__ bias, float* __restrict__ C,
               int KK, int ldc, int epi)
{
    extern __shared__ char smem[];
    const uint32_t sb = s2u(smem);
    const int tid  = threadIdx.x;
    const int wid  = tid >> 5, lane = tid & 31;
    const int bx   = blockIdx.x, by = blockIdx.y;
    const int wm   = wid & 1;          // 2 warps along M (64 each)
    const int wn   = wid >> 1;         // 2 warps along N (64 each)
    const int NT   = KK >> 6;          // K-chunks of 64

    uint32_t sA[3], sB[3];
    #pragma unroll
    for (int s = 0; s < 3; s++) {
        sA[s] = sb + s * 2 * STG_OP;
        sB[s] = sA[s] + STG_OP;
    }

    // ---- cp.async store addressing: 128 threads, 16 rows/pass, 8 passes
    const int lrow = tid >> 3;                       // 0..15
    const uint32_t ssw = ((tid & 7) * 16) ^ ((lrow & 7) << 4);
    const __half* Ag = A + (size_t)(by * 128 + lrow) * KK + (tid & 7) * 8;
    const __half* Bg = B + (size_t)(bx * 128 + lrow) * KK + (tid & 7) * 8;

    auto load_stage = [&](int s, int kt) {
        size_t kof = (size_t)kt * 64;
        #pragma unroll
        for (int i = 0; i < 8; i++)
            cpa16(sA[s] + (lrow + i * 16) * 128 + ssw, Ag + kof + (size_t)i * 16 * KK);
        #pragma unroll
        for (int i = 0; i < 8; i++)
            cpa16(sB[s] + (lrow + i * 16) * 128 + ssw, Bg + kof + (size_t)i * 16 * KK);
    };

    float acc[4][8][4];
    #pragma unroll
    for (int i = 0; i < 4; i++)
        #pragma unroll
        for (int j = 0; j < 8; j++)
            #pragma unroll
            for (int r = 0; r < 4; r++) acc[i][j][r] = 0.f;

    load_stage(0, 0); CP_COMMIT();
    load_stage(1, 1); CP_COMMIT();

    // ---- ldmatrix addressing: precomputed per-kh swizzled column offsets
    const uint32_t maskx = (lane & 7) << 4;
    const uint32_t aRow = (wm * 64 + (lane & 15)) * 128;
    const uint32_t bRow = (wn * 64 + (lane & 7) + ((lane >> 4) & 1) * 8) * 128;
    uint32_t axo[4], bxo[4];
    {
        const uint32_t aHf = (lane >> 4) * 16;
        const uint32_t bHf = ((lane >> 3) & 1) * 16;
        #pragma unroll
        for (int kh = 0; kh < 4; kh++) {
            axo[kh] = (kh * 32 + aHf) ^ maskx;
            bxo[kh] = (kh * 32 + bHf) ^ maskx;
        }
    }

    // fragment double buffers
    uint32_t af[2][4][4], bf[2][8][2];

    #define LD_FRAGS(buf, sAd, sBd, kh) do {                                   \
        _Pragma("unroll")                                                      \
        for (int mt = 0; mt < 4; mt++)                                         \
            LDSM4(af[buf][mt][0], af[buf][mt][1], af[buf][mt][2],              \
                  af[buf][mt][3], (sAd) + aRow + mt * 16 * 128 + axo[kh]);     \
        _Pragma("unroll")                                                      \
        for (int np = 0; np < 4; np++)                                         \
            LDSM4(bf[buf][np*2][0], bf[buf][np*2][1], bf[buf][np*2+1][0],      \
                  bf[buf][np*2+1][1], (sBd) + bRow + np * 16 * 128 + bxo[kh]); \
    } while (0)

    for (int kt = 0; kt < NT; kt++) {
        CP_WAIT1();
        __syncthreads();
        int s = kt % 3;
        if (kt + 2 < NT) load_stage((kt + 2) % 3, kt + 2);
        CP_COMMIT();

        const uint32_t sAd = sA[s], sBd = sB[s];
        LD_FRAGS(0, sAd, sBd, 0);
        #pragma unroll
        for (int kh = 0; kh < 4; kh++) {
            int cur = kh & 1;
            if (kh < 3) {
                if ((kh & 1) == 0) LD_FRAGS(1, sAd, sBd, kh + 1);
                else               LD_FRAGS(0, sAd, sBd, kh + 1);
            }
            #pragma unroll
            for (int mt = 0; mt < 4; mt++)
                #pragma unroll
                for (int nt = 0; nt < 8; nt++)
                    MMA16816(acc[mt][nt], af[cur][mt], bf[cur][nt]);
        }
    }

    // epilogue: bias hoisted, optional gelu, direct store
    float bv0[8], bv1[8];
    #pragma unroll
    for (int nt = 0; nt < 8; nt++) {
        int col = bx * 128 + wn * 64 + nt * 8 + (lane & 3) * 2;
        bv0[nt] = __ldg(bias + col);
        bv1[nt] = __ldg(bias + col + 1);
    }
    #pragma unroll
    for (int mt = 0; mt < 4; mt++) {
        int r0 = by * 128 + wm * 64 + mt * 16 + (lane >> 2);
        #pragma unroll
        for (int nt = 0; nt < 8; nt++) {
            int col = bx * 128 + wn * 64 + nt * 8 + (lane & 3) * 2;
            float v0 = acc[mt][nt][0] + bv0[nt], v1 = acc[mt][nt][1] + bv1[nt];
            float v2 = acc[mt][nt][2] + bv0[nt], v3 = acc[mt][nt][3] + bv1[nt];
            if (epi) { v0 = gelu_exact(v0); v1 = gelu_exact(v1);
                       v2 = gelu_exact(v2); v3 = gelu_exact(v3); }
            *(float2*)(C + (size_t)r0 * ldc + col)       = make_float2(v0, v1);
            *(float2*)(C + (size_t)(r0 + 8) * ldc + col) = make_float2(v2, v3);
        }
    }
    #undef LD_FRAGS
}

// ---------------- windowed local attention + fp16 output --------------------
// qkv layout: row-major [MROWS, 3*DIM] = [q | k | v]
// out rows fp16: [fwd(1024) | rev(1024)]  (K = 2048 for fb GEMM)
__global__ void attn_kernel(const float* __restrict__ qkv,
                            __half* __restrict__ out)
{
    int gw   = (blockIdx.x * blockDim.x + threadIdx.x) >> 5;
    int lane = threadIdx.x & 31;
    if (gw >= MROWS * HEADS) return;
    int h   = gw & (HEADS - 1);
    int row = gw >> 4;
    int t   = row & (TT - 1);
    int off = h * HS + lane * 2;

    auto ld2 = [&](int part, int rr) -> float2 {
        return *(const float2*)(qkv + (size_t)rr * (3 * DIM) + part * DIM + off);
    };
    const float2 zero = make_float2(0.f, 0.f);

    {   // forward
        float2 qf = (t >= 1) ? ld2(0, row - 1) : zero;
        float2 k0 = ld2(1, row);
        float2 k1 = (t >= 1) ? ld2(1, row - 1) : zero;
        float2 k2 = (t >= 2) ? ld2(1, row - 2) : zero;
        float d0 = qf.x*k0.x + qf.y*k0.y;
        float d1 = qf.x*k1.x + qf.y*k1.y;
        float d2 = qf.x*k2.x + qf.y*k2.y;
        #pragma unroll
        for (int o = 16; o; o >>= 1) {
            d0 += __shfl_xor_sync(0xffffffffu, d0, o);
            d1 += __shfl_xor_sync(0xffffffffu, d1, o);
            d2 += __shfl_xor_sync(0xffffffffu, d2, o);
        }
        d0 *= 0.125f; d1 *= 0.125f; d2 *= 0.125f;
        float m = fmaxf(d0, fmaxf(d1, d2));
        float e0 = expf(d0-m), e1 = expf(d1-m), e2 = expf(d2-m);
        float inv = 1.0f / (e0 + e1 + e2);
        e0 *= inv; e1 *= inv; e2 *= inv;
        float2 v0 = ld2(2, row);
        float2 v1 = (t >= 1) ? ld2(2, row - 1) : zero;
        float2 v2 = (t >= 2) ? ld2(2, row - 2) : zero;
        float oa = e0*v0.x + e1*v1.x + e2*v2.x;
        float ob = e0*v0.y + e1*v1.y + e2*v2.y;
        *(__half2*)(out + (size_t)row * (2 * DIM) + off) =
            __halves2half2(__float2half(oa), __float2half(ob));
    }
    {   // reverse
        float2 qr = (t + 1 < TT) ? ld2(0, row + 1) : zero;
        float2 k0 = ld2(1, row);
        float2 k1 = (t + 1 < TT) ? ld2(1, row + 1) : zero;
        float2 k2 = (t + 2 < TT) ? ld2(1, row + 2) : zero;
        float d0 = qr.x*k0.x + qr.y*k0.y;
        float d1 = qr.x*k1.x + qr.y*k1.y;
        float d2 = qr.x*k2.x + qr.y*k2.y;
        #pragma unroll
        for (int o = 16; o; o >>= 1) {
            d0 += __shfl_xor_sync(0xffffffffu, d0, o);
            d1 += __shfl_xor_sync(0xffffffffu, d1, o);
            d2 += __shfl_xor_sync(0xffffffffu, d2, o);
        }
        d0 *= 0.125f; d1 *= 0.125f; d2 *= 0.125f;
        float m = fmaxf(d0, fmaxf(d1, d2));
        float e0 = expf(d0-m), e1 = expf(d1-m), e2 = expf(d2-m);
        float inv = 1.0f / (e0 + e1 + e2);
        e0 *= inv; e1 *= inv; e2 *= inv;
        float2 v0 = ld2(2, row);
        float2 v1 = (t + 1 < TT) ? ld2(2, row + 1) : zero;
        float2 v2 = (t + 2 < TT) ? ld2(2, row + 2) : zero;
        float oa = e0*v0.x + e1*v1.x + e2*v2.x;
        float ob = e0*v0.y + e1*v1.y + e2*v2.y;
        *(__half2*)(out + (size_t)row * (2 * DIM) + DIM + off) =
            __halves2half2(__float2half(oa), __float2half(ob));
    }
}

// ---------------- launch ----------------------------------------------------
extern "C" void kernel_launch(void* const* d_in, const int* in_sizes, int n_in,
                              void* d_out, int out_size)
{
    const float* x   = (const float*)d_in[0];
    const float* Wq  = (const float*)d_in[1];
    const float* bq  = (const float*)d_in[2];
    const float* Wk  = (const float*)d_in[3];
    const float* bk  = (const float*)d_in[4];
    const float* Wv  = (const float*)d_in[5];
    const float* bv  = (const float*)d_in[6];
    const float* Wfb = (const float*)d_in[7];
    const float* bfb = (const float*)d_in[8];
    const float* Wo  = (const float*)d_in[9];
    const float* bo  = (const float*)d_in[10];
    const float* g1  = (const float*)d_in[11];
    const float* b1  = (const float*)d_in[12];
    const float* g2  = (const float*)d_in[13];
    const float* b2  = (const float*)d_in[14];
    float* out = (float*)d_out;

    void *p;
    float *xn, *qkv, *y, *bqkv;
    __half *ah, *at, *wqkvT, *woT, *wfbT;
    cudaGetSymbolAddress(&p, g_xn);    xn    = (float*)p;
    cudaGetSymbolAddress(&p, g_qkv);   qkv   = (float*)p;
    cudaGetSymbolAddress(&p, g_y);     y     = (float*)p;
    cudaGetSymbolAddress(&p, g_bqkv);  bqkv  = (float*)p;
    cudaGetSymbolAddress(&p, g_ah);    ah    = (__half*)p;
    cudaGetSymbolAddress(&p, g_at);    at    = (__half*)p;
    cudaGetSymbolAddress(&p, g_wqkvT); wqkvT = (__half*)p;
    cudaGetSymbolAddress(&p, g_woT);   woT   = (__half*)p;
    cudaGetSymbolAddress(&p, g_wfbT);  wfbT  = (__half*)p;

    cudaFuncSetAttribute(gemm_hmma, cudaFuncAttributeMaxDynamicSharedMemorySize, GSMEM);

    // 0) weight prep (one launch) + bias concat
    size_t welems = 6 * (size_t)DIM * DIM;  // 6M
    split_weight_all<<<(int)(welems / 256), 256>>>(Wq, Wk, Wv, Wo, Wfb);
    makebias<<<(3 * DIM) / 256, 256>>>(bq, bk, bv, bqkv);

    // 1) LN1 -> fp32 (residual) + fp16
    ln_h_kernel<<<MROWS, 256>>>(x, nullptr, g1, b1, xn, ah);
    // 2) fused qkv GEMM: [8192, 3072], K = 1024
    gemm_hmma<<<dim3(24, 64), 128, GSMEM>>>(ah, wqkvT, bqkv, qkv, DIM, 3*DIM, 0);
    // 3) local attention -> fp16 at [M, 2048]
    attn_kernel<<<(MROWS*HEADS*32)/256, 256>>>(qkv, at);
    // 4) y = at @ Wfb + bfb, K = 2048
    gemm_hmma<<<dim3(8, 64), 128, GSMEM>>>(at, wfbT, bfb, y, 2*DIM, DIM, 0);
    // 5) LN2(y + xn) -> fp16
    ln_h_kernel<<<MROWS, 256>>>(y, xn, g2, b2, nullptr, ah);
    // 6) out = gelu(z @ Wo + bo), K = 1024
    gemm_hmma<<<dim3(8, 64), 128, GSMEM>>>(ah, woT, bo, out, DIM, DIM, 1);
}

// round 10
// speedup vs baseline: 7.7114x; 1.0588x over previous
#include <cuda_runtime.h>
#include <cuda_fp16.h>
#include <math.h>
#include <stdint.h>

// Problem constants
#define BATCH 2
#define TT    4096
#define DIM   1024
#define MROWS (BATCH * TT)     // 8192
#define HEADS 16
#define HS    64

// ---------------- scratch (static device globals; no allocation) ------------
__device__ float g_xn [MROWS * DIM];
__device__ float g_y  [MROWS * DIM];

// fp16 buffers
__device__ __half g_qkv [(size_t)MROWS * 3 * DIM];      // [q|k|v] fp16
__device__ __half g_ah  [(size_t)MROWS * DIM];          // LN out fp16
__device__ __half g_at  [(size_t)MROWS * 2 * DIM];      // attn out fp16
__device__ __half g_wqkvT[(size_t)(3 * DIM) * DIM];     // 3072 x 1024 (N-major)
__device__ __half g_woT [(size_t)DIM * DIM];            // 1024 x 1024
__device__ __half g_wfbT[(size_t)DIM * 2 * DIM];        // 1024 x 2048
__device__ float g_bqkv[3 * DIM];

// ---------------- PTX helpers ----------------------------------------------
__device__ __forceinline__ uint32_t s2u(const void* p) {
    uint32_t a;
    asm("{ .reg .u64 t; cvta.to.shared.u64 t, %1; cvt.u32.u64 %0, t; }"
        : "=r"(a) : "l"(p));
    return a;
}
__device__ __forceinline__ void cpa16(uint32_t s, const void* g) {
    asm volatile("cp.async.cg.shared.global [%0], [%1], 16;" :: "r"(s), "l"(g));
}
#define CP_COMMIT() asm volatile("cp.async.commit_group;" ::: "memory")
#define CP_WAIT1()  asm volatile("cp.async.wait_group 1;" ::: "memory")

#define LDSM4(r0, r1, r2, r3, addr) \
    asm volatile("ldmatrix.sync.aligned.m8n8.x4.shared.b16 {%0,%1,%2,%3}, [%4];" \
        : "=r"(r0), "=r"(r1), "=r"(r2), "=r"(r3) : "r"(addr))

#define MMA16816(d, a, b) \
    asm volatile("mma.sync.aligned.m16n8k16.row.col.f32.f16.f16.f32 " \
        "{%0,%1,%2,%3},{%4,%5,%6,%7},{%8,%9},{%0,%1,%2,%3};" \
        : "+f"((d)[0]), "+f"((d)[1]), "+f"((d)[2]), "+f"((d)[3]) \
        : "r"((a)[0]), "r"((a)[1]), "r"((a)[2]), "r"((a)[3]), \
          "r"((b)[0]), "r"((b)[1]))

// ---------------- LayerNorm fused with fp16 conversion ----------------------
__global__ void ln_h_kernel(const float* __restrict__ x,
                            const float* __restrict__ res,
                            const float* __restrict__ g,
                            const float* __restrict__ b,
                            float* __restrict__ xn_out,          // may be null
                            __half* __restrict__ h_out)
{
    int row = blockIdx.x;
    int tid = threadIdx.x;
    float4 v = ((const float4*)(x + (size_t)row * DIM))[tid];
    if (res) {
        float4 r = ((const float4*)(res + (size_t)row * DIM))[tid];
        v.x += r.x; v.y += r.y; v.z += r.z; v.w += r.w;
    }
    float s  = v.x + v.y + v.z + v.w;
    float ss = v.x*v.x + v.y*v.y + v.z*v.z + v.w*v.w;
    #pragma unroll
    for (int o = 16; o; o >>= 1) {
        s  += __shfl_xor_sync(0xffffffffu, s,  o);
        ss += __shfl_xor_sync(0xffffffffu, ss, o);
    }
    __shared__ float rs[8], rss[8];
    int wid = tid >> 5, lid = tid & 31;
    if (lid == 0) { rs[wid] = s; rss[wid] = ss; }
    __syncthreads();
    float tots = 0.f, totss = 0.f;
    #pragma unroll
    for (int i = 0; i < 8; i++) { tots += rs[i]; totss += rss[i]; }
    float mean = tots * (1.0f / DIM);
    float var  = totss * (1.0f / DIM) - mean * mean;
    float inv  = rsqrtf(var + 1e-6f);
    float4 gg = ((const float4*)g)[tid], bb = ((const float4*)b)[tid];
    float4 o;
    o.x = (v.x - mean) * inv * gg.x + bb.x;
    o.y = (v.y - mean) * inv * gg.y + bb.y;
    o.z = (v.z - mean) * inv * gg.z + bb.z;
    o.w = (v.w - mean) * inv * gg.w + bb.w;
    if (xn_out) ((float4*)(xn_out + (size_t)row * DIM))[tid] = o;

    __half* base = h_out + (size_t)row * DIM + tid * 4;
    *(__half2*)(base)     = __halves2half2(__float2half(o.x), __float2half(o.y));
    *(__half2*)(base + 2) = __halves2half2(__float2half(o.z), __float2half(o.w));
}

// ---------------- all weight conversions in one kernel ----------------------
// W[K,N] fp32 -> O[N, K] fp16 (N-major)
__global__ void split_weight_all(const float* __restrict__ Wq,
                                 const float* __restrict__ Wk,
                                 const float* __restrict__ Wv,
                                 const float* __restrict__ Wo,
                                 const float* __restrict__ Wfb)
{
    size_t idx = (size_t)blockIdx.x * blockDim.x + threadIdx.x;   // < 6M
    const size_t SQ = (size_t)DIM * DIM;                          // 1M
    const float* W; __half* O; int K, nofs;
    if (idx < 4 * SQ) {
        int which = (int)(idx >> 20);
        idx &= (SQ - 1);
        K = DIM;
        if      (which == 0) { W = Wq; O = g_wqkvT; nofs = 0; }
        else if (which == 1) { W = Wk; O = g_wqkvT; nofs = DIM; }
        else if (which == 2) { W = Wv; O = g_wqkvT; nofs = 2 * DIM; }
        else                 { W = Wo; O = g_woT;   nofs = 0; }
    } else {
        idx -= 4 * SQ;
        K = 2 * DIM; W = Wfb; O = g_wfbT; nofs = 0;
    }
    int k = (int)(idx % K);
    int n = (int)(idx / K);
    float x = W[(size_t)k * DIM + n];
    O[(size_t)(nofs + n) * K + k] = __float2half(x);
}

__global__ void makebias(const float* bq, const float* bk, const float* bv, float* o)
{
    int i = blockIdx.x * blockDim.x + threadIdx.x;
    if (i < DIM) o[i] = bq[i];
    else if (i < 2 * DIM) o[i] = bk[i - DIM];
    else if (i < 3 * DIM) o[i] = bv[i - 2 * DIM];
}

// ---------------- HMMA fp16 GEMM --------------------------------------------
// C = A[M,K] * B[N,K]^T + bias.  epi: 0 = fp32 out, 1 = fp32+gelu, 2 = fp16 out
#define STG_OP 16384
#define GSMEM  (3 * 2 * STG_OP)      // 98304

__device__ __forceinline__ float gelu_exact(float x) {
    return 0.5f * x * (1.0f + erff(x * 0.7071067811865475f));
}

__global__ __launch_bounds__(128, 2)
void gemm_hmma(const __half* __restrict__ A, const __half* __restrict__ B,
               const float* __restrict__ bias, void* __restrict__ Cv,
               int KK, int ldc, int epi)
{
    extern __shared__ char smem[];
    const uint32_t sb = s2u(smem);
    const int tid  = threadIdx.x;
    const int wid  = tid >> 5, lane = tid & 31;
    const int bx   = blockIdx.x, by = blockIdx.y;
    const int wm   = wid & 1;
    const int wn   = wid >> 1;
    const int NT   = KK >> 6;

    uint32_t sA[3], sB[3];
    #pragma unroll
    for (int s = 0; s < 3; s++) {
        sA[s] = sb + s * 2 * STG_OP;
        sB[s] = sA[s] + STG_OP;
    }

    const int lrow = tid >> 3;
    const uint32_t ssw = ((tid & 7) * 16) ^ ((lrow & 7) << 4);
    const __half* Ag = A + (size_t)(by * 128 + lrow) * KK + (tid & 7) * 8;
    const __half* Bg = B + (size_t)(bx * 128 + lrow) * KK + (tid & 7) * 8;

    auto load_stage = [&](int s, int kt) {
        size_t kof = (size_t)kt * 64;
        #pragma unroll
        for (int i = 0; i < 8; i++)
            cpa16(sA[s] + (lrow + i * 16) * 128 + ssw, Ag + kof + (size_t)i * 16 * KK);
        #pragma unroll
        for (int i = 0; i < 8; i++)
            cpa16(sB[s] + (lrow + i * 16) * 128 + ssw, Bg + kof + (size_t)i * 16 * KK);
    };

    float acc[4][8][4];
    #pragma unroll
    for (int i = 0; i < 4; i++)
        #pragma unroll
        for (int j = 0; j < 8; j++)
            #pragma unroll
            for (int r = 0; r < 4; r++) acc[i][j][r] = 0.f;

    load_stage(0, 0); CP_COMMIT();
    load_stage(1, 1); CP_COMMIT();

    const uint32_t maskx = (lane & 7) << 4;
    const uint32_t aRow = (wm * 64 + (lane & 15)) * 128;
    const uint32_t bRow = (wn * 64 + (lane & 7) + ((lane >> 4) & 1) * 8) * 128;
    uint32_t axo[4], bxo[4];
    {
        const uint32_t aHf = (lane >> 4) * 16;
        const uint32_t bHf = ((lane >> 3) & 1) * 16;
        #pragma unroll
        for (int kh = 0; kh < 4; kh++) {
            axo[kh] = (kh * 32 + aHf) ^ maskx;
            bxo[kh] = (kh * 32 + bHf) ^ maskx;
        }
    }

    uint32_t af[2][4][4], bf[2][8][2];

    #define LD_FRAGS(buf, sAd, sBd, kh) do {                                   \
        _Pragma("unroll")                                                      \
        for (int mt = 0; mt < 4; mt++)                                         \
            LDSM4(af[buf][mt][0], af[buf][mt][1], af[buf][mt][2],              \
                  af[buf][mt][3], (sAd) + aRow + mt * 16 * 128 + axo[kh]);     \
        _Pragma("unroll")                                                      \
        for (int np = 0; np < 4; np++)                                         \
            LDSM4(bf[buf][np*2][0], bf[buf][np*2][1], bf[buf][np*2+1][0],      \
                  bf[buf][np*2+1][1], (sBd) + bRow + np * 16 * 128 + bxo[kh]); \
    } while (0)

    for (int kt = 0; kt < NT; kt++) {
        CP_WAIT1();
        __syncthreads();
        int s = kt % 3;
        if (kt + 2 < NT) load_stage((kt + 2) % 3, kt + 2);
        CP_COMMIT();

        const uint32_t sAd = sA[s], sBd = sB[s];
        LD_FRAGS(0, sAd, sBd, 0);
        #pragma unroll
        for (int kh = 0; kh < 4; kh++) {
            int cur = kh & 1;
            if (kh < 3) {
                if ((kh & 1) == 0) LD_FRAGS(1, sAd, sBd, kh + 1);
                else               LD_FRAGS(0, sAd, sBd, kh + 1);
            }
            #pragma unroll
            for (int mt = 0; mt < 4; mt++)
                #pragma unroll
                for (int nt = 0; nt < 8; nt++)
                    MMA16816(acc[mt][nt], af[cur][mt], bf[cur][nt]);
        }
    }

    float bv0[8], bv1[8];
    #pragma unroll
    for (int nt = 0; nt < 8; nt++) {
        int col = bx * 128 + wn * 64 + nt * 8 + (lane & 3) * 2;
        bv0[nt] = __ldg(bias + col);
        bv1[nt] = __ldg(bias + col + 1);
    }
    #pragma unroll
    for (int mt = 0; mt < 4; mt++) {
        int r0 = by * 128 + wm * 64 + mt * 16 + (lane >> 2);
        #pragma unroll
        for (int nt = 0; nt < 8; nt++) {
            int col = bx * 128 + wn * 64 + nt * 8 + (lane & 3) * 2;
            float v0 = acc[mt][nt][0] + bv0[nt], v1 = acc[mt][nt][1] + bv1[nt];
            float v2 = acc[mt][nt][2] + bv0[nt], v3 = acc[mt][nt][3] + bv1[nt];
            if (epi == 1) { v0 = gelu_exact(v0); v1 = gelu_exact(v1);
                            v2 = gelu_exact(v2); v3 = gelu_exact(v3); }
            if (epi == 2) {
                __half* Ch = (__half*)Cv;
                *(__half2*)(Ch + (size_t)r0 * ldc + col) =
                    __halves2half2(__float2half(v0), __float2half(v1));
                *(__half2*)(Ch + (size_t)(r0 + 8) * ldc + col) =
                    __halves2half2(__float2half(v2), __float2half(v3));
            } else {
                float* C = (float*)Cv;
                *(float2*)(C + (size_t)r0 * ldc + col)       = make_float2(v0, v1);
                *(float2*)(C + (size_t)(r0 + 8) * ldc + col) = make_float2(v2, v3);
            }
        }
    }
    #undef LD_FRAGS
}

// ---------------- windowed local attention (fp16 in, fp16 out) --------------
// qkv fp16 [MROWS, 3*DIM]; warp = (row, head-pair): 16 lanes x 4 elems per head.
__global__ void attn_kernel(const __half* __restrict__ qkv,
                            __half* __restrict__ out)
{
    int gw   = (blockIdx.x * blockDim.x + threadIdx.x) >> 5;
    int lane = threadIdx.x & 31;
    if (gw >= MROWS * (HEADS / 2)) return;
    int hp  = gw & 7;                 // head pair 0..7
    int row = gw >> 3;
    int t   = row & (TT - 1);
    // lanes 0-15 -> head 2*hp, lanes 16-31 -> head 2*hp+1; each lane owns 4 dims
    int off = hp * 128 + (lane >> 4) * 64 + (lane & 15) * 4;

    auto ld4 = [&](int part, int rr) -> float4 {
        uint2 u = *(const uint2*)(qkv + (size_t)rr * (3 * DIM) + part * DIM + off);
        float2 a = __half22float2(*(__half2*)&u.x);
        float2 b = __half22float2(*(__half2*)&u.y);
        return make_float4(a.x, a.y, b.x, b.y);
    };
    auto st4 = [&](int col, float a, float b, float c, float d) {
        uint2 u;
        *(__half2*)&u.x = __halves2half2(__float2half(a), __float2half(b));
        *(__half2*)&u.y = __halves2half2(__float2half(c), __float2half(d));
        *(uint2*)(out + (size_t)row * (2 * DIM) + col) = u;
    };
    const float4 zero = make_float4(0.f, 0.f, 0.f, 0.f);
    auto dot = [](float4 a, float4 b) {
        return a.x*b.x + a.y*b.y + a.z*b.z + a.w*b.w;
    };

    {   // forward: query = q[t-1], keys/values rows t, t-1, t-2
        float4 qf = (t >= 1) ? ld4(0, row - 1) : zero;
        float4 k0 = ld4(1, row);
        float4 k1 = (t >= 1) ? ld4(1, row - 1) : zero;
        float4 k2 = (t >= 2) ? ld4(1, row - 2) : zero;
        float d0 = dot(qf, k0), d1 = dot(qf, k1), d2 = dot(qf, k2);
        #pragma unroll
        for (int o = 8; o; o >>= 1) {
            d0 += __shfl_xor_sync(0xffffffffu, d0, o);
            d1 += __shfl_xor_sync(0xffffffffu, d1, o);
            d2 += __shfl_xor_sync(0xffffffffu, d2, o);
        }
        d0 *= 0.125f; d1 *= 0.125f; d2 *= 0.125f;
        float m = fmaxf(d0, fmaxf(d1, d2));
        float e0 = expf(d0-m), e1 = expf(d1-m), e2 = expf(d2-m);
        float inv = 1.0f / (e0 + e1 + e2);
        e0 *= inv; e1 *= inv; e2 *= inv;
        float4 v0 = ld4(2, row);
        float4 v1 = (t >= 1) ? ld4(2, row - 1) : zero;
        float4 v2 = (t >= 2) ? ld4(2, row - 2) : zero;
        st4(off, e0*v0.x + e1*v1.x + e2*v2.x,
                 e0*v0.y + e1*v1.y + e2*v2.y,
                 e0*v0.z + e1*v1.z + e2*v2.z,
                 e0*v0.w + e1*v1.w + e2*v2.w);
    }
    {   // reverse: query = q[t+1], keys/values rows t, t+1, t+2
        float4 qr = (t + 1 < TT) ? ld4(0, row + 1) : zero;
        float4 k0 = ld4(1, row);
        float4 k1 = (t + 1 < TT) ? ld4(1, row + 1) : zero;
        float4 k2 = (t + 2 < TT) ? ld4(1, row + 2) : zero;
        float d0 = dot(qr, k0), d1 = dot(qr, k1), d2 = dot(qr, k2);
        #pragma unroll
        for (int o = 8; o; o >>= 1) {
            d0 += __shfl_xor_sync(0xffffffffu, d0, o);
            d1 += __shfl_xor_sync(0xffffffffu, d1, o);
            d2 += __shfl_xor_sync(0xffffffffu, d2, o);
        }
        d0 *= 0.125f; d1 *= 0.125f; d2 *= 0.125f;
        float m = fmaxf(d0, fmaxf(d1, d2));
        float e0 = expf(d0-m), e1 = expf(d1-m), e2 = expf(d2-m);
        float inv = 1.0f / (e0 + e1 + e2);
        e0 *= inv; e1 *= inv; e2 *= inv;
        float4 v0 = ld4(2, row);
        float4 v1 = (t + 1 < TT) ? ld4(2, row + 1) : zero;
        float4 v2 = (t + 2 < TT) ? ld4(2, row + 2) : zero;
        st4(DIM + off, e0*v0.x + e1*v1.x + e2*v2.x,
                       e0*v0.y + e1*v1.y + e2*v2.y,
                       e0*v0.z + e1*v1.z + e2*v2.z,
                       e0*v0.w + e1*v1.w + e2*v2.w);
    }
}

// ---------------- launch ----------------------------------------------------
extern "C" void kernel_launch(void* const* d_in, const int* in_sizes, int n_in,
                              void* d_out, int out_size)
{
    const float* x   = (const float*)d_in[0];
    const float* Wq  = (const float*)d_in[1];
    const float* bq  = (const float*)d_in[2];
    const float* Wk  = (const float*)d_in[3];
    const float* bk  = (const float*)d_in[4];
    const float* Wv  = (const float*)d_in[5];
    const float* bv  = (const float*)d_in[6];
    const float* Wfb = (const float*)d_in[7];
    const float* bfb = (const float*)d_in[8];
    const float* Wo  = (const float*)d_in[9];
    const float* bo  = (const float*)d_in[10];
    const float* g1  = (const float*)d_in[11];
    const float* b1  = (const float*)d_in[12];
    const float* g2  = (const float*)d_in[13];
    const float* b2  = (const float*)d_in[14];
    float* out = (float*)d_out;

    void *p;
    float *xn, *y, *bqkv;
    __half *qkv, *ah, *at, *wqkvT, *woT, *wfbT;
    cudaGetSymbolAddress(&p, g_xn);    xn    = (float*)p;
    cudaGetSymbolAddress(&p, g_y);     y     = (float*)p;
    cudaGetSymbolAddress(&p, g_bqkv);  bqkv  = (float*)p;
    cudaGetSymbolAddress(&p, g_qkv);   qkv   = (__half*)p;
    cudaGetSymbolAddress(&p, g_ah);    ah    = (__half*)p;
    cudaGetSymbolAddress(&p, g_at);    at    = (__half*)p;
    cudaGetSymbolAddress(&p, g_wqkvT); wqkvT = (__half*)p;
    cudaGetSymbolAddress(&p, g_woT);   woT   = (__half*)p;
    cudaGetSymbolAddress(&p, g_wfbT);  wfbT  = (__half*)p;

    cudaFuncSetAttribute(gemm_hmma, cudaFuncAttributeMaxDynamicSharedMemorySize, GSMEM);

    // 0) weight prep + bias concat
    size_t welems = 6 * (size_t)DIM * DIM;
    split_weight_all<<<(int)(welems / 256), 256>>>(Wq, Wk, Wv, Wo, Wfb);
    makebias<<<(3 * DIM) / 256, 256>>>(bq, bk, bv, bqkv);

    // 1) LN1 -> fp32 (residual) + fp16
    ln_h_kernel<<<MROWS, 256>>>(x, nullptr, g1, b1, xn, ah);
    // 2) fused qkv GEMM: [8192, 3072], K=1024, fp16 out
    gemm_hmma<<<dim3(24, 64), 128, GSMEM>>>(ah, wqkvT, bqkv, qkv, DIM, 3*DIM, 2);
    // 3) local attention (fp16 -> fp16), warp = 2 heads
    attn_kernel<<<(MROWS*(HEADS/2)*32)/256, 256>>>(qkv, at);
    // 4) y = at @ Wfb + bfb, K=2048, fp32 out
    gemm_hmma<<<dim3(8, 64), 128, GSMEM>>>(at, wfbT, bfb, y, 2*DIM, DIM, 0);
    // 5) LN2(y + xn) -> fp16
    ln_h_kernel<<<MROWS, 256>>>(y, xn, g2, b2, nullptr, ah);
    // 6) out = gelu(z @ Wo + bo), K=1024, fp32+gelu
    gemm_hmma<<<dim3(8, 64), 128, GSMEM>>>(ah, woT, bo, out, DIM, DIM, 1);
}

// round 11
// speedup vs baseline: 7.9376x; 1.0293x over previous
#include <cuda_runtime.h>
#include <cuda_fp16.h>
#include <math.h>
#include <stdint.h>

// Problem constants
#define BATCH 2
#define TT    4096
#define DIM   1024
#define MROWS (BATCH * TT)     // 8192
#define HEADS 16
#define HS    64

// ---------------- scratch (static device globals; no allocation) ------------
__device__ __half g_xh  [(size_t)MROWS * DIM];          // LN1 out (GEMM A + residual)
__device__ __half g_qkv [(size_t)MROWS * 3 * DIM];      // [q|k|v] fp16
__device__ __half g_at  [(size_t)MROWS * 2 * DIM];      // attn out fp16
__device__ __half g_yh  [(size_t)MROWS * DIM];          // fb out fp16
__device__ __half g_zh  [(size_t)MROWS * DIM];          // LN2 out fp16
__device__ __half g_wqkvT[(size_t)(3 * DIM) * DIM];     // 3072 x 1024 (N-major)
__device__ __half g_woT [(size_t)DIM * DIM];            // 1024 x 1024
__device__ __half g_wfbT[(size_t)DIM * 2 * DIM];        // 1024 x 2048
__device__ float g_bqkv[3 * DIM];

// ---------------- PTX helpers ----------------------------------------------
__device__ __forceinline__ uint32_t s2u(const void* p) {
    uint32_t a;
    asm("{ .reg .u64 t; cvta.to.shared.u64 t, %1; cvt.u32.u64 %0, t; }"
        : "=r"(a) : "l"(p));
    return a;
}
__device__ __forceinline__ void cpa16(uint32_t s, const void* g) {
    asm volatile("cp.async.cg.shared.global [%0], [%1], 16;" :: "r"(s), "l"(g));
}
#define CP_COMMIT() asm volatile("cp.async.commit_group;" ::: "memory")
#define CP_WAIT1()  asm volatile("cp.async.wait_group 1;" ::: "memory")

#define LDSM4(r0, r1, r2, r3, addr) \
    asm volatile("ldmatrix.sync.aligned.m8n8.x4.shared.b16 {%0,%1,%2,%3}, [%4];" \
        : "=r"(r0), "=r"(r1), "=r"(r2), "=r"(r3) : "r"(addr))

#define MMA16816(d, a, b) \
    asm volatile("mma.sync.aligned.m16n8k16.row.col.f32.f16.f16.f32 " \
        "{%0,%1,%2,%3},{%4,%5,%6,%7},{%8,%9},{%0,%1,%2,%3};" \
        : "+f"((d)[0]), "+f"((d)[1]), "+f"((d)[2]), "+f"((d)[3]) \
        : "r"((a)[0]), "r"((a)[1]), "r"((a)[2]), "r"((a)[3]), \
          "r"((b)[0]), "r"((b)[1]))

// ---------------- LayerNorm kernels (fp16 output) ----------------------------
// shared reduction helper: given per-thread float4, produce mean & inv-std
__device__ __forceinline__ void ln_stats(float4 v, int tid, float& mean, float& inv)
{
    float s  = v.x + v.y + v.z + v.w;
    float ss = v.x*v.x + v.y*v.y + v.z*v.z + v.w*v.w;
    #pragma unroll
    for (int o = 16; o; o >>= 1) {
        s  += __shfl_xor_sync(0xffffffffu, s,  o);
        ss += __shfl_xor_sync(0xffffffffu, ss, o);
    }
    __shared__ float rs[8], rss[8];
    int wid = tid >> 5, lid = tid & 31;
    if (lid == 0) { rs[wid] = s; rss[wid] = ss; }
    __syncthreads();
    float tots = 0.f, totss = 0.f;
    #pragma unroll
    for (int i = 0; i < 8; i++) { tots += rs[i]; totss += rss[i]; }
    mean = tots * (1.0f / DIM);
    float var = totss * (1.0f / DIM) - mean * mean;
    inv = rsqrtf(var + 1e-6f);
}

// LN1: fp32 input -> fp16 out
__global__ void ln1_kernel(const float* __restrict__ x,
                           const float* __restrict__ g,
                           const float* __restrict__ b,
                           __half* __restrict__ h_out)
{
    int row = blockIdx.x;
    int tid = threadIdx.x;
    float4 v = ((const float4*)(x + (size_t)row * DIM))[tid];
    float mean, inv;
    ln_stats(v, tid, mean, inv);
    float4 gg = ((const float4*)g)[tid], bb = ((const float4*)b)[tid];
    float ox = (v.x - mean) * inv * gg.x + bb.x;
    float oy = (v.y - mean) * inv * gg.y + bb.y;
    float oz = (v.z - mean) * inv * gg.z + bb.z;
    float ow = (v.w - mean) * inv * gg.w + bb.w;
    __half* base = h_out + (size_t)row * DIM + tid * 4;
    *(__half2*)(base)     = __halves2half2(__float2half(ox), __float2half(oy));
    *(__half2*)(base + 2) = __halves2half2(__float2half(oz), __float2half(ow));
}

// LN2: fp16 y + fp16 residual -> fp16 out
__global__ void ln2_kernel(const __half* __restrict__ y,
                           const __half* __restrict__ res,
                           const float* __restrict__ g,
                           const float* __restrict__ b,
                           __half* __restrict__ h_out)
{
    int row = blockIdx.x;
    int tid = threadIdx.x;
    uint2 uy = ((const uint2*)(y   + (size_t)row * DIM))[tid];
    uint2 ur = ((const uint2*)(res + (size_t)row * DIM))[tid];
    float2 y0 = __half22float2(*(__half2*)&uy.x);
    float2 y1 = __half22float2(*(__half2*)&uy.y);
    float2 r0 = __half22float2(*(__half2*)&ur.x);
    float2 r1 = __half22float2(*(__half2*)&ur.y);
    float4 v = make_float4(y0.x + r0.x, y0.y + r0.y, y1.x + r1.x, y1.y + r1.y);
    float mean, inv;
    ln_stats(v, tid, mean, inv);
    float4 gg = ((const float4*)g)[tid], bb = ((const float4*)b)[tid];
    float ox = (v.x - mean) * inv * gg.x + bb.x;
    float oy = (v.y - mean) * inv * gg.y + bb.y;
    float oz = (v.z - mean) * inv * gg.z + bb.z;
    float ow = (v.w - mean) * inv * gg.w + bb.w;
    __half* base = h_out + (size_t)row * DIM + tid * 4;
    *(__half2*)(base)     = __halves2half2(__float2half(ox), __float2half(oy));
    *(__half2*)(base + 2) = __halves2half2(__float2half(oz), __float2half(ow));
}

// ---------------- all weight conversions in one kernel ----------------------
__global__ void split_weight_all(const float* __restrict__ Wq,
                                 const float* __restrict__ Wk,
                                 const float* __restrict__ Wv,
                                 const float* __restrict__ Wo,
                                 const float* __restrict__ Wfb)
{
    size_t idx = (size_t)blockIdx.x * blockDim.x + threadIdx.x;   // < 6M
    const size_t SQ = (size_t)DIM * DIM;                          // 1M
    const float* W; __half* O; int K, nofs;
    if (idx < 4 * SQ) {
        int which = (int)(idx >> 20);
        idx &= (SQ - 1);
        K = DIM;
        if      (which == 0) { W = Wq; O = g_wqkvT; nofs = 0; }
        else if (which == 1) { W = Wk; O = g_wqkvT; nofs = DIM; }
        else if (which == 2) { W = Wv; O = g_wqkvT; nofs = 2 * DIM; }
        else                 { W = Wo; O = g_woT;   nofs = 0; }
    } else {
        idx -= 4 * SQ;
        K = 2 * DIM; W = Wfb; O = g_wfbT; nofs = 0;
    }
    int k = (int)(idx % K);
    int n = (int)(idx / K);
    float x = W[(size_t)k * DIM + n];
    O[(size_t)(nofs + n) * K + k] = __float2half(x);
}

__global__ void makebias(const float* bq, const float* bk, const float* bv, float* o)
{
    int i = blockIdx.x * blockDim.x + threadIdx.x;
    if (i < DIM) o[i] = bq[i];
    else if (i < 2 * DIM) o[i] = bk[i - DIM];
    else if (i < 3 * DIM) o[i] = bv[i - 2 * DIM];
}

// ---------------- HMMA fp16 GEMM --------------------------------------------
// C = A[M,K] * B[N,K]^T + bias.  epi: 0 = fp32 out, 1 = fp32+gelu, 2 = fp16 out
#define STG_OP 16384
#define GSMEM  (3 * 2 * STG_OP)      // 98304

__device__ __forceinline__ float gelu_exact(float x) {
    return 0.5f * x * (1.0f + erff(x * 0.7071067811865475f));
}

__global__ __launch_bounds__(128, 2)
void gemm_hmma(const __half* __restrict__ A, const __half* __restrict__ B,
               const float* __restrict__ bias, void* __restrict__ Cv,
               int KK, int ldc, int epi)
{
    extern __shared__ char smem[];
    const uint32_t sb = s2u(smem);
    const int tid  = threadIdx.x;
    const int wid  = tid >> 5, lane = tid & 31;
    const int bx   = blockIdx.x, by = blockIdx.y;
    const int wm   = wid & 1;
    const int wn   = wid >> 1;
    const int NT   = KK >> 6;

    uint32_t sA[3], sB[3];
    #pragma unroll
    for (int s = 0; s < 3; s++) {
        sA[s] = sb + s * 2 * STG_OP;
        sB[s] = sA[s] + STG_OP;
    }

    const int lrow = tid >> 3;
    const uint32_t ssw = ((tid & 7) * 16) ^ ((lrow & 7) << 4);
    const __half* Ag = A + (size_t)(by * 128 + lrow) * KK + (tid & 7) * 8;
    const __half* Bg = B + (size_t)(bx * 128 + lrow) * KK + (tid & 7) * 8;

    auto load_stage = [&](int s, int kt) {
        size_t kof = (size_t)kt * 64;
        #pragma unroll
        for (int i = 0; i < 8; i++)
            cpa16(sA[s] + (lrow + i * 16) * 128 + ssw, Ag + kof + (size_t)i * 16 * KK);
        #pragma unroll
        for (int i = 0; i < 8; i++)
            cpa16(sB[s] + (lrow + i * 16) * 128 + ssw, Bg + kof + (size_t)i * 16 * KK);
    };

    float acc[4][8][4];
    #pragma unroll
    for (int i = 0; i < 4; i++)
        #pragma unroll
        for (int j = 0; j < 8; j++)
            #pragma unroll
            for (int r = 0; r < 4; r++) acc[i][j][r] = 0.f;

    load_stage(0, 0); CP_COMMIT();
    load_stage(1, 1); CP_COMMIT();

    const uint32_t maskx = (lane & 7) << 4;
    const uint32_t aRow = (wm * 64 + (lane & 15)) * 128;
    const uint32_t bRow = (wn * 64 + (lane & 7) + ((lane >> 4) & 1) * 8) * 128;
    uint32_t axo[4], bxo[4];
    {
        const uint32_t aHf = (lane >> 4) * 16;
        const uint32_t bHf = ((lane >> 3) & 1) * 16;
        #pragma unroll
        for (int kh = 0; kh < 4; kh++) {
            axo[kh] = (kh * 32 + aHf) ^ maskx;
            bxo[kh] = (kh * 32 + bHf) ^ maskx;
        }
    }

    uint32_t af[2][4][4], bf[2][8][2];

    #define LD_FRAGS(buf, sAd, sBd, kh) do {                                   \
        _Pragma("unroll")                                                      \
        for (int mt = 0; mt < 4; mt++)                                         \
            LDSM4(af[buf][mt][0], af[buf][mt][1], af[buf][mt][2],              \
                  af[buf][mt][3], (sAd) + aRow + mt * 16 * 128 + axo[kh]);     \
        _Pragma("unroll")                                                      \
        for (int np = 0; np < 4; np++)                                         \
            LDSM4(bf[buf][np*2][0], bf[buf][np*2][1], bf[buf][np*2+1][0],      \
                  bf[buf][np*2+1][1], (sBd) + bRow + np * 16 * 128 + bxo[kh]); \
    } while (0)

    for (int kt = 0; kt < NT; kt++) {
        CP_WAIT1();
        __syncthreads();
        int s = kt % 3;
        if (kt + 2 < NT) load_stage((kt + 2) % 3, kt + 2);
        CP_COMMIT();

        const uint32_t sAd = sA[s], sBd = sB[s];
        LD_FRAGS(0, sAd, sBd, 0);
        #pragma unroll
        for (int kh = 0; kh < 4; kh++) {
            int cur = kh & 1;
            if (kh < 3) {
                if ((kh & 1) == 0) LD_FRAGS(1, sAd, sBd, kh + 1);
                else               LD_FRAGS(0, sAd, sBd, kh + 1);
            }
            #pragma unroll
            for (int mt = 0; mt < 4; mt++)
                #pragma unroll
                for (int nt = 0; nt < 8; nt++)
                    MMA16816(acc[mt][nt], af[cur][mt], bf[cur][nt]);
        }
    }

    float bv0[8], bv1[8];
    #pragma unroll
    for (int nt = 0; nt < 8; nt++) {
        int col = bx * 128 + wn * 64 + nt * 8 + (lane & 3) * 2;
        bv0[nt] = __ldg(bias + col);
        bv1[nt] = __ldg(bias + col + 1);
    }
    #pragma unroll
    for (int mt = 0; mt < 4; mt++) {
        int r0 = by * 128 + wm * 64 + mt * 16 + (lane >> 2);
        #pragma unroll
        for (int nt = 0; nt < 8; nt++) {
            int col = bx * 128 + wn * 64 + nt * 8 + (lane & 3) * 2;
            float v0 = acc[mt][nt][0] + bv0[nt], v1 = acc[mt][nt][1] + bv1[nt];
            float v2 = acc[mt][nt][2] + bv0[nt], v3 = acc[mt][nt][3] + bv1[nt];
            if (epi == 1) { v0 = gelu_exact(v0); v1 = gelu_exact(v1);
                            v2 = gelu_exact(v2); v3 = gelu_exact(v3); }
            if (epi == 2) {
                __half* Ch = (__half*)Cv;
                *(__half2*)(Ch + (size_t)r0 * ldc + col) =
                    __halves2half2(__float2half(v0), __float2half(v1));
                *(__half2*)(Ch + (size_t)(r0 + 8) * ldc + col) =
                    __halves2half2(__float2half(v2), __float2half(v3));
            } else {
                float* C = (float*)Cv;
                *(float2*)(C + (size_t)r0 * ldc + col)       = make_float2(v0, v1);
                *(float2*)(C + (size_t)(r0 + 8) * ldc + col) = make_float2(v2, v3);
            }
        }
    }
    #undef LD_FRAGS
}

// ---------------- windowed local attention (fp16 in, fp16 out) --------------
// warp = (row, 4 heads): 8 lanes per head, each lane owns 8 dims (uint4 = 16B).
__global__ void attn_kernel(const __half* __restrict__ qkv,
                            __half* __restrict__ out)
{
    int gw   = (blockIdx.x * blockDim.x + threadIdx.x) >> 5;
    int lane = threadIdx.x & 31;
    if (gw >= MROWS * (HEADS / 4)) return;
    int quad = gw & 3;                 // head quad 0..3
    int row  = gw >> 2;
    int t    = row & (TT - 1);
    // head = quad*4 + (lane>>3); lane&7 indexes 8-dim chunk
    int off = quad * 256 + (lane >> 3) * 64 + (lane & 7) * 8;

    auto ld8 = [&](int part, int rr) -> uint4 {
        return *(const uint4*)(qkv + (size_t)rr * (3 * DIM) + part * DIM + off);
    };
    auto dot8 = [](uint4 a, uint4 b) -> float {
        float d = 0.f;
        const __half2* ah = (const __half2*)&a;
        const __half2* bh = (const __half2*)&b;
        #pragma unroll
        for (int j = 0; j < 4; j++) {
            float2 fa = __half22float2(ah[j]);
            float2 fb = __half22float2(bh[j]);
            d += fa.x * fb.x + fa.y * fb.y;
        }
        return d;
    };
    auto wsum = [](uint4 v0, uint4 v1, uint4 v2,
                   float e0, float e1, float e2) -> uint4 {
        uint4 o;
        const __half2* p0 = (const __half2*)&v0;
        const __half2* p1 = (const __half2*)&v1;
        const __half2* p2 = (const __half2*)&v2;
        __half2* po = (__half2*)&o;
        #pragma unroll
        for (int j = 0; j < 4; j++) {
            float2 f0 = __half22float2(p0[j]);
            float2 f1 = __half22float2(p1[j]);
            float2 f2 = __half22float2(p2[j]);
            float a = e0 * f0.x + e1 * f1.x + e2 * f2.x;
            float b = e0 * f0.y + e1 * f1.y + e2 * f2.y;
            po[j] = __halves2half2(__float2half(a), __float2half(b));
        }
        return o;
    };
    const uint4 zero = make_uint4(0, 0, 0, 0);

    // shared rows
    uint4 k0 = ld8(1, row);
    uint4 v0 = ld8(2, row);

    {   // forward: query = q[t-1], keys/values rows t, t-1, t-2
        uint4 qf = (t >= 1) ? ld8(0, row - 1) : zero;
        uint4 k1 = (t >= 1) ? ld8(1, row - 1) : zero;
        uint4 k2 = (t >= 2) ? ld8(1, row - 2) : zero;
        float d0 = dot8(qf, k0), d1 = dot8(qf, k1), d2 = dot8(qf, k2);
        #pragma unroll
        for (int o = 4; o; o >>= 1) {
            d0 += __shfl_xor_sync(0xffffffffu, d0, o);
            d1 += __shfl_xor_sync(0xffffffffu, d1, o);
            d2 += __shfl_xor_sync(0xffffffffu, d2, o);
        }
        d0 *= 0.125f; d1 *= 0.125f; d2 *= 0.125f;
        float m = fmaxf(d0, fmaxf(d1, d2));
        float e0 = expf(d0-m), e1 = expf(d1-m), e2 = expf(d2-m);
        float inv = 1.0f / (e0 + e1 + e2);
        e0 *= inv; e1 *= inv; e2 *= inv;
        uint4 v1 = (t >= 1) ? ld8(2, row - 1) : zero;
        uint4 v2 = (t >= 2) ? ld8(2, row - 2) : zero;
        *(uint4*)(out + (size_t)row * (2 * DIM) + off) = wsum(v0, v1, v2, e0, e1, e2);
    }
    {   // reverse: query = q[t+1], keys/values rows t, t+1, t+2
        uint4 qr = (t + 1 < TT) ? ld8(0, row + 1) : zero;
        uint4 k1 = (t + 1 < TT) ? ld8(1, row + 1) : zero;
        uint4 k2 = (t + 2 < TT) ? ld8(1, row + 2) : zero;
        float d0 = dot8(qr, k0), d1 = dot8(qr, k1), d2 = dot8(qr, k2);
        #pragma unroll
        for (int o = 4; o; o >>= 1) {
            d0 += __shfl_xor_sync(0xffffffffu, d0, o);
            d1 += __shfl_xor_sync(0xffffffffu, d1, o);
            d2 += __shfl_xor_sync(0xffffffffu, d2, o);
        }
        d0 *= 0.125f; d1 *= 0.125f; d2 *= 0.125f;
        float m = fmaxf(d0, fmaxf(d1, d2));
        float e0 = expf(d0-m), e1 = expf(d1-m), e2 = expf(d2-m);
        float inv = 1.0f / (e0 + e1 + e2);
        e0 *= inv; e1 *= inv; e2 *= inv;
        uint4 v1 = (t + 1 < TT) ? ld8(2, row + 1) : zero;
        uint4 v2 = (t + 2 < TT) ? ld8(2, row + 2) : zero;
        *(uint4*)(out + (size_t)row * (2 * DIM) + DIM + off) = wsum(v0, v1, v2, e0, e1, e2);
    }
}

// ---------------- launch ----------------------------------------------------
extern "C" void kernel_launch(void* const* d_in, const int* in_sizes, int n_in,
                              void* d_out, int out_size)
{
    const float* x   = (const float*)d_in[0];
    const float* Wq  = (const float*)d_in[1];
    const float* bq  = (const float*)d_in[2];
    const float* Wk  = (const float*)d_in[3];
    const float* bk  = (const float*)d_in[4];
    const float* Wv  = (const float*)d_in[5];
    const float* bv  = (const float*)d_in[6];
    const float* Wfb = (const float*)d_in[7];
    const float* bfb = (const float*)d_in[8];
    const float* Wo  = (const float*)d_in[9];
    const float* bo  = (const float*)d_in[10];
    const float* g1  = (const float*)d_in[11];
    const float* b1  = (const float*)d_in[12];
    const float* g2  = (const float*)d_in[13];
    const float* b2  = (const float*)d_in[14];
    float* out = (float*)d_out;

    void *p;
    float *bqkv;
    __half *xh, *qkv, *at, *yh, *zh, *wqkvT, *woT, *wfbT;
    cudaGetSymbolAddress(&p, g_bqkv);  bqkv  = (float*)p;
    cudaGetSymbolAddress(&p, g_xh);    xh    = (__half*)p;
    cudaGetSymbolAddress(&p, g_qkv);   qkv   = (__half*)p;
    cudaGetSymbolAddress(&p, g_at);    at    = (__half*)p;
    cudaGetSymbolAddress(&p, g_yh);    yh    = (__half*)p;
    cudaGetSymbolAddress(&p, g_zh);    zh    = (__half*)p;
    cudaGetSymbolAddress(&p, g_wqkvT); wqkvT = (__half*)p;
    cudaGetSymbolAddress(&p, g_woT);   woT   = (__half*)p;
    cudaGetSymbolAddress(&p, g_wfbT);  wfbT  = (__half*)p;

    cudaFuncSetAttribute(gemm_hmma, cudaFuncAttributeMaxDynamicSharedMemorySize, GSMEM);

    // 0) weight prep + bias concat
    size_t welems = 6 * (size_t)DIM * DIM;
    split_weight_all<<<(int)(welems / 256), 256>>>(Wq, Wk, Wv, Wo, Wfb);
    makebias<<<(3 * DIM) / 256, 256>>>(bq, bk, bv, bqkv);

    // 1) LN1 -> fp16 (single buffer: GEMM A + residual)
    ln1_kernel<<<MROWS, 256>>>(x, g1, b1, xh);
    // 2) fused qkv GEMM: [8192, 3072], K=1024, fp16 out
    gemm_hmma<<<dim3(24, 64), 128, GSMEM>>>(xh, wqkvT, bqkv, qkv, DIM, 3*DIM, 2);
    // 3) local attention (fp16 -> fp16), warp = 4 heads
    attn_kernel<<<(MROWS*(HEADS/4)*32)/256, 256>>>(qkv, at);
    // 4) y = at @ Wfb + bfb, K=2048, fp16 out
    gemm_hmma<<<dim3(8, 64), 128, GSMEM>>>(at, wfbT, bfb, yh, 2*DIM, DIM, 2);
    // 5) LN2(y + xh) -> fp16
    ln2_kernel<<<MROWS, 256>>>(yh, xh, g2, b2, zh);
    // 6) out = gelu(z @ Wo + bo), K=1024, fp32+gelu
    gemm_hmma<<<dim3(8, 64), 128, GSMEM>>>(zh, woT, bo, out, DIM, DIM, 1);
}

// round 12
// speedup vs baseline: 8.3600x; 1.0532x over previous
#include <cuda_runtime.h>
#include <cuda_fp16.h>
#include <math.h>
#include <stdint.h>

// Problem constants
#define BATCH 2
#define TT    4096
#define DIM   1024
#define MROWS (BATCH * TT)     // 8192
#define HEADS 16
#define HS    64

// ---------------- scratch (static device globals; no allocation) ------------
__device__ __half g_xh  [(size_t)MROWS * DIM];          // LN1 out (GEMM A + residual)
__device__ __half g_qkv [(size_t)MROWS * 3 * DIM];      // [q|k|v] fp16
__device__ __half g_at  [(size_t)MROWS * 2 * DIM];      // attn out fp16
__device__ __half g_yh  [(size_t)MROWS * DIM];          // fb out fp16
__device__ __half g_zh  [(size_t)MROWS * DIM];          // LN2 out fp16
__device__ __half g_wqkvT[(size_t)(3 * DIM) * DIM];     // 3072 x 1024 (N-major)
__device__ __half g_woT [(size_t)DIM * DIM];            // 1024 x 1024
__device__ __half g_wfbT[(size_t)DIM * 2 * DIM];        // 1024 x 2048
__device__ float g_bqkv[3 * DIM];

// ---------------- PTX helpers ----------------------------------------------
__device__ __forceinline__ uint32_t s2u(const void* p) {
    uint32_t a;
    asm("{ .reg .u64 t; cvta.to.shared.u64 t, %1; cvt.u32.u64 %0, t; }"
        : "=r"(a) : "l"(p));
    return a;
}
__device__ __forceinline__ void cpa16(uint32_t s, const void* g) {
    asm volatile("cp.async.cg.shared.global [%0], [%1], 16;" :: "r"(s), "l"(g));
}
#define CP_COMMIT() asm volatile("cp.async.commit_group;" ::: "memory")
#define CP_WAIT1()  asm volatile("cp.async.wait_group 1;" ::: "memory")

#define LDSM4(r0, r1, r2, r3, addr) \
    asm volatile("ldmatrix.sync.aligned.m8n8.x4.shared.b16 {%0,%1,%2,%3}, [%4];" \
        : "=r"(r0), "=r"(r1), "=r"(r2), "=r"(r3) : "r"(addr))

#define MMA16816(d, a, b) \
    asm volatile("mma.sync.aligned.m16n8k16.row.col.f32.f16.f16.f32 " \
        "{%0,%1,%2,%3},{%4,%5,%6,%7},{%8,%9},{%0,%1,%2,%3};" \
        : "+f"((d)[0]), "+f"((d)[1]), "+f"((d)[2]), "+f"((d)[3]) \
        : "r"((a)[0]), "r"((a)[1]), "r"((a)[2]), "r"((a)[3]), \
          "r"((b)[0]), "r"((b)[1]))

// ---------------- fused prep: LN1 + weight conversion + bias concat ---------
#define WBLOCKS 24576   // 6M elems / 256
#define BBLOCKS 12      // 3072 / 256

__global__ void prep_kernel(const float* __restrict__ x,
                            const float* __restrict__ g1,
                            const float* __restrict__ b1,
                            __half* __restrict__ xh,
                            const float* __restrict__ Wq,
                            const float* __restrict__ Wk,
                            const float* __restrict__ Wv,
                            const float* __restrict__ Wo,
                            const float* __restrict__ Wfb,
                            const float* __restrict__ bq,
                            const float* __restrict__ bk,
                            const float* __restrict__ bv,
                            float* __restrict__ bqkv)
{
    __shared__ float rs[8], rss[8];
    int blk = blockIdx.x;
    int tid = threadIdx.x;

    if (blk < MROWS) {
        // ---- LN1 row ----
        int row = blk;
        float4 v = ((const float4*)(x + (size_t)row * DIM))[tid];
        float s  = v.x + v.y + v.z + v.w;
        float ss = v.x*v.x + v.y*v.y + v.z*v.z + v.w*v.w;
        #pragma unroll
        for (int o = 16; o; o >>= 1) {
            s  += __shfl_xor_sync(0xffffffffu, s,  o);
            ss += __shfl_xor_sync(0xffffffffu, ss, o);
        }
        int wid = tid >> 5, lid = tid & 31;
        if (lid == 0) { rs[wid] = s; rss[wid] = ss; }
        __syncthreads();
        float tots = 0.f, totss = 0.f;
        #pragma unroll
        for (int i = 0; i < 8; i++) { tots += rs[i]; totss += rss[i]; }
        float mean = tots * (1.0f / DIM);
        float var  = totss * (1.0f / DIM) - mean * mean;
        float inv  = rsqrtf(var + 1e-6f);
        float4 gg = ((const float4*)g1)[tid], bb = ((const float4*)b1)[tid];
        float ox = (v.x - mean) * inv * gg.x + bb.x;
        float oy = (v.y - mean) * inv * gg.y + bb.y;
        float oz = (v.z - mean) * inv * gg.z + bb.z;
        float ow = (v.w - mean) * inv * gg.w + bb.w;
        __half* base = xh + (size_t)row * DIM + tid * 4;
        *(__half2*)(base)     = __halves2half2(__float2half(ox), __float2half(oy));
        *(__half2*)(base + 2) = __halves2half2(__float2half(oz), __float2half(ow));
        return;
    }
    blk -= MROWS;
    if (blk < WBLOCKS) {
        // ---- weight conversion: W[K,N] fp32 -> O[N,K] fp16 (N-major) ----
        size_t idx = (size_t)blk * 256 + tid;        // < 6M
        const size_t SQ = (size_t)DIM * DIM;         // 1M
        const float* W; __half* O; int K, nofs;
        if (idx < 4 * SQ) {
            int which = (int)(idx >> 20);
            idx &= (SQ - 1);
            K = DIM;
            if      (which == 0) { W = Wq; O = g_wqkvT; nofs = 0; }
            else if (which == 1) { W = Wk; O = g_wqkvT; nofs = DIM; }
            else if (which == 2) { W = Wv; O = g_wqkvT; nofs = 2 * DIM; }
            else                 { W = Wo; O = g_woT;   nofs = 0; }
        } else {
            idx -= 4 * SQ;
            K = 2 * DIM; W = Wfb; O = g_wfbT; nofs = 0;
        }
        int k = (int)(idx % K);
        int n = (int)(idx / K);
        float xv = W[(size_t)k * DIM + n];
        O[(size_t)(nofs + n) * K + k] = __float2half(xv);
        return;
    }
    blk -= WBLOCKS;
    // ---- bias concat ----
    int i = blk * 256 + tid;
    if (i < DIM) bqkv[i] = bq[i];
    else if (i < 2 * DIM) bqkv[i] = bk[i - DIM];
    else if (i < 3 * DIM) bqkv[i] = bv[i - 2 * DIM];
}

// ---------------- LN2: fp16 y + fp16 residual -> fp16 out -------------------
__global__ void ln2_kernel(const __half* __restrict__ y,
                           const __half* __restrict__ res,
                           const float* __restrict__ g,
                           const float* __restrict__ b,
                           __half* __restrict__ h_out)
{
    __shared__ float rs[8], rss[8];
    int row = blockIdx.x;
    int tid = threadIdx.x;
    uint2 uy = ((const uint2*)(y   + (size_t)row * DIM))[tid];
    uint2 ur = ((const uint2*)(res + (size_t)row * DIM))[tid];
    float2 y0 = __half22float2(*(__half2*)&uy.x);
    float2 y1 = __half22float2(*(__half2*)&uy.y);
    float2 r0 = __half22float2(*(__half2*)&ur.x);
    float2 r1 = __half22float2(*(__half2*)&ur.y);
    float4 v = make_float4(y0.x + r0.x, y0.y + r0.y, y1.x + r1.x, y1.y + r1.y);
    float s  = v.x + v.y + v.z + v.w;
    float ss = v.x*v.x + v.y*v.y + v.z*v.z + v.w*v.w;
    #pragma unroll
    for (int o = 16; o; o >>= 1) {
        s  += __shfl_xor_sync(0xffffffffu, s,  o);
        ss += __shfl_xor_sync(0xffffffffu, ss, o);
    }
    int wid = tid >> 5, lid = tid & 31;
    if (lid == 0) { rs[wid] = s; rss[wid] = ss; }
    __syncthreads();
    float tots = 0.f, totss = 0.f;
    #pragma unroll
    for (int i = 0; i < 8; i++) { tots += rs[i]; totss += rss[i]; }
    float mean = tots * (1.0f / DIM);
    float var  = totss * (1.0f / DIM) - mean * mean;
    float inv  = rsqrtf(var + 1e-6f);
    float4 gg = ((const float4*)g)[tid], bb = ((const float4*)b)[tid];
    float ox = (v.x - mean) * inv * gg.x + bb.x;
    float oy = (v.y - mean) * inv * gg.y + bb.y;
    float oz = (v.z - mean) * inv * gg.z + bb.z;
    float ow = (v.w - mean) * inv * gg.w + bb.w;
    __half* base = h_out + (size_t)row * DIM + tid * 4;
    *(__half2*)(base)     = __halves2half2(__float2half(ox), __float2half(oy));
    *(__half2*)(base + 2) = __halves2half2(__float2half(oz), __float2half(ow));
}

// ---------------- HMMA fp16 GEMM --------------------------------------------
// C = A[M,K] * B[N,K]^T + bias.  epi: 0 = fp32 out, 1 = fp32+gelu, 2 = fp16 out
// Cross-kt fragment pipelining: next kt's kh0 frags prefetched under kh3's MMAs.
#define STG_OP 16384
#define GSMEM  (3 * 2 * STG_OP)      // 98304

__device__ __forceinline__ float gelu_exact(float x) {
    return 0.5f * x * (1.0f + erff(x * 0.7071067811865475f));
}

__global__ __launch_bounds__(128, 2)
void gemm_hmma(const __half* __restrict__ A, const __half* __restrict__ B,
               const float* __restrict__ bias, void* __restrict__ Cv,
               int KK, int ldc, int epi)
{
    extern __shared__ char smem[];
    const uint32_t sb = s2u(smem);
    const int tid  = threadIdx.x;
    const int wid  = tid >> 5, lane = tid & 31;
    const int bx   = blockIdx.x, by = blockIdx.y;
    const int wm   = wid & 1;
    const int wn   = wid >> 1;
    const int NT   = KK >> 6;

    uint32_t sA[3], sB[3];
    #pragma unroll
    for (int s = 0; s < 3; s++) {
        sA[s] = sb + s * 2 * STG_OP;
        sB[s] = sA[s] + STG_OP;
    }

    const int lrow = tid >> 3;
    const uint32_t ssw = ((tid & 7) * 16) ^ ((lrow & 7) << 4);
    const __half* Ag = A + (size_t)(by * 128 + lrow) * KK + (tid & 7) * 8;
    const __half* Bg = B + (size_t)(bx * 128 + lrow) * KK + (tid & 7) * 8;

    auto load_stage = [&](int s, int kt) {
        size_t kof = (size_t)kt * 64;
        #pragma unroll
        for (int i = 0; i < 8; i++)
            cpa16(sA[s] + (lrow + i * 16) * 128 + ssw, Ag + kof + (size_t)i * 16 * KK);
        #pragma unroll
        for (int i = 0; i < 8; i++)
            cpa16(sB[s] + (lrow + i * 16) * 128 + ssw, Bg + kof + (size_t)i * 16 * KK);
    };

    float acc[4][8][4];
    #pragma unroll
    for (int i = 0; i < 4; i++)
        #pragma unroll
        for (int j = 0; j < 8; j++)
            #pragma unroll
            for (int r = 0; r < 4; r++) acc[i][j][r] = 0.f;

    load_stage(0, 0); CP_COMMIT();
    load_stage(1, 1); CP_COMMIT();

    const uint32_t maskx = (lane & 7) << 4;
    const uint32_t aRow = (wm * 64 + (lane & 15)) * 128;
    const uint32_t bRow = (wn * 64 + (lane & 7) + ((lane >> 4) & 1) * 8) * 128;
    uint32_t axo[4], bxo[4];
    {
        const uint32_t aHf = (lane >> 4) * 16;
        const uint32_t bHf = ((lane >> 3) & 1) * 16;
        #pragma unroll
        for (int kh = 0; kh < 4; kh++) {
            axo[kh] = (kh * 32 + aHf) ^ maskx;
            bxo[kh] = (kh * 32 + bHf) ^ maskx;
        }
    }

    uint32_t af[2][4][4], bf[2][8][2];

    #define LD_FRAGS(buf, sAd, sBd, kh) do {                                   \
        _Pragma("unroll")                                                      \
        for (int mt = 0; mt < 4; mt++)                                         \
            LDSM4(af[buf][mt][0], af[buf][mt][1], af[buf][mt][2],              \
                  af[buf][mt][3], (sAd) + aRow + mt * 16 * 128 + axo[kh]);     \
        _Pragma("unroll")                                                      \
        for (int np = 0; np < 4; np++)                                         \
            LDSM4(bf[buf][np*2][0], bf[buf][np*2][1], bf[buf][np*2+1][0],      \
                  bf[buf][np*2+1][1], (sBd) + bRow + np * 16 * 128 + bxo[kh]); \
    } while (0)

    #define MMA_BLOCK(buf) do {                                                \
        _Pragma("unroll")                                                      \
        for (int mt = 0; mt < 4; mt++)                                         \
            _Pragma("unroll")                                                  \
            for (int nt = 0; nt < 8; nt++)                                     \
                MMA16816(acc[mt][nt], af[buf][mt], bf[buf][nt]);               \
    } while (0)

    // steady-state entry: stage 0 ready, kh0 frags in buf0
    CP_WAIT1();
    __syncthreads();
    LD_FRAGS(0, sA[0], sB[0], 0);

    for (int kt = 0; kt < NT; kt++) {
        const int s  = kt % 3;
        const int sn = (kt + 1) % 3;
        const uint32_t sAd = sA[s], sBd = sB[s];

        LD_FRAGS(1, sAd, sBd, 1);
        MMA_BLOCK(0);
        LD_FRAGS(0, sAd, sBd, 2);
        MMA_BLOCK(1);
        LD_FRAGS(1, sAd, sBd, 3);
        MMA_BLOCK(0);

        if (kt + 1 < NT) {
            CP_WAIT1();
            __syncthreads();
            if (kt + 2 < NT) load_stage((kt + 2) % 3, kt + 2);
            CP_COMMIT();
            LD_FRAGS(0, sA[sn], sB[sn], 0);   // next kt's kh0, under kh3 MMAs
        }
        MMA_BLOCK(1);
    }

    float bv0[8], bv1[8];
    #pragma unroll
    for (int nt = 0; nt < 8; nt++) {
        int col = bx * 128 + wn * 64 + nt * 8 + (lane & 3) * 2;
        bv0[nt] = __ldg(bias + col);
        bv1[nt] = __ldg(bias + col + 1);
    }
    #pragma unroll
    for (int mt = 0; mt < 4; mt++) {
        int r0 = by * 128 + wm * 64 + mt * 16 + (lane >> 2);
        #pragma unroll
        for (int nt = 0; nt < 8; nt++) {
            int col = bx * 128 + wn * 64 + nt * 8 + (lane & 3) * 2;
            float v0 = acc[mt][nt][0] + bv0[nt], v1 = acc[mt][nt][1] + bv1[nt];
            float v2 = acc[mt][nt][2] + bv0[nt], v3 = acc[mt][nt][3] + bv1[nt];
            if (epi == 1) { v0 = gelu_exact(v0); v1 = gelu_exact(v1);
                            v2 = gelu_exact(v2); v3 = gelu_exact(v3); }
            if (epi == 2) {
                __half* Ch = (__half*)Cv;
                *(__half2*)(Ch + (size_t)r0 * ldc + col) =
                    __halves2half2(__float2half(v0), __float2half(v1));
                *(__half2*)(Ch + (size_t)(r0 + 8) * ldc + col) =
                    __halves2half2(__float2half(v2), __float2half(v3));
            } else {
                float* C = (float*)Cv;
                *(float2*)(C + (size_t)r0 * ldc + col)       = make_float2(v0, v1);
                *(float2*)(C + (size_t)(r0 + 8) * ldc + col) = make_float2(v2, v3);
            }
        }
    }
    #undef LD_FRAGS
    #undef MMA_BLOCK
}

// ---------------- windowed local attention (fp16 in, fp16 out) --------------
// warp = (row, 4 heads): 8 lanes per head, each lane owns 8 dims (uint4 = 16B).
__global__ void attn_kernel(const __half* __restrict__ qkv,
                            __half* __restrict__ out)
{
    int gw   = (blockIdx.x * blockDim.x + threadIdx.x) >> 5;
    int lane = threadIdx.x & 31;
    if (gw >= MROWS * (HEADS / 4)) return;
    int quad = gw & 3;
    int row  = gw >> 2;
    int t    = row & (TT - 1);
    int off = quad * 256 + (lane >> 3) * 64 + (lane & 7) * 8;

    auto ld8 = [&](int part, int rr) -> uint4 {
        return *(const uint4*)(qkv + (size_t)rr * (3 * DIM) + part * DIM + off);
    };
    auto dot8 = [](uint4 a, uint4 b) -> float {
        float d = 0.f;
        const __half2* ah = (const __half2*)&a;
        const __half2* bh = (const __half2*)&b;
        #pragma unroll
        for (int j = 0; j < 4; j++) {
            float2 fa = __half22float2(ah[j]);
            float2 fb = __half22float2(bh[j]);
            d += fa.x * fb.x + fa.y * fb.y;
        }
        return d;
    };
    auto wsum = [](uint4 v0, uint4 v1, uint4 v2,
                   float e0, float e1, float e2) -> uint4 {
        uint4 o;
        const __half2* p0 = (const __half2*)&v0;
        const __half2* p1 = (const __half2*)&v1;
        const __half2* p2 = (const __half2*)&v2;
        __half2* po = (__half2*)&o;
        #pragma unroll
        for (int j = 0; j < 4; j++) {
            float2 f0 = __half22float2(p0[j]);
            float2 f1 = __half22float2(p1[j]);
            float2 f2 = __half22float2(p2[j]);
            float a = e0 * f0.x + e1 * f1.x + e2 * f2.x;
            float b = e0 * f0.y + e1 * f1.y + e2 * f2.y;
            po[j] = __halves2half2(__float2half(a), __float2half(b));
        }
        return o;
    };
    const uint4 zero = make_uint4(0, 0, 0, 0);

    uint4 k0 = ld8(1, row);
    uint4 v0 = ld8(2, row);

    {   // forward
        uint4 qf = (t >= 1) ? ld8(0, row - 1) : zero;
        uint4 k1 = (t >= 1) ? ld8(1, row - 1) : zero;
        uint4 k2 = (t >= 2) ? ld8(1, row - 2) : zero;
        float d0 = dot8(qf, k0), d1 = dot8(qf, k1), d2 = dot8(qf, k2);
        #pragma unroll
        for (int o = 4; o; o >>= 1) {
            d0 += __shfl_xor_sync(0xffffffffu, d0, o);
            d1 += __shfl_xor_sync(0xffffffffu, d1, o);
            d2 += __shfl_xor_sync(0xffffffffu, d2, o);
        }
        d0 *= 0.125f; d1 *= 0.125f; d2 *= 0.125f;
        float m = fmaxf(d0, fmaxf(d1, d2));
        float e0 = expf(d0-m), e1 = expf(d1-m), e2 = expf(d2-m);
        float inv = 1.0f / (e0 + e1 + e2);
        e0 *= inv; e1 *= inv; e2 *= inv;
        uint4 v1 = (t >= 1) ? ld8(2, row - 1) : zero;
        uint4 v2 = (t >= 2) ? ld8(2, row - 2) : zero;
        *(uint4*)(out + (size_t)row * (2 * DIM) + off) = wsum(v0, v1, v2, e0, e1, e2);
    }
    {   // reverse
        uint4 qr = (t + 1 < TT) ? ld8(0, row + 1) : zero;
        uint4 k1 = (t + 1 < TT) ? ld8(1, row + 1) : zero;
        uint4 k2 = (t + 2 < TT) ? ld8(1, row + 2) : zero;
        float d0 = dot8(qr, k0), d1 = dot8(qr, k1), d2 = dot8(qr, k2);
        #pragma unroll
        for (int o = 4; o; o >>= 1) {
            d0 += __shfl_xor_sync(0xffffffffu, d0, o);
            d1 += __shfl_xor_sync(0xffffffffu, d1, o);
            d2 += __shfl_xor_sync(0xffffffffu, d2, o);
        }
        d0 *= 0.125f; d1 *= 0.125f; d2 *= 0.125f;
        float m = fmaxf(d0, fmaxf(d1, d2));
        float e0 = expf(d0-m), e1 = expf(d1-m), e2 = expf(d2-m);
        float inv = 1.0f / (e0 + e1 + e2);
        e0 *= inv; e1 *= inv; e2 *= inv;
        uint4 v1 = (t + 1 < TT) ? ld8(2, row + 1) : zero;
        uint4 v2 = (t + 2 < TT) ? ld8(2, row + 2) : zero;
        *(uint4*)(out + (size_t)row * (2 * DIM) + DIM + off) = wsum(v0, v1, v2, e0, e1, e2);
    }
}

// ---------------- launch ----------------------------------------------------
extern "C" void kernel_launch(void* const* d_in, const int* in_sizes, int n_in,
                              void* d_out, int out_size)
{
    const float* x   = (const float*)d_in[0];
    const float* Wq  = (const float*)d_in[1];
    const float* bq  = (const float*)d_in[2];
    const float* Wk  = (const float*)d_in[3];
    const float* bk  = (const float*)d_in[4];
    const float* Wv  = (const float*)d_in[5];
    const float* bv  = (const float*)d_in[6];
    const float* Wfb = (const float*)d_in[7];
    const float* bfb = (const float*)d_in[8];
    const float* Wo  = (const float*)d_in[9];
    const float* bo  = (const float*)d_in[10];
    const float* g1  = (const float*)d_in[11];
    const float* b1  = (const float*)d_in[12];
    const float* g2  = (const float*)d_in[13];
    const float* b2  = (const float*)d_in[14];
    float* out = (float*)d_out;

    void *p;
    float *bqkv;
    __half *xh, *qkv, *at, *yh, *zh, *wqkvT, *woT, *wfbT;
    cudaGetSymbolAddress(&p, g_bqkv);  bqkv  = (float*)p;
    cudaGetSymbolAddress(&p, g_xh);    xh    = (__half*)p;
    cudaGetSymbolAddress(&p, g_qkv);   qkv   = (__half*)p;
    cudaGetSymbolAddress(&p, g_at);    at    = (__half*)p;
    cudaGetSymbolAddress(&p, g_yh);    yh    = (__half*)p;
    cudaGetSymbolAddress(&p, g_zh);    zh    = (__half*)p;
    cudaGetSymbolAddress(&p, g_wqkvT); wqkvT = (__half*)p;
    cudaGetSymbolAddress(&p, g_woT);   woT   = (__half*)p;
    cudaGetSymbolAddress(&p, g_wfbT);  wfbT  = (__half*)p;

    cudaFuncSetAttribute(gemm_hmma, cudaFuncAttributeMaxDynamicSharedMemorySize, GSMEM);

    // 0+1) fused prep: LN1 + weight conversion + bias concat (one launch)
    prep_kernel<<<MROWS + WBLOCKS + BBLOCKS, 256>>>(
        x, g1, b1, xh, Wq, Wk, Wv, Wo, Wfb, bq, bk, bv, bqkv);

    // 2) fused qkv GEMM: [8192, 3072], K=1024, fp16 out
    gemm_hmma<<<dim3(24, 64), 128, GSMEM>>>(xh, wqkvT, bqkv, qkv, DIM, 3*DIM, 2);
    // 3) local attention (fp16 -> fp16), warp = 4 heads
    attn_kernel<<<(MROWS*(HEADS/4)*32)/256, 256>>>(qkv, at);
    // 4) y = at @ Wfb + bfb, K=2048, fp16 out
    gemm_hmma<<<dim3(8, 64), 128, GSMEM>>>(at, wfbT, bfb, yh, 2*DIM, DIM, 2);
    // 5) LN2(y + xh) -> fp16
    ln2_kernel<<<MROWS, 256>>>(yh, xh, g2, b2, zh);
    // 6) out = gelu(z @ Wo + bo), K=1024, fp32+gelu
    gemm_hmma<<<dim3(8, 64), 128, GSMEM>>>(zh, woT, bo, out, DIM, DIM, 1);
}

// round 13
// speedup vs baseline: 8.9169x; 1.0666x over previous
#include <cuda_runtime.h>
#include <cuda_fp16.h>
#include <math.h>
#include <stdint.h>

// Problem constants
#define BATCH 2
#define TT    4096
#define DIM   1024
#define MROWS (BATCH * TT)     // 8192
#define HEADS 16
#define HS    64

// ---------------- scratch (static device globals; no allocation) ------------
__device__ __half g_xh  [(size_t)MROWS * DIM];          // LN1 out (GEMM A + residual)
__device__ __half g_qkv [(size_t)MROWS * 3 * DIM];      // [q|k|v] fp16
__device__ __half g_at  [(size_t)MROWS * 2 * DIM];      // attn out fp16
__device__ __half g_yh  [(size_t)MROWS * DIM];          // fb out fp16
__device__ __half g_zh  [(size_t)MROWS * DIM];          // LN2 out fp16
__device__ __half g_wqkvT[(size_t)(3 * DIM) * DIM];     // 3072 x 1024 (N-major)
__device__ __half g_woT [(size_t)DIM * DIM];            // 1024 x 1024
__device__ __half g_wfbT[(size_t)DIM * 2 * DIM];        // 1024 x 2048
__device__ float g_bqkv[3 * DIM];

// ---------------- PTX helpers ----------------------------------------------
__device__ __forceinline__ uint32_t s2u(const void* p) {
    uint32_t a;
    asm("{ .reg .u64 t; cvta.to.shared.u64 t, %1; cvt.u32.u64 %0, t; }"
        : "=r"(a) : "l"(p));
    return a;
}
__device__ __forceinline__ void cpa16(uint32_t s, const void* g) {
    asm volatile("cp.async.cg.shared.global [%0], [%1], 16;" :: "r"(s), "l"(g));
}
#define CP_COMMIT() asm volatile("cp.async.commit_group;" ::: "memory")
#define CP_WAIT1()  asm volatile("cp.async.wait_group 1;" ::: "memory")

#define LDSM4(r0, r1, r2, r3, addr) \
    asm volatile("ldmatrix.sync.aligned.m8n8.x4.shared.b16 {%0,%1,%2,%3}, [%4];" \
        : "=r"(r0), "=r"(r1), "=r"(r2), "=r"(r3) : "r"(addr))

#define MMA16816(d, a, b) \
    asm volatile("mma.sync.aligned.m16n8k16.row.col.f32.f16.f16.f32 " \
        "{%0,%1,%2,%3},{%4,%5,%6,%7},{%8,%9},{%0,%1,%2,%3};" \
        : "+f"((d)[0]), "+f"((d)[1]), "+f"((d)[2]), "+f"((d)[3]) \
        : "r"((a)[0]), "r"((a)[1]), "r"((a)[2]), "r"((a)[3]), \
          "r"((b)[0]), "r"((b)[1]))

// ---------------- fused prep: LN1 + weight transpose + bias concat ----------
// weight work: 32x32 smem-tile transpose, fully coalesced both sides.
#define WTILES_SQ 1024              // per 1024x1024 matrix: 32x32 tiles
#define WTILES (4 * WTILES_SQ + 2 * WTILES_SQ)   // 6144 (Wfb is 2048x1024 -> 2048 tiles)
#define BBLOCKS 12                  // 3072 / 256

__global__ void prep_kernel(const float* __restrict__ x,
                            const float* __restrict__ g1,
                            const float* __restrict__ b1,
                            __half* __restrict__ xh,
                            const float* __restrict__ Wq,
                            const float* __restrict__ Wk,
                            const float* __restrict__ Wv,
                            const float* __restrict__ Wo,
                            const float* __restrict__ Wfb,
                            const float* __restrict__ bq,
                            const float* __restrict__ bk,
                            const float* __restrict__ bv,
                            float* __restrict__ bqkv)
{
    __shared__ float rs[8], rss[8];
    __shared__ float ts[32][33];
    int blk = blockIdx.x;
    int tid = threadIdx.x;

    if (blk < MROWS) {
        // ---- LN1 row ----
        int row = blk;
        float4 v = ((const float4*)(x + (size_t)row * DIM))[tid];
        float s  = v.x + v.y + v.z + v.w;
        float ss = v.x*v.x + v.y*v.y + v.z*v.z + v.w*v.w;
        #pragma unroll
        for (int o = 16; o; o >>= 1) {
            s  += __shfl_xor_sync(0xffffffffu, s,  o);
            ss += __shfl_xor_sync(0xffffffffu, ss, o);
        }
        int wid = tid >> 5, lid = tid & 31;
        if (lid == 0) { rs[wid] = s; rss[wid] = ss; }
        __syncthreads();
        float tots = 0.f, totss = 0.f;
        #pragma unroll
        for (int i = 0; i < 8; i++) { tots += rs[i]; totss += rss[i]; }
        float mean = tots * (1.0f / DIM);
        float var  = totss * (1.0f / DIM) - mean * mean;
        float inv  = rsqrtf(var + 1e-6f);
        float4 gg = ((const float4*)g1)[tid], bb = ((const float4*)b1)[tid];
        float ox = (v.x - mean) * inv * gg.x + bb.x;
        float oy = (v.y - mean) * inv * gg.y + bb.y;
        float oz = (v.z - mean) * inv * gg.z + bb.z;
        float ow = (v.w - mean) * inv * gg.w + bb.w;
        __half* base = xh + (size_t)row * DIM + tid * 4;
        *(__half2*)(base)     = __halves2half2(__float2half(ox), __float2half(oy));
        *(__half2*)(base + 2) = __halves2half2(__float2half(oz), __float2half(ow));
        return;
    }
    blk -= MROWS;
    if (blk < WTILES) {
        // ---- weight transpose tile: W[K,1024] fp32 -> O[N-major, K] fp16 ----
        const float* W; __half* O; int K, nofs, tile;
        if (blk < 4 * WTILES_SQ) {
            int which = blk >> 10;
            tile = blk & (WTILES_SQ - 1);
            K = DIM;
            if      (which == 0) { W = Wq; O = g_wqkvT; nofs = 0; }
            else if (which == 1) { W = Wk; O = g_wqkvT; nofs = DIM; }
            else if (which == 2) { W = Wv; O = g_wqkvT; nofs = 2 * DIM; }
            else                 { W = Wo; O = g_woT;   nofs = 0; }
        } else {
            tile = blk - 4 * WTILES_SQ;       // 0..2047
            K = 2 * DIM; W = Wfb; O = g_wfbT; nofs = 0;
        }
        // tiles laid out: 32 tiles along n per k-row-of-tiles
        int k0 = (tile >> 5) * 32;
        int n0 = (tile & 31) * 32;
        int r = tid >> 5, c = tid & 31;
        #pragma unroll
        for (int i = 0; i < 4; i++)
            ts[r + 8 * i][c] = W[(size_t)(k0 + r + 8 * i) * DIM + n0 + c];
        __syncthreads();
        #pragma unroll
        for (int i = 0; i < 4; i++) {
            int n = n0 + r + 8 * i;
            O[(size_t)(nofs + n) * K + k0 + c] = __float2half(ts[c][r + 8 * i]);
        }
        return;
    }
    blk -= WTILES;
    // ---- bias concat ----
    int i = blk * 256 + tid;
    if (i < DIM) bqkv[i] = bq[i];
    else if (i < 2 * DIM) bqkv[i] = bk[i - DIM];
    else if (i < 3 * DIM) bqkv[i] = bv[i - 2 * DIM];
}

// ---------------- LN2: fp16 y + fp16 residual -> fp16 out -------------------
__global__ void ln2_kernel(const __half* __restrict__ y,
                           const __half* __restrict__ res,
                           const float* __restrict__ g,
                           const float* __restrict__ b,
                           __half* __restrict__ h_out)
{
    __shared__ float rs[8], rss[8];
    int row = blockIdx.x;
    int tid = threadIdx.x;
    uint2 uy = ((const uint2*)(y   + (size_t)row * DIM))[tid];
    uint2 ur = ((const uint2*)(res + (size_t)row * DIM))[tid];
    float2 y0 = __half22float2(*(__half2*)&uy.x);
    float2 y1 = __half22float2(*(__half2*)&uy.y);
    float2 r0 = __half22float2(*(__half2*)&ur.x);
    float2 r1 = __half22float2(*(__half2*)&ur.y);
    float4 v = make_float4(y0.x + r0.x, y0.y + r0.y, y1.x + r1.x, y1.y + r1.y);
    float s  = v.x + v.y + v.z + v.w;
    float ss = v.x*v.x + v.y*v.y + v.z*v.z + v.w*v.w;
    #pragma unroll
    for (int o = 16; o; o >>= 1) {
        s  += __shfl_xor_sync(0xffffffffu, s,  o);
        ss += __shfl_xor_sync(0xffffffffu, ss, o);
    }
    int wid = tid >> 5, lid = tid & 31;
    if (lid == 0) { rs[wid] = s; rss[wid] = ss; }
    __syncthreads();
    float tots = 0.f, totss = 0.f;
    #pragma unroll
    for (int i = 0; i < 8; i++) { tots += rs[i]; totss += rss[i]; }
    float mean = tots * (1.0f / DIM);
    float var  = totss * (1.0f / DIM) - mean * mean;
    float inv  = rsqrtf(var + 1e-6f);
    float4 gg = ((const float4*)g)[tid], bb = ((const float4*)b)[tid];
    float ox = (v.x - mean) * inv * gg.x + bb.x;
    float oy = (v.y - mean) * inv * gg.y + bb.y;
    float oz = (v.z - mean) * inv * gg.z + bb.z;
    float ow = (v.w - mean) * inv * gg.w + bb.w;
    __half* base = h_out + (size_t)row * DIM + tid * 4;
    *(__half2*)(base)     = __halves2half2(__float2half(ox), __float2half(oy));
    *(__half2*)(base + 2) = __halves2half2(__float2half(oz), __float2half(ow));
}

// ---------------- HMMA fp16 GEMM --------------------------------------------
// C = A[M,K] * B[N,K]^T + bias.  epi: 0 = fp32 out, 1 = fp32+gelu, 2 = fp16 out
// Cross-kt fragment pipelining: next kt's kh0 frags prefetched under kh3's MMAs.
#define STG_OP 16384
#define GSMEM  (3 * 2 * STG_OP)      // 98304

__device__ __forceinline__ float gelu_exact(float x) {
    return 0.5f * x * (1.0f + erff(x * 0.7071067811865475f));
}

__global__ __launch_bounds__(128, 2)
void gemm_hmma(const __half* __restrict__ A, const __half* __restrict__ B,
               const float* __restrict__ bias, void* __restrict__ Cv,
               int KK, int ldc, int epi)
{
    extern __shared__ char smem[];
    const uint32_t sb = s2u(smem);
    const int tid  = threadIdx.x;
    const int wid  = tid >> 5, lane = tid & 31;
    const int bx   = blockIdx.x, by = blockIdx.y;
    const int wm   = wid & 1;
    const int wn   = wid >> 1;
    const int NT   = KK >> 6;

    uint32_t sA[3], sB[3];
    #pragma unroll
    for (int s = 0; s < 3; s++) {
        sA[s] = sb + s * 2 * STG_OP;
        sB[s] = sA[s] + STG_OP;
    }

    const int lrow = tid >> 3;
    const uint32_t ssw = ((tid & 7) * 16) ^ ((lrow & 7) << 4);
    const __half* Ag = A + (size_t)(by * 128 + lrow) * KK + (tid & 7) * 8;
    const __half* Bg = B + (size_t)(bx * 128 + lrow) * KK + (tid & 7) * 8;

    auto load_stage = [&](int s, int kt) {
        size_t kof = (size_t)kt * 64;
        #pragma unroll
        for (int i = 0; i < 8; i++)
            cpa16(sA[s] + (lrow + i * 16) * 128 + ssw, Ag + kof + (size_t)i * 16 * KK);
        #pragma unroll
        for (int i = 0; i < 8; i++)
            cpa16(sB[s] + (lrow + i * 16) * 128 + ssw, Bg + kof + (size_t)i * 16 * KK);
    };

    float acc[4][8][4];
    #pragma unroll
    for (int i = 0; i < 4; i++)
        #pragma unroll
        for (int j = 0; j < 8; j++)
            #pragma unroll
            for (int r = 0; r < 4; r++) acc[i][j][r] = 0.f;

    load_stage(0, 0); CP_COMMIT();
    load_stage(1, 1); CP_COMMIT();

    const uint32_t maskx = (lane & 7) << 4;
    const uint32_t aRow = (wm * 64 + (lane & 15)) * 128;
    const uint32_t bRow = (wn * 64 + (lane & 7) + ((lane >> 4) & 1) * 8) * 128;
    uint32_t axo[4], bxo[4];
    {
        const uint32_t aHf = (lane >> 4) * 16;
        const uint32_t bHf = ((lane >> 3) & 1) * 16;
        #pragma unroll
        for (int kh = 0; kh < 4; kh++) {
            axo[kh] = (kh * 32 + aHf) ^ maskx;
            bxo[kh] = (kh * 32 + bHf) ^ maskx;
        }
    }

    uint32_t af[2][4][4], bf[2][8][2];

    #define LD_FRAGS(buf, sAd, sBd, kh) do {                                   \
        _Pragma("unroll")                                                      \
        for (int mt = 0; mt < 4; mt++)                                         \
            LDSM4(af[buf][mt][0], af[buf][mt][1], af[buf][mt][2],              \
                  af[buf][mt][3], (sAd) + aRow + mt * 16 * 128 + axo[kh]);     \
        _Pragma("unroll")                                                      \
        for (int np = 0; np < 4; np++)                                         \
            LDSM4(bf[buf][np*2][0], bf[buf][np*2][1], bf[buf][np*2+1][0],      \
                  bf[buf][np*2+1][1], (sBd) + bRow + np * 16 * 128 + bxo[kh]); \
    } while (0)

    #define MMA_BLOCK(buf) do {                                                \
        _Pragma("unroll")                                                      \
        for (int mt = 0; mt < 4; mt++)                                         \
            _Pragma("unroll")                                                  \
            for (int nt = 0; nt < 8; nt++)                                     \
                MMA16816(acc[mt][nt], af[buf][mt], bf[buf][nt]);               \
    } while (0)

    CP_WAIT1();
    __syncthreads();
    LD_FRAGS(0, sA[0], sB[0], 0);

    for (int kt = 0; kt < NT; kt++) {
        const int s  = kt % 3;
        const int sn = (kt + 1) % 3;
        const uint32_t sAd = sA[s], sBd = sB[s];

        LD_FRAGS(1, sAd, sBd, 1);
        MMA_BLOCK(0);
        LD_FRAGS(0, sAd, sBd, 2);
        MMA_BLOCK(1);
        LD_FRAGS(1, sAd, sBd, 3);
        MMA_BLOCK(0);

        if (kt + 1 < NT) {
            CP_WAIT1();
            __syncthreads();
            if (kt + 2 < NT) load_stage((kt + 2) % 3, kt + 2);
            CP_COMMIT();
            LD_FRAGS(0, sA[sn], sB[sn], 0);
        }
        MMA_BLOCK(1);
    }

    float bv0[8], bv1[8];
    #pragma unroll
    for (int nt = 0; nt < 8; nt++) {
        int col = bx * 128 + wn * 64 + nt * 8 + (lane & 3) * 2;
        bv0[nt] = __ldg(bias + col);
        bv1[nt] = __ldg(bias + col + 1);
    }
    #pragma unroll
    for (int mt = 0; mt < 4; mt++) {
        int r0 = by * 128 + wm * 64 + mt * 16 + (lane >> 2);
        #pragma unroll
        for (int nt = 0; nt < 8; nt++) {
            int col = bx * 128 + wn * 64 + nt * 8 + (lane & 3) * 2;
            float v0 = acc[mt][nt][0] + bv0[nt], v1 = acc[mt][nt][1] + bv1[nt];
            float v2 = acc[mt][nt][2] + bv0[nt], v3 = acc[mt][nt][3] + bv1[nt];
            if (epi == 1) { v0 = gelu_exact(v0); v1 = gelu_exact(v1);
                            v2 = gelu_exact(v2); v3 = gelu_exact(v3); }
            if (epi == 2) {
                __half* Ch = (__half*)Cv;
                *(__half2*)(Ch + (size_t)r0 * ldc + col) =
                    __halves2half2(__float2half(v0), __float2half(v1));
                *(__half2*)(Ch + (size_t)(r0 + 8) * ldc + col) =
                    __halves2half2(__float2half(v2), __float2half(v3));
            } else {
                float* C = (float*)Cv;
                *(float2*)(C + (size_t)r0 * ldc + col)       = make_float2(v0, v1);
                *(float2*)(C + (size_t)(r0 + 8) * ldc + col) = make_float2(v2, v3);
            }
        }
    }
    #undef LD_FRAGS
    #undef MMA_BLOCK
}

// ---------------- windowed local attention (fp16 in, fp16 out) --------------
__global__ void attn_kernel(const __half* __restrict__ qkv,
                            __half* __restrict__ out)
{
    int gw   = (blockIdx.x * blockDim.x + threadIdx.x) >> 5;
    int lane = threadIdx.x & 31;
    if (gw >= MROWS * (HEADS / 4)) return;
    int quad = gw & 3;
    int row  = gw >> 2;
    int t    = row & (TT - 1);
    int off = quad * 256 + (lane >> 3) * 64 + (lane & 7) * 8;

    auto ld8 = [&](int part, int rr) -> uint4 {
        return *(const uint4*)(qkv + (size_t)rr * (3 * DIM) + part * DIM + off);
    };
    auto dot8 = [](uint4 a, uint4 b) -> float {
        float d = 0.f;
        const __half2* ah = (const __half2*)&a;
        const __half2* bh = (const __half2*)&b;
        #pragma unroll
        for (int j = 0; j < 4; j++) {
            float2 fa = __half22float2(ah[j]);
            float2 fb = __half22float2(bh[j]);
            d += fa.x * fb.x + fa.y * fb.y;
        }
        return d;
    };
    auto wsum = [](uint4 v0, uint4 v1, uint4 v2,
                   float e0, float e1, float e2) -> uint4 {
        uint4 o;
        const __half2* p0 = (const __half2*)&v0;
        const __half2* p1 = (const __half2*)&v1;
        const __half2* p2 = (const __half2*)&v2;
        __half2* po = (__half2*)&o;
        #pragma unroll
        for (int j = 0; j < 4; j++) {
            float2 f0 = __half22float2(p0[j]);
            float2 f1 = __half22float2(p1[j]);
            float2 f2 = __half22float2(p2[j]);
            float a = e0 * f0.x + e1 * f1.x + e2 * f2.x;
            float b = e0 * f0.y + e1 * f1.y + e2 * f2.y;
            po[j] = __halves2half2(__float2half(a), __float2half(b));
        }
        return o;
    };
    const uint4 zero = make_uint4(0, 0, 0, 0);

    uint4 k0 = ld8(1, row);
    uint4 v0 = ld8(2, row);

    {   // forward
        uint4 qf = (t >= 1) ? ld8(0, row - 1) : zero;
        uint4 k1 = (t >= 1) ? ld8(1, row - 1) : zero;
        uint4 k2 = (t >= 2) ? ld8(1, row - 2) : zero;
        float d0 = dot8(qf, k0), d1 = dot8(qf, k1), d2 = dot8(qf, k2);
        #pragma unroll
        for (int o = 4; o; o >>= 1) {
            d0 += __shfl_xor_sync(0xffffffffu, d0, o);
            d1 += __shfl_xor_sync(0xffffffffu, d1, o);
            d2 += __shfl_xor_sync(0xffffffffu, d2, o);
        }
        d0 *= 0.125f; d1 *= 0.125f; d2 *= 0.125f;
        float m = fmaxf(d0, fmaxf(d1, d2));
        float e0 = expf(d0-m), e1 = expf(d1-m), e2 = expf(d2-m);
        float inv = 1.0f / (e0 + e1 + e2);
        e0 *= inv; e1 *= inv; e2 *= inv;
        uint4 v1 = (t >= 1) ? ld8(2, row - 1) : zero;
        uint4 v2 = (t >= 2) ? ld8(2, row - 2) : zero;
        *(uint4*)(out + (size_t)row * (2 * DIM) + off) = wsum(v0, v1, v2, e0, e1, e2);
    }
    {   // reverse
        uint4 qr = (t + 1 < TT) ? ld8(0, row + 1) : zero;
        uint4 k1 = (t + 1 < TT) ? ld8(1, row + 1) : zero;
        uint4 k2 = (t + 2 < TT) ? ld8(1, row + 2) : zero;
        float d0 = dot8(qr, k0), d1 = dot8(qr, k1), d2 = dot8(qr, k2);
        #pragma unroll
        for (int o = 4; o; o >>= 1) {
            d0 += __shfl_xor_sync(0xffffffffu, d0, o);
            d1 += __shfl_xor_sync(0xffffffffu, d1, o);
            d2 += __shfl_xor_sync(0xffffffffu, d2, o);
        }
        d0 *= 0.125f; d1 *= 0.125f; d2 *= 0.125f;
        float m = fmaxf(d0, fmaxf(d1, d2));
        float e0 = expf(d0-m), e1 = expf(d1-m), e2 = expf(d2-m);
        float inv = 1.0f / (e0 + e1 + e2);
        e0 *= inv; e1 *= inv; e2 *= inv;
        uint4 v1 = (t + 1 < TT) ? ld8(2, row + 1) : zero;
        uint4 v2 = (t + 2 < TT) ? ld8(2, row + 2) : zero;
        *(uint4*)(out + (size_t)row * (2 * DIM) + DIM + off) = wsum(v0, v1, v2, e0, e1, e2);
    }
}

// ---------------- launch ----------------------------------------------------
extern "C" void kernel_launch(void* const* d_in, const int* in_sizes, int n_in,
                              void* d_out, int out_size)
{
    const float* x   = (const float*)d_in[0];
    const float* Wq  = (const float*)d_in[1];
    const float* bq  = (const float*)d_in[2];
    const float* Wk  = (const float*)d_in[3];
    const float* bk  = (const float*)d_in[4];
    const float* Wv  = (const float*)d_in[5];
    const float* bv  = (const float*)d_in[6];
    const float* Wfb = (const float*)d_in[7];
    const float* bfb = (const float*)d_in[8];
    const float* Wo  = (const float*)d_in[9];
    const float* bo  = (const float*)d_in[10];
    const float* g1  = (const float*)d_in[11];
    const float* b1  = (const float*)d_in[12];
    const float* g2  = (const float*)d_in[13];
    const float* b2  = (const float*)d_in[14];
    float* out = (float*)d_out;

    void *p;
    float *bqkv;
    __half *xh, *qkv, *at, *yh, *zh, *wqkvT, *woT, *wfbT;
    cudaGetSymbolAddress(&p, g_bqkv);  bqkv  = (float*)p;
    cudaGetSymbolAddress(&p, g_xh);    xh    = (__half*)p;
    cudaGetSymbolAddress(&p, g_qkv);   qkv   = (__half*)p;
    cudaGetSymbolAddress(&p, g_at);    at    = (__half*)p;
    cudaGetSymbolAddress(&p, g_yh);    yh    = (__half*)p;
    cudaGetSymbolAddress(&p, g_zh);    zh    = (__half*)p;
    cudaGetSymbolAddress(&p, g_wqkvT); wqkvT = (__half*)p;
    cudaGetSymbolAddress(&p, g_woT);   woT   = (__half*)p;
    cudaGetSymbolAddress(&p, g_wfbT);  wfbT  = (__half*)p;

    cudaFuncSetAttribute(gemm_hmma, cudaFuncAttributeMaxDynamicSharedMemorySize, GSMEM);

    // 0+1) fused prep: LN1 + coalesced weight transpose + bias concat
    prep_kernel<<<MROWS + WTILES + BBLOCKS, 256>>>(
        x, g1, b1, xh, Wq, Wk, Wv, Wo, Wfb, bq, bk, bv, bqkv);

    // 2) fused qkv GEMM: [8192, 3072], K=1024, fp16 out
    gemm_hmma<<<dim3(24, 64), 128, GSMEM>>>(xh, wqkvT, bqkv, qkv, DIM, 3*DIM, 2);
    // 3) local attention (fp16 -> fp16), warp = 4 heads
    attn_kernel<<<(MROWS*(HEADS/4)*32)/256, 256>>>(qkv, at);
    // 4) y = at @ Wfb + bfb, K=2048, fp16 out
    gemm_hmma<<<dim3(8, 64), 128, GSMEM>>>(at, wfbT, bfb, yh, 2*DIM, DIM, 2);
    // 5) LN2(y + xh) -> fp16
    ln2_kernel<<<MROWS, 256>>>(yh, xh, g2, b2, zh);
    // 6) out = gelu(z @ Wo + bo), K=1024, fp32+gelu
    gemm_hmma<<<dim3(8, 64), 128, GSMEM>>>(zh, woT, bo, out, DIM, DIM, 1);
}

// round 14
// speedup vs baseline: 9.0140x; 1.0109x over previous
#include <cuda_runtime.h>
#include <cuda_fp16.h>
#include <math.h>
#include <stdint.h>

// Problem constants
#define BATCH 2
#define TT    4096
#define DIM   1024
#define MROWS (BATCH * TT)     // 8192
#define HEADS 16
#define HS    64

// ---------------- scratch (static device globals; no allocation) ------------
__device__ __half g_xh  [(size_t)MROWS * DIM];          // LN1 out (GEMM A + residual)
__device__ __half g_qkv [(size_t)MROWS * 3 * DIM];      // [q|k|v] fp16
__device__ __half g_at  [(size_t)MROWS * 2 * DIM];      // attn out fp16
__device__ __half g_yh  [(size_t)MROWS * DIM];          // fb out fp16
__device__ __half g_zh  [(size_t)MROWS * DIM];          // LN2 out fp16
__device__ __half g_wqkvT[(size_t)(3 * DIM) * DIM];     // 3072 x 1024 (N-major)
__device__ __half g_woT [(size_t)DIM * DIM];            // 1024 x 1024
__device__ __half g_wfbT[(size_t)DIM * 2 * DIM];        // 1024 x 2048
__device__ float g_bqkv[3 * DIM];

// ---------------- PTX helpers ----------------------------------------------
__device__ __forceinline__ uint32_t s2u(const void* p) {
    uint32_t a;
    asm("{ .reg .u64 t; cvta.to.shared.u64 t, %1; cvt.u32.u64 %0, t; }"
        : "=r"(a) : "l"(p));
    return a;
}
__device__ __forceinline__ void cpa16(uint32_t s, const void* g) {
    asm volatile("cp.async.cg.shared.global [%0], [%1], 16;" :: "r"(s), "l"(g));
}
#define CP_COMMIT() asm volatile("cp.async.commit_group;" ::: "memory")
#define CP_WAIT1()  asm volatile("cp.async.wait_group 1;" ::: "memory")

#define LDSM4(r0, r1, r2, r3, addr) \
    asm volatile("ldmatrix.sync.aligned.m8n8.x4.shared.b16 {%0,%1,%2,%3}, [%4];" \
        : "=r"(r0), "=r"(r1), "=r"(r2), "=r"(r3) : "r"(addr))

#define MMA16816(d, a, b) \
    asm volatile("mma.sync.aligned.m16n8k16.row.col.f32.f16.f16.f32 " \
        "{%0,%1,%2,%3},{%4,%5,%6,%7},{%8,%9},{%0,%1,%2,%3};" \
        : "+f"((d)[0]), "+f"((d)[1]), "+f"((d)[2]), "+f"((d)[3]) \
        : "r"((a)[0]), "r"((a)[1]), "r"((a)[2]), "r"((a)[3]), \
          "r"((b)[0]), "r"((b)[1]))

// ---------------- prep: LN1 + wqkv transpose + bias concat ------------------
#define WQKV_TILES 3072             // Wq, Wk, Wv: 3 x 1024 32x32 tiles
#define BBLOCKS 12                  // 3072 / 256

__global__ void prep_kernel(const float* __restrict__ x,
                            const float* __restrict__ g1,
                            const float* __restrict__ b1,
                            __half* __restrict__ xh,
                            const float* __restrict__ Wq,
                            const float* __restrict__ Wk,
                            const float* __restrict__ Wv,
                            const float* __restrict__ bq,
                            const float* __restrict__ bk,
                            const float* __restrict__ bv,
                            float* __restrict__ bqkv)
{
    __shared__ float rs[8], rss[8];
    __shared__ float ts[32][33];
    int blk = blockIdx.x;
    int tid = threadIdx.x;

    if (blk < MROWS) {
        // ---- LN1 row ----
        int row = blk;
        float4 v = ((const float4*)(x + (size_t)row * DIM))[tid];
        float s  = v.x + v.y + v.z + v.w;
        float ss = v.x*v.x + v.y*v.y + v.z*v.z + v.w*v.w;
        #pragma unroll
        for (int o = 16; o; o >>= 1) {
            s  += __shfl_xor_sync(0xffffffffu, s,  o);
            ss += __shfl_xor_sync(0xffffffffu, ss, o);
        }
        int wid = tid >> 5, lid = tid & 31;
        if (lid == 0) { rs[wid] = s; rss[wid] = ss; }
        __syncthreads();
        float tots = 0.f, totss = 0.f;
        #pragma unroll
        for (int i = 0; i < 8; i++) { tots += rs[i]; totss += rss[i]; }
        float mean = tots * (1.0f / DIM);
        float var  = totss * (1.0f / DIM) - mean * mean;
        float inv  = rsqrtf(var + 1e-6f);
        float4 gg = ((const float4*)g1)[tid], bb = ((const float4*)b1)[tid];
        float ox = (v.x - mean) * inv * gg.x + bb.x;
        float oy = (v.y - mean) * inv * gg.y + bb.y;
        float oz = (v.z - mean) * inv * gg.z + bb.z;
        float ow = (v.w - mean) * inv * gg.w + bb.w;
        __half* base = xh + (size_t)row * DIM + tid * 4;
        *(__half2*)(base)     = __halves2half2(__float2half(ox), __float2half(oy));
        *(__half2*)(base + 2) = __halves2half2(__float2half(oz), __float2half(ow));
        return;
    }
    blk -= MROWS;
    if (blk < WQKV_TILES) {
        // ---- wqkv transpose tile ----
        int which = blk >> 10;
        int tile  = blk & 1023;
        const float* W = (which == 0) ? Wq : (which == 1) ? Wk : Wv;
        int nofs = which * DIM;
        int k0 = (tile >> 5) * 32;
        int n0 = (tile & 31) * 32;
        int r = tid >> 5, c = tid & 31;
        #pragma unroll
        for (int i = 0; i < 4; i++)
            ts[r + 8 * i][c] = W[(size_t)(k0 + r + 8 * i) * DIM + n0 + c];
        __syncthreads();
        #pragma unroll
        for (int i = 0; i < 4; i++) {
            int n = n0 + r + 8 * i;
            g_wqkvT[(size_t)(nofs + n) * DIM + k0 + c] = __float2half(ts[c][r + 8 * i]);
        }
        return;
    }
    blk -= WQKV_TILES;
    // ---- bias concat ----
    int i = blk * 256 + tid;
    if (i < DIM) bqkv[i] = bq[i];
    else if (i < 2 * DIM) bqkv[i] = bk[i - DIM];
    else if (i < 3 * DIM) bqkv[i] = bv[i - 2 * DIM];
}

// ---------------- LN2: fp16 y + fp16 residual -> fp16 out -------------------
__global__ void ln2_kernel(const __half* __restrict__ y,
                           const __half* __restrict__ res,
                           const float* __restrict__ g,
                           const float* __restrict__ b,
                           __half* __restrict__ h_out)
{
    __shared__ float rs[8], rss[8];
    int row = blockIdx.x;
    int tid = threadIdx.x;
    uint2 uy = ((const uint2*)(y   + (size_t)row * DIM))[tid];
    uint2 ur = ((const uint2*)(res + (size_t)row * DIM))[tid];
    float2 y0 = __half22float2(*(__half2*)&uy.x);
    float2 y1 = __half22float2(*(__half2*)&uy.y);
    float2 r0 = __half22float2(*(__half2*)&ur.x);
    float2 r1 = __half22float2(*(__half2*)&ur.y);
    float4 v = make_float4(y0.x + r0.x, y0.y + r0.y, y1.x + r1.x, y1.y + r1.y);
    float s  = v.x + v.y + v.z + v.w;
    float ss = v.x*v.x + v.y*v.y + v.z*v.z + v.w*v.w;
    #pragma unroll
    for (int o = 16; o; o >>= 1) {
        s  += __shfl_xor_sync(0xffffffffu, s,  o);
        ss += __shfl_xor_sync(0xffffffffu, ss, o);
    }
    int wid = tid >> 5, lid = tid & 31;
    if (lid == 0) { rs[wid] = s; rss[wid] = ss; }
    __syncthreads();
    float tots = 0.f, totss = 0.f;
    #pragma unroll
    for (int i = 0; i < 8; i++) { tots += rs[i]; totss += rss[i]; }
    float mean = tots * (1.0f / DIM);
    float var  = totss * (1.0f / DIM) - mean * mean;
    float inv  = rsqrtf(var + 1e-6f);
    float4 gg = ((const float4*)g)[tid], bb = ((const float4*)b)[tid];
    float ox = (v.x - mean) * inv * gg.x + bb.x;
    float oy = (v.y - mean) * inv * gg.y + bb.y;
    float oz = (v.z - mean) * inv * gg.z + bb.z;
    float ow = (v.w - mean) * inv * gg.w + bb.w;
    __half* base = h_out + (size_t)row * DIM + tid * 4;
    *(__half2*)(base)     = __halves2half2(__float2half(ox), __float2half(oy));
    *(__half2*)(base + 2) = __halves2half2(__float2half(oz), __float2half(ow));
}

// ---------------- HMMA fp16 GEMM (+ optional tail aux transposes) -----------
// C = A[M,K] * B[N,K]^T + bias.  epi: 0 = fp32 out, 1 = fp32+gelu, 2 = fp16 out
// 1D grid: blocks [0, ntiles) are GEMM tiles (bx = bid % nx, by = bid / nx);
// blocks >= ntiles (qkv launch only) transpose Wo/Wfb for the later GEMMs,
// filling the tail wave's idle slots with memory work.
#define STG_OP 16384
#define GSMEM  (3 * 2 * STG_OP)      // 98304
#define AUX_WO   1024
#define AUX_WFB  2048
#define AUX_TOT  (AUX_WO + AUX_WFB)  // 3072

__device__ __forceinline__ float gelu_exact(float x) {
    return 0.5f * x * (1.0f + erff(x * 0.7071067811865475f));
}

__global__ __launch_bounds__(128, 2)
void gemm_hmma(const __half* __restrict__ A, const __half* __restrict__ B,
               const float* __restrict__ bias, void* __restrict__ Cv,
               int KK, int ldc, int epi, int ntiles, int nx,
               const float* __restrict__ WoSrc, const float* __restrict__ WfbSrc)
{
    extern __shared__ char smem[];
    const int bid = blockIdx.x;
    const int tid = threadIdx.x;

    if (bid >= ntiles) {
        // ---- aux: coalesced 32x32 transpose (128 threads, 8 rows/pass) ----
        float (*ts)[33] = (float(*)[33])smem;
        int blk = bid - ntiles;
        const float* W; __half* O; int K, tile;
        if (blk < AUX_WO) { W = WoSrc; O = g_woT; K = DIM; tile = blk; }
        else { W = WfbSrc; O = g_wfbT; K = 2 * DIM; tile = blk - AUX_WO; }
        int k0 = (tile >> 5) * 32;
        int n0 = (tile & 31) * 32;
        int r = tid >> 5, c = tid & 31;     // 4 rows per pass, 8 passes
        #pragma unroll
        for (int i = 0; i < 8; i++)
            ts[r + 4 * i][c] = W[(size_t)(k0 + r + 4 * i) * DIM + n0 + c];
        __syncthreads();
        #pragma unroll
        for (int i = 0; i < 8; i++) {
            int n = n0 + r + 4 * i;
            O[(size_t)n * K + k0 + c] = __float2half(ts[c][r + 4 * i]);
        }
        return;
    }

    const uint32_t sb = s2u(smem);
    const int wid  = tid >> 5, lane = tid & 31;
    const int bx   = bid % nx, by = bid / nx;
    const int wm   = wid & 1;
    const int wn   = wid >> 1;
    const int NT   = KK >> 6;

    uint32_t sA[3], sB[3];
    #pragma unroll
    for (int s = 0; s < 3; s++) {
        sA[s] = sb + s * 2 * STG_OP;
        sB[s] = sA[s] + STG_OP;
    }

    const int lrow = tid >> 3;
    const uint32_t ssw = ((tid & 7) * 16) ^ ((lrow & 7) << 4);
    const __half* Ag = A + (size_t)(by * 128 + lrow) * KK + (tid & 7) * 8;
    const __half* Bg = B + (size_t)(bx * 128 + lrow) * KK + (tid & 7) * 8;

    auto load_stage = [&](int s, int kt) {
        size_t kof = (size_t)kt * 64;
        #pragma unroll
        for (int i = 0; i < 8; i++)
            cpa16(sA[s] + (lrow + i * 16) * 128 + ssw, Ag + kof + (size_t)i * 16 * KK);
        #pragma unroll
        for (int i = 0; i < 8; i++)
            cpa16(sB[s] + (lrow + i * 16) * 128 + ssw, Bg + kof + (size_t)i * 16 * KK);
    };

    float acc[4][8][4];
    #pragma unroll
    for (int i = 0; i < 4; i++)
        #pragma unroll
        for (int j = 0; j < 8; j++)
            #pragma unroll
            for (int r = 0; r < 4; r++) acc[i][j][r] = 0.f;

    load_stage(0, 0); CP_COMMIT();
    load_stage(1, 1); CP_COMMIT();

    const uint32_t maskx = (lane & 7) << 4;
    const uint32_t aRow = (wm * 64 + (lane & 15)) * 128;
    const uint32_t bRow = (wn * 64 + (lane & 7) + ((lane >> 4) & 1) * 8) * 128;
    uint32_t axo[4], bxo[4];
    {
        const uint32_t aHf = (lane >> 4) * 16;
        const uint32_t bHf = ((lane >> 3) & 1) * 16;
        #pragma unroll
        for (int kh = 0; kh < 4; kh++) {
            axo[kh] = (kh * 32 + aHf) ^ maskx;
            bxo[kh] = (kh * 32 + bHf) ^ maskx;
        }
    }

    uint32_t af[2][4][4], bf[2][8][2];

    #define LD_FRAGS(buf, sAd, sBd, kh) do {                                   \
        _Pragma("unroll")                                                      \
        for (int mt = 0; mt < 4; mt++)                                         \
            LDSM4(af[buf][mt][0], af[buf][mt][1], af[buf][mt][2],              \
                  af[buf][mt][3], (sAd) + aRow + mt * 16 * 128 + axo[kh]);     \
        _Pragma("unroll")                                                      \
        for (int np = 0; np < 4; np++)                                         \
            LDSM4(bf[buf][np*2][0], bf[buf][np*2][1], bf[buf][np*2+1][0],      \
                  bf[buf][np*2+1][1], (sBd) + bRow + np * 16 * 128 + bxo[kh]); \
    } while (0)

    #define MMA_BLOCK(buf) do {                                                \
        _Pragma("unroll")                                                      \
        for (int mt = 0; mt < 4; mt++)                                         \
            _Pragma("unroll")                                                  \
            for (int nt = 0; nt < 8; nt++)                                     \
                MMA16816(acc[mt][nt], af[buf][mt], bf[buf][nt]);               \
    } while (0)

    CP_WAIT1();
    __syncthreads();
    LD_FRAGS(0, sA[0], sB[0], 0);

    for (int kt = 0; kt < NT; kt++) {
        const int s  = kt % 3;
        const int sn = (kt + 1) % 3;
        const uint32_t sAd = sA[s], sBd = sB[s];

        LD_FRAGS(1, sAd, sBd, 1);
        MMA_BLOCK(0);
        LD_FRAGS(0, sAd, sBd, 2);
        MMA_BLOCK(1);
        LD_FRAGS(1, sAd, sBd, 3);
        MMA_BLOCK(0);

        if (kt + 1 < NT) {
            CP_WAIT1();
            __syncthreads();
            if (kt + 2 < NT) load_stage((kt + 2) % 3, kt + 2);
            CP_COMMIT();
            LD_FRAGS(0, sA[sn], sB[sn], 0);
        }
        MMA_BLOCK(1);
    }

    float bv0[8], bv1[8];
    #pragma unroll
    for (int nt = 0; nt < 8; nt++) {
        int col = bx * 128 + wn * 64 + nt * 8 + (lane & 3) * 2;
        bv0[nt] = __ldg(bias + col);
        bv1[nt] = __ldg(bias + col + 1);
    }
    #pragma unroll
    for (int mt = 0; mt < 4; mt++) {
        int r0 = by * 128 + wm * 64 + mt * 16 + (lane >> 2);
        #pragma unroll
        for (int nt = 0; nt < 8; nt++) {
            int col = bx * 128 + wn * 64 + nt * 8 + (lane & 3) * 2;
            float v0 = acc[mt][nt][0] + bv0[nt], v1 = acc[mt][nt][1] + bv1[nt];
            float v2 = acc[mt][nt][2] + bv0[nt], v3 = acc[mt][nt][3] + bv1[nt];
            if (epi == 1) { v0 = gelu_exact(v0); v1 = gelu_exact(v1);
                            v2 = gelu_exact(v2); v3 = gelu_exact(v3); }
            if (epi == 2) {
                __half* Ch = (__half*)Cv;
                *(__half2*)(Ch + (size_t)r0 * ldc + col) =
                    __halves2half2(__float2half(v0), __float2half(v1));
                *(__half2*)(Ch + (size_t)(r0 + 8) * ldc + col) =
                    __halves2half2(__float2half(v2), __float2half(v3));
            } else {
                float* C = (float*)Cv;
                *(float2*)(C + (size_t)r0 * ldc + col)       = make_float2(v0, v1);
                *(float2*)(C + (size_t)(r0 + 8) * ldc + col) = make_float2(v2, v3);
            }
        }
    }
    #undef LD_FRAGS
    #undef MMA_BLOCK
}

// ---------------- windowed local attention (fp16 in, fp16 out) --------------
__global__ void attn_kernel(const __half* __restrict__ qkv,
                            __half* __restrict__ out)
{
    int gw   = (blockIdx.x * blockDim.x + threadIdx.x) >> 5;
    int lane = threadIdx.x & 31;
    if (gw >= MROWS * (HEADS / 4)) return;
    int quad = gw & 3;
    int row  = gw >> 2;
    int t    = row & (TT - 1);
    int off = quad * 256 + (lane >> 3) * 64 + (lane & 7) * 8;

    auto ld8 = [&](int part, int rr) -> uint4 {
        return *(const uint4*)(qkv + (size_t)rr * (3 * DIM) + part * DIM + off);
    };
    auto dot8 = [](uint4 a, uint4 b) -> float {
        float d = 0.f;
        const __half2* ah = (const __half2*)&a;
        const __half2* bh = (const __half2*)&b;
        #pragma unroll
        for (int j = 0; j < 4; j++) {
            float2 fa = __half22float2(ah[j]);
            float2 fb = __half22float2(bh[j]);
            d += fa.x * fb.x + fa.y * fb.y;
        }
        return d;
    };
    auto wsum = [](uint4 v0, uint4 v1, uint4 v2,
                   float e0, float e1, float e2) -> uint4 {
        uint4 o;
        const __half2* p0 = (const __half2*)&v0;
        const __half2* p1 = (const __half2*)&v1;
        const __half2* p2 = (const __half2*)&v2;
        __half2* po = (__half2*)&o;
        #pragma unroll
        for (int j = 0; j < 4; j++) {
            float2 f0 = __half22float2(p0[j]);
            float2 f1 = __half22float2(p1[j]);
            float2 f2 = __half22float2(p2[j]);
            float a = e0 * f0.x + e1 * f1.x + e2 * f2.x;
            float b = e0 * f0.y + e1 * f1.y + e2 * f2.y;
            po[j] = __halves2half2(__float2half(a), __float2half(b));
        }
        return o;
    };
    const uint4 zero = make_uint4(0, 0, 0, 0);

    uint4 k0 = ld8(1, row);
    uint4 v0 = ld8(2, row);

    {   // forward
        uint4 qf = (t >= 1) ? ld8(0, row - 1) : zero;
        uint4 k1 = (t >= 1) ? ld8(1, row - 1) : zero;
        uint4 k2 = (t >= 2) ? ld8(1, row - 2) : zero;
        float d0 = dot8(qf, k0), d1 = dot8(qf, k1), d2 = dot8(qf, k2);
        #pragma unroll
        for (int o = 4; o; o >>= 1) {
            d0 += __shfl_xor_sync(0xffffffffu, d0, o);
            d1 += __shfl_xor_sync(0xffffffffu, d1, o);
            d2 += __shfl_xor_sync(0xffffffffu, d2, o);
        }
        d0 *= 0.125f; d1 *= 0.125f; d2 *= 0.125f;
        float m = fmaxf(d0, fmaxf(d1, d2));
        float e0 = expf(d0-m), e1 = expf(d1-m), e2 = expf(d2-m);
        float inv = 1.0f / (e0 + e1 + e2);
        e0 *= inv; e1 *= inv; e2 *= inv;
        uint4 v1 = (t >= 1) ? ld8(2, row - 1) : zero;
        uint4 v2 = (t >= 2) ? ld8(2, row - 2) : zero;
        *(uint4*)(out + (size_t)row * (2 * DIM) + off) = wsum(v0, v1, v2, e0, e1, e2);
    }
    {   // reverse
        uint4 qr = (t + 1 < TT) ? ld8(0, row + 1) : zero;
        uint4 k1 = (t + 1 < TT) ? ld8(1, row + 1) : zero;
        uint4 k2 = (t + 2 < TT) ? ld8(1, row + 2) : zero;
        float d0 = dot8(qr, k0), d1 = dot8(qr, k1), d2 = dot8(qr, k2);
        #pragma unroll
        for (int o = 4; o; o >>= 1) {
            d0 += __shfl_xor_sync(0xffffffffu, d0, o);
            d1 += __shfl_xor_sync(0xffffffffu, d1, o);
            d2 += __shfl_xor_sync(0xffffffffu, d2, o);
        }
        d0 *= 0.125f; d1 *= 0.125f; d2 *= 0.125f;
        float m = fmaxf(d0, fmaxf(d1, d2));
        float e0 = expf(d0-m), e1 = expf(d1-m), e2 = expf(d2-m);
        float inv = 1.0f / (e0 + e1 + e2);
        e0 *= inv; e1 *= inv; e2 *= inv;
        uint4 v1 = (t + 1 < TT) ? ld8(2, row + 1) : zero;
        uint4 v2 = (t + 2 < TT) ? ld8(2, row + 2) : zero;
        *(uint4*)(out + (size_t)row * (2 * DIM) + DIM + off) = wsum(v0, v1, v2, e0, e1, e2);
    }
}

// ---------------- launch ----------------------------------------------------
extern "C" void kernel_launch(void* const* d_in, const int* in_sizes, int n_in,
                              void* d_out, int out_size)
{
    const float* x   = (const float*)d_in[0];
    const float* Wq  = (const float*)d_in[1];
    const float* bq  = (const float*)d_in[2];
    const float* Wk  = (const float*)d_in[3];
    const float* bk  = (const float*)d_in[4];
    const float* Wv  = (const float*)d_in[5];
    const float* bv  = (const float*)d_in[6];
    const float* Wfb = (const float*)d_in[7];
    const float* bfb = (const float*)d_in[8];
    const float* Wo  = (const float*)d_in[9];
    const float* bo  = (const float*)d_in[10];
    const float* g1  = (const float*)d_in[11];
    const float* b1  = (const float*)d_in[12];
    const float* g2  = (const float*)d_in[13];
    const float* b2  = (const float*)d_in[14];
    float* out = (float*)d_out;

    void *p;
    float *bqkv;
    __half *xh, *qkv, *at, *yh, *zh, *wqkvT, *woT, *wfbT;
    cudaGetSymbolAddress(&p, g_bqkv);  bqkv  = (float*)p;
    cudaGetSymbolAddress(&p, g_xh);    xh    = (__half*)p;
    cudaGetSymbolAddress(&p, g_qkv);   qkv   = (__half*)p;
    cudaGetSymbolAddress(&p, g_at);    at    = (__half*)p;
    cudaGetSymbolAddress(&p, g_yh);    yh    = (__half*)p;
    cudaGetSymbolAddress(&p, g_zh);    zh    = (__half*)p;
    cudaGetSymbolAddress(&p, g_wqkvT); wqkvT = (__half*)p;
    cudaGetSymbolAddress(&p, g_woT);   woT   = (__half*)p;
    cudaGetSymbolAddress(&p, g_wfbT);  wfbT  = (__half*)p;

    cudaFuncSetAttribute(gemm_hmma, cudaFuncAttributeMaxDynamicSharedMemorySize, GSMEM);

    // 0) prep: LN1 + wqkv transpose + bias concat
    prep_kernel<<<MROWS + WQKV_TILES + BBLOCKS, 256>>>(
        x, g1, b1, xh, Wq, Wk, Wv, bq, bk, bv, bqkv);

    // 1) fused qkv GEMM (1536 tiles) + tail aux: Wo/Wfb transposes (3072 blks)
    gemm_hmma<<<1536 + AUX_TOT, 128, GSMEM>>>(
        xh, wqkvT, bqkv, qkv, DIM, 3*DIM, 2, 1536, 24, Wo, Wfb);

    // 2) local attention (fp16 -> fp16), warp = 4 heads
    attn_kernel<<<(MROWS*(HEADS/4)*32)/256, 256>>>(qkv, at);

    // 3) y = at @ Wfb + bfb, K=2048, fp16 out
    gemm_hmma<<<512, 128, GSMEM>>>(at, wfbT, bfb, yh, 2*DIM, DIM, 2, 512, 8,
                                   nullptr, nullptr);
    // 4) LN2(y + xh) -> fp16
    ln2_kernel<<<MROWS, 256>>>(yh, xh, g2, b2, zh);
    // 5) out = gelu(z @ Wo + bo), K=1024, fp32+gelu
    gemm_hmma<<<512, 128, GSMEM>>>(zh, woT, bo, out, DIM, DIM, 1, 512, 8,
                                   nullptr, nullptr);
}